// round 6
// baseline (speedup 1.0000x reference)
#include <cuda_runtime.h>
#include <cuda_fp16.h>
#include <math.h>
#include <stdint.h>

// ---------------- problem constants ----------------
#define T_  4
#define B_  16
#define C_  512
#define H_  16
#define W_  16
#define N_  256
#define NH_ 8
#define D_  64
#define M_  (T_*B_*N_)     // 16384
#define HID_ 2048
#define ROWS_PER_T (B_*N_) // 4096

// ---------------- scratch ----------------
__device__ float  g_xt [M_*C_];
__device__ float  g_xt2[M_*C_];
__device__ __half g_h16[M_*C_];
__device__ __half g_q16[M_*3*C_];
__device__ __half g_a16[M_*C_];
__device__ __half g_m16[M_*HID_];
__device__ __half g_wall[3*C_*C_ + C_*C_ + 2*HID_*C_];  // qkv|proj|fc1|fc2 fp16

#define WOFF_QKV  0
#define WOFF_PROJ (3*C_*C_)
#define WOFF_FC1  (WOFF_PROJ + C_*C_)
#define WOFF_FC2  (WOFF_FC1 + HID_*C_)

__device__ __forceinline__ float sigm(float w){ return 1.0f/(1.0f+expf(-w)); }
__device__ __forceinline__ uint32_t s2u(const void* p){
    uint32_t a;
    asm("{ .reg .u64 t; cvta.to.shared.u64 t, %1; cvt.u32.u64 %0, t; }" : "=r"(a) : "l"(p));
    return a;
}
__device__ __forceinline__ void cp16(uint32_t s, const void* g){
    asm volatile("cp.async.cg.shared.global [%0], [%1], 16;" :: "r"(s), "l"(g));
}
__device__ __forceinline__ void ldsm4(uint32_t* r, uint32_t addr){
    asm volatile("ldmatrix.sync.aligned.m8n8.x4.shared.b16 {%0,%1,%2,%3}, [%4];"
                 : "=r"(r[0]), "=r"(r[1]), "=r"(r[2]), "=r"(r[3]) : "r"(addr));
}
__device__ __forceinline__ void mma16816(float* c, const uint32_t* a, uint32_t b0, uint32_t b1){
    asm volatile(
        "mma.sync.aligned.m16n8k16.row.col.f32.f16.f16.f32 "
        "{%0,%1,%2,%3}, {%4,%5,%6,%7}, {%8,%9}, {%0,%1,%2,%3};"
        : "+f"(c[0]), "+f"(c[1]), "+f"(c[2]), "+f"(c[3])
        : "r"(a[0]), "r"(a[1]), "r"(a[2]), "r"(a[3]), "r"(b0), "r"(b1));
}

// ---------------- HMMA GEMM, 4-stage gmem pipeline + 2-deep frag pipeline ---
// logical row r = bn_token*4 + t  <->  phys row = (r&3)*4096 + (r>>2)
// MODE 0: fp32 out + bias + residual (proj)
// MODE 1: fused LIF per-512-col decay lifw[2..4] -> fp16 spikes (qkv)
// MODE 2: fused LIF decay lifw[7] + bias -> fp16 spikes (fc1)
// MODE 3: bias + residual, write fp32 transposed [T,B,C,N] direct (fc2)
#define LDT 40
#define S_  4
#define STAGE_BYTES (128*LDT*2)       // 10240
#define GEMM_SMEM (S_*2*STAGE_BYTES)  // 81920
#define STG  132
#define STG3 133

#define LD_FRAGS(af, bf, off) do { \
    _Pragma("unroll") \
    for (int mi = 0; mi < 4; mi++) ldsm4(af[mi], abase[mi] + (off)); \
    _Pragma("unroll") \
    for (int np = 0; np < 2; np++) ldsm4(bf[np], bbase[np] + (off)); \
} while(0)

#define MMA_ALL(af, bf) do { \
    _Pragma("unroll") \
    for (int mi = 0; mi < 4; mi++) \
        _Pragma("unroll") \
        for (int ni = 0; ni < 4; ni++) \
            mma16816(acc[mi][ni], af[mi], bf[ni>>1][2*(ni&1)], bf[ni>>1][2*(ni&1)+1]); \
} while(0)

template<int MODE>
__global__ void __launch_bounds__(256) tc_gemm(
        const __half* __restrict__ A, const __half* __restrict__ Wt,
        const float* __restrict__ bias, const float* __restrict__ res,
        float* __restrict__ outf, __half* __restrict__ outh,
        const float* __restrict__ lifw, int Ndim, int K){
    extern __shared__ char smraw[];
    float* stage = (float*)smraw;
    uint32_t sAu = s2u(smraw);
    uint32_t sBu = sAu + S_*STAGE_BYTES;

    int tid = threadIdx.x;
    int warp = tid >> 5, lane = tid & 31;
    int wm = (warp & 1) * 64;
    int wn = (warp >> 1) * 32;
    int bm = blockIdx.y * 128, bn = blockIdx.x * 128;
    float acc[4][4][4] = {};

    const __half* ga[2]; const __half* gb[2];
    uint32_t so[2];
    #pragma unroll
    for (int it = 0; it < 2; it++){
        int task = tid + it*256;
        int row = task >> 2, ch = task & 3;
        int pr = (row & 3)*ROWS_PER_T + (bm >> 2) + (row >> 2);
        ga[it] = A  + (size_t)pr*K + ch*8;
        gb[it] = Wt + (size_t)(bn+row)*K + ch*8;
        so[it] = (uint32_t)((row*LDT + ch*8)*2);
    }

    const int NC = K / 32;
    #pragma unroll
    for (int p = 0; p < S_-1; p++){
        #pragma unroll
        for (int it = 0; it < 2; it++){
            cp16(sAu + p*STAGE_BYTES + so[it], ga[it] + p*32);
            cp16(sBu + p*STAGE_BYTES + so[it], gb[it] + p*32);
        }
        asm volatile("cp.async.commit_group;");
    }

    int l8 = lane >> 3;
    int arow = (lane & 7) + (l8 & 1) * 8, acol = (l8 >> 1) * 8;
    int brow = (lane & 7) + (l8 >> 1) * 8, bcol = (l8 & 1) * 8;
    uint32_t abase[4], bbase[2];
    #pragma unroll
    for (int mi = 0; mi < 4; mi++)
        abase[mi] = sAu + ((wm + mi*16 + arow)*LDT + acol)*2;
    #pragma unroll
    for (int np = 0; np < 2; np++)
        bbase[np] = sBu + ((wn + np*16 + brow)*LDT + bcol)*2;

    uint32_t af0[4][4], bf0[2][4], af1[4][4], bf1[2][4];
    asm volatile("cp.async.wait_group 2;" ::: "memory");
    __syncthreads();
    LD_FRAGS(af0, bf0, 0);

    for (int c = 0; c < NC; c++){
        uint32_t stoff = (uint32_t)(c % S_) * STAGE_BYTES;
        // prefetch ks=1 fragments of this stage, then MMA on ks=0
        LD_FRAGS(af1, bf1, stoff + 32);
        MMA_ALL(af0, bf0);
        // gmem prefetch for stage c+S_-1
        if (c + S_-1 < NC){
            uint32_t poff = (uint32_t)((c + S_-1) % S_) * STAGE_BYTES;
            #pragma unroll
            for (int it = 0; it < 2; it++){
                cp16(sAu + poff + so[it], ga[it] + (c+S_-1)*32);
                cp16(sBu + poff + so[it], gb[it] + (c+S_-1)*32);
            }
        }
        asm volatile("cp.async.commit_group;");
        if (c + 1 < NC){
            asm volatile("cp.async.wait_group 2;" ::: "memory");
            __syncthreads();
            uint32_t nstoff = (uint32_t)((c+1) % S_) * STAGE_BYTES;
            LD_FRAGS(af0, bf0, nstoff);
        }
        MMA_ALL(af1, bf1);
    }

    int g = lane >> 2, i2 = (lane & 3) * 2;
    if (MODE == 0){
        #pragma unroll
        for (int mi = 0; mi < 4; mi++){
            int rl0 = bm + wm + mi*16 + g;
            int rl1 = rl0 + 8;
            int rp0 = (rl0 & 3)*ROWS_PER_T + (rl0 >> 2);
            int rp1 = (rl1 & 3)*ROWS_PER_T + (rl1 >> 2);
            #pragma unroll
            for (int ni = 0; ni < 4; ni++){
                int col = bn + wn + ni*8 + i2;
                float b0 = bias ? bias[col]   : 0.f;
                float b1 = bias ? bias[col+1] : 0.f;
                float v00 = acc[mi][ni][0] + b0, v01 = acc[mi][ni][1] + b1;
                float v10 = acc[mi][ni][2] + b0, v11 = acc[mi][ni][3] + b1;
                size_t o0 = (size_t)rp0*Ndim + col;
                size_t o1 = (size_t)rp1*Ndim + col;
                if (res){
                    v00 += res[o0]; v01 += res[o0+1];
                    v10 += res[o1]; v11 += res[o1+1];
                }
                *(float2*)&outf[o0] = make_float2(v00, v01);
                *(float2*)&outf[o1] = make_float2(v10, v11);
            }
        }
    } else if (MODE == 1 || MODE == 2){
        __syncthreads();
        #pragma unroll
        for (int mi = 0; mi < 4; mi++){
            int r0 = wm + mi*16 + g, r1 = r0 + 8;
            #pragma unroll
            for (int ni = 0; ni < 4; ni++){
                int cl = wn + ni*8 + i2;
                *(float2*)&stage[r0*STG + cl] = make_float2(acc[mi][ni][0], acc[mi][ni][1]);
                *(float2*)&stage[r1*STG + cl] = make_float2(acc[mi][ni][2], acc[mi][ni][3]);
            }
        }
        __syncthreads();
        float d0, d1 = 0.f, d2 = 0.f;
        if (MODE == 1){ d0 = sigm(lifw[2]); d1 = sigm(lifw[3]); d2 = sigm(lifw[4]); }
        else          { d0 = sigm(lifw[7]); }
        #pragma unroll
        for (int it = 0; it < 2; it++){
            int t2 = tid + it*256;
            int bnl = t2 >> 4, cg = (t2 & 15) * 8;
            int gc = bn + cg;
            float dec = (MODE == 1) ? (gc < 512 ? d0 : (gc < 1024 ? d1 : d2)) : d0;
            float bi[8];
            if (bias){
                float4 q0 = *(const float4*)&bias[gc];
                float4 q1 = *(const float4*)&bias[gc+4];
                bi[0]=q0.x; bi[1]=q0.y; bi[2]=q0.z; bi[3]=q0.w;
                bi[4]=q1.x; bi[5]=q1.y; bi[6]=q1.z; bi[7]=q1.w;
            } else {
                #pragma unroll
                for (int j = 0; j < 8; j++) bi[j] = 0.f;
            }
            float v[8];
            #pragma unroll
            for (int j = 0; j < 8; j++) v[j] = 0.f;
            #pragma unroll
            for (int t = 0; t < 4; t++){
                int r = bnl*4 + t;
                float4 x0 = *(float4*)&stage[r*STG + cg];
                float4 x1 = *(float4*)&stage[r*STG + cg + 4];
                float xv[8] = {x0.x,x0.y,x0.z,x0.w,x1.x,x1.y,x1.z,x1.w};
                union { __half h[8]; uint4 u; } pk;
                #pragma unroll
                for (int j = 0; j < 8; j++){
                    float xx = xv[j] + bi[j];
                    v[j] += (xx - v[j])*dec;
                    float sp = (v[j] >= 1.0f) ? 1.f : 0.f;
                    pk.h[j] = __float2half_rn(sp);
                    if (sp > 0.f) v[j] = 0.f;
                }
                int pr = t*ROWS_PER_T + (bm >> 2) + bnl;
                *(uint4*)&outh[(size_t)pr*Ndim + gc] = pk.u;
            }
        }
    } else {
        __syncthreads();
        #pragma unroll
        for (int mi = 0; mi < 4; mi++){
            int r0 = wm + mi*16 + g, r1 = r0 + 8;
            int rl0 = bm + r0, rl1 = bm + r1;
            int rp0 = (rl0 & 3)*ROWS_PER_T + (rl0 >> 2);
            int rp1 = (rl1 & 3)*ROWS_PER_T + (rl1 >> 2);
            #pragma unroll
            for (int ni = 0; ni < 4; ni++){
                int cl = wn + ni*8 + i2;
                int col = bn + cl;
                float b0 = bias[col], b1 = bias[col+1];
                size_t o0 = (size_t)rp0*Ndim + col;
                size_t o1 = (size_t)rp1*Ndim + col;
                stage[r0*STG3 + cl]   = acc[mi][ni][0] + b0 + res[o0];
                stage[r0*STG3 + cl+1] = acc[mi][ni][1] + b1 + res[o0+1];
                stage[r1*STG3 + cl]   = acc[mi][ni][2] + b0 + res[o1];
                stage[r1*STG3 + cl+1] = acc[mi][ni][3] + b1 + res[o1+1];
            }
        }
        __syncthreads();
        int btok = bm >> 2;
        int b = btok >> 8, n0 = btok & 255;
        #pragma unroll
        for (int it = 0; it < 16; it++){
            int f4 = tid + it*256;
            int rown = f4 >> 3;
            int n4 = f4 & 7;
            int cc = rown >> 2, t = rown & 3;
            float4 val;
            val.x = stage[((n4*4+0)*4 + t)*STG3 + cc];
            val.y = stage[((n4*4+1)*4 + t)*STG3 + cc];
            val.z = stage[((n4*4+2)*4 + t)*STG3 + cc];
            val.w = stage[((n4*4+3)*4 + t)*STG3 + cc];
            size_t dst = ((size_t)(t*B_ + b)*C_ + bn + cc)*N_ + n0 + n4*4;
            *(float4*)&outf[dst] = val;
        }
    }
}

// ---------------- all-weights f32 -> f16 convert ----------------------------
__global__ void k_f2hall(const float* __restrict__ w0, const float* __restrict__ w1,
                         const float* __restrict__ w2, const float* __restrict__ w3){
    int i = blockIdx.x*blockDim.x + threadIdx.x;
    const float* src;
    if (i < 196608){ src = w0; }
    else if (i < 262144){ src = w1 - 786432; }
    else if (i < 524288){ src = w2 - 1048576; }
    else { src = w3 - 2097152; }
    float4 f = *(const float4*)&src[i*4];
    union { __half h[4]; uint2 u; } pk;
    pk.h[0]=__float2half_rn(f.x); pk.h[1]=__float2half_rn(f.y);
    pk.h[2]=__float2half_rn(f.z); pk.h[3]=__float2half_rn(f.w);
    *(uint2*)&g_wall[(size_t)i*4] = pk.u;
}

// ---------------- fused input-LIF + depthwise conv + residual ---------------
__global__ void __launch_bounds__(256) k_conv_lif(
        const float* __restrict__ x, const float* __restrict__ cw,
        const float* __restrict__ cb, const float* __restrict__ lifw){
    __shared__ float  xs[16*257];
    __shared__ __half sp[16*264];
    __shared__ float  ws[16*9];
    __shared__ float  wb[16];
    int tid = threadIdx.x;
    int b  = blockIdx.x >> 5;
    int c0 = (blockIdx.x & 31) * 16;
    if (tid < 16*9) ws[tid] = cw[c0*9 + tid];
    if (tid < 16)   wb[tid] = cb[c0 + tid];
    float dec = sigm(lifw[0]);
    float v[16];
    #pragma unroll
    for (int i = 0; i < 16; i++) v[i] = 0.f;
    __syncthreads();
    for (int t = 0; t < T_; t++){
        int tb = t*B_ + b;
        #pragma unroll
        for (int i = 0; i < 16; i++){
            int lin = tid + i*256;
            int cl = lin >> 8, px = lin & 255;
            float xv = x[((size_t)tb*C_ + c0 + cl)*256 + px];
            xs[cl*257 + px] = xv;
            float vv = v[i] + (xv - v[i])*dec;
            float s = (vv >= 1.0f) ? 1.f : 0.f;
            v[i] = (s > 0.f) ? 0.f : vv;
            sp[cl*264 + px] = __float2half_rn(s);
        }
        __syncthreads();
        #pragma unroll
        for (int i = 0; i < 16; i++){
            int lin = tid + i*256;
            int cl = lin & 15, n = lin >> 4;
            int hh = n >> 4, wp = n & 15;
            float acc = wb[cl];
            const float* wk = &ws[cl*9];
            #pragma unroll
            for (int kh = 0; kh < 3; kh++){
                int h2 = hh + kh - 1;
                if (h2 < 0 || h2 > 15) continue;
                #pragma unroll
                for (int kw = 0; kw < 3; kw++){
                    int w2 = wp + kw - 1;
                    if (w2 < 0 || w2 > 15) continue;
                    acc += __half2float(sp[cl*264 + h2*16 + w2]) * wk[kh*3 + kw];
                }
            }
            float val = xs[cl*257 + n] + acc;
            g_xt[((size_t)tb*256 + n)*C_ + c0 + cl] = val;
        }
        __syncthreads();
    }
}

// ---------------- LayerNorm + LIF, warp-per-token ---------------------------
__global__ void __launch_bounds__(256) k_ln_lif(
        const float* __restrict__ in, __half* __restrict__ out,
        const float* __restrict__ gam, const float* __restrict__ bet,
        const float* __restrict__ lifw, int lidx){
    int tid = threadIdx.x, wid = tid >> 5, lane = tid & 31;
    int bn = blockIdx.x*8 + wid;
    int cb = lane*16;
    float dec = sigm(lifw[lidx]);
    float gg[16], bb[16];
    #pragma unroll
    for (int i = 0; i < 4; i++){
        float4 t1 = *(const float4*)&gam[cb + i*4];
        float4 t2 = *(const float4*)&bet[cb + i*4];
        gg[i*4]=t1.x; gg[i*4+1]=t1.y; gg[i*4+2]=t1.z; gg[i*4+3]=t1.w;
        bb[i*4]=t2.x; bb[i*4+1]=t2.y; bb[i*4+2]=t2.z; bb[i*4+3]=t2.w;
    }
    float v[16];
    #pragma unroll
    for (int i = 0; i < 16; i++) v[i] = 0.f;
    for (int t = 0; t < T_; t++){
        int row = t*ROWS_PER_T + bn;
        const float* xr = in + (size_t)row*C_ + cb;
        float xv[16];
        #pragma unroll
        for (int i = 0; i < 4; i++){
            float4 x4 = *(const float4*)&xr[i*4];
            xv[i*4]=x4.x; xv[i*4+1]=x4.y; xv[i*4+2]=x4.z; xv[i*4+3]=x4.w;
        }
        float s = 0.f, ss = 0.f;
        #pragma unroll
        for (int i = 0; i < 16; i++){ s += xv[i]; ss += xv[i]*xv[i]; }
        #pragma unroll
        for (int o = 16; o > 0; o >>= 1){
            s  += __shfl_xor_sync(0xffffffffu, s,  o);
            ss += __shfl_xor_sync(0xffffffffu, ss, o);
        }
        float mean = s*(1.0f/C_);
        float var  = ss*(1.0f/C_) - mean*mean;
        float rstd = rsqrtf(var + 1e-5f);
        union { __half h[16]; uint4 u[2]; } pk;
        #pragma unroll
        for (int k = 0; k < 16; k++){
            float ln = (xv[k]-mean)*rstd*gg[k] + bb[k];
            v[k] += (ln - v[k])*dec;
            float spv = (v[k] >= 1.0f) ? 1.f : 0.f;
            pk.h[k] = __float2half_rn(spv);
            if (spv > 0.f) v[k] = 0.f;
        }
        uint4* dst = (uint4*)(out + (size_t)row*C_ + cb);
        dst[0] = pk.u[0]; dst[1] = pk.u[1];
    }
}

// ---------------- fused attention: kv = k^T v, a = q@kv*scale + LIF ---------
__global__ void __launch_bounds__(256) k_attn(const float* __restrict__ lifw){
    int blk = blockIdx.x;          // 128 = B*NH
    int h = blk & (NH_-1);
    int b = blk >> 3;
    __shared__ float ks[64*64];
    __shared__ float vs[64*64];
    __shared__ float kvs[64*64];
    int tid = threadIdx.x;
    int ti = tid >> 4, tj = tid & 15;
    float dec = sigm(lifw[5]);
    float vst[64];
    #pragma unroll
    for (int j = 0; j < 64; j++) vst[j] = 0.f;

    for (int t = 0; t < T_; t++){
        int tb = t*B_ + b;
        const __half* base = g_q16 + (size_t)tb*256*(3*C_);
        float acc[4][4] = {};
        for (int n0 = 0; n0 < N_; n0 += 64){
            int tok = tid >> 2, doff = (tid & 3)*16;
            const __half* kr = base + (size_t)(n0+tok)*(3*C_) + C_   + h*D_ + doff;
            const __half* vr = base + (size_t)(n0+tok)*(3*C_) + 2*C_ + h*D_ + doff;
            #pragma unroll
            for (int i = 0; i < 16; i++){
                ks[tok*64 + doff + i] = __half2float(kr[i]);
                vs[tok*64 + doff + i] = __half2float(vr[i]);
            }
            __syncthreads();
            #pragma unroll 8
            for (int nn = 0; nn < 64; nn++){
                float ra[4], rb[4];
                #pragma unroll
                for (int i = 0; i < 4; i++) ra[i] = ks[nn*64 + ti*4 + i];
                #pragma unroll
                for (int j = 0; j < 4; j++) rb[j] = vs[nn*64 + tj*4 + j];
                #pragma unroll
                for (int i = 0; i < 4; i++)
                    #pragma unroll
                    for (int j = 0; j < 4; j++)
                        acc[i][j] += ra[i]*rb[j];
            }
            __syncthreads();
        }
        #pragma unroll
        for (int i = 0; i < 4; i++)
            #pragma unroll
            for (int j = 0; j < 4; j++)
                kvs[(ti*4+i)*64 + tj*4+j] = acc[i][j];
        __syncthreads();

        int row = tb*256 + tid;
        const __half2* qp = (const __half2*)(g_q16 + (size_t)row*(3*C_) + h*D_);
        half2 q[32];
        #pragma unroll
        for (int i = 0; i < 32; i++) q[i] = qp[i];
        #pragma unroll
        for (int jc = 0; jc < 8; jc++){
            float s[8] = {};
            #pragma unroll 8
            for (int i2 = 0; i2 < 32; i2++){
                float2 qf = __half22float2(q[i2]);
                #pragma unroll
                for (int j = 0; j < 8; j++){
                    s[j] += qf.x*kvs[(2*i2)*64 + jc*8 + j];
                    s[j] += qf.y*kvs[(2*i2+1)*64 + jc*8 + j];
                }
            }
            union { __half hh[8]; uint4 u; } pk;
            #pragma unroll
            for (int j = 0; j < 8; j++){
                int jj = jc*8 + j;
                float a = s[j]*0.125f;
                vst[jj] += (a - vst[jj])*dec;
                float sp = (vst[jj] >= 1.0f) ? 1.f : 0.f;
                pk.hh[j] = __float2half_rn(sp);
                if (sp > 0.f) vst[jj] = 0.f;
            }
            *(uint4*)(g_a16 + (size_t)row*C_ + h*D_ + jc*8) = pk.u;
        }
        __syncthreads();
    }
}

// ---------------- host orchestration ----------------------------------------
extern "C" void kernel_launch(void* const* d_in, const int* in_sizes, int n_in,
                              void* d_out, int out_size){
    const float* x      = (const float*)d_in[0];
    const float* conv_w = (const float*)d_in[1];
    const float* conv_b = (const float*)d_in[2];
    const float* ln1_g  = (const float*)d_in[3];
    const float* ln1_b  = (const float*)d_in[4];
    const float* qkv_w  = (const float*)d_in[5];
    const float* proj_w = (const float*)d_in[6];
    const float* proj_b = (const float*)d_in[7];
    const float* ln2_g  = (const float*)d_in[8];
    const float* ln2_b  = (const float*)d_in[9];
    const float* fc1_w  = (const float*)d_in[10];
    const float* fc1_b  = (const float*)d_in[11];
    const float* fc2_w  = (const float*)d_in[12];
    const float* fc2_b  = (const float*)d_in[13];
    const float* lif_w  = (const float*)d_in[14];
    float* out = (float*)d_out;

    cudaFuncSetAttribute(tc_gemm<0>, cudaFuncAttributeMaxDynamicSharedMemorySize, GEMM_SMEM);
    cudaFuncSetAttribute(tc_gemm<1>, cudaFuncAttributeMaxDynamicSharedMemorySize, GEMM_SMEM);
    cudaFuncSetAttribute(tc_gemm<2>, cudaFuncAttributeMaxDynamicSharedMemorySize, GEMM_SMEM);
    cudaFuncSetAttribute(tc_gemm<3>, cudaFuncAttributeMaxDynamicSharedMemorySize, GEMM_SMEM);

    float *p_xt, *p_xt2;
    __half *p_h16, *p_q16, *p_a16, *p_m16, *p_w;
    cudaGetSymbolAddress((void**)&p_xt,  g_xt);
    cudaGetSymbolAddress((void**)&p_xt2, g_xt2);
    cudaGetSymbolAddress((void**)&p_h16, g_h16);
    cudaGetSymbolAddress((void**)&p_q16, g_q16);
    cudaGetSymbolAddress((void**)&p_a16, g_a16);
    cudaGetSymbolAddress((void**)&p_m16, g_m16);
    cudaGetSymbolAddress((void**)&p_w,   g_wall);

    k_f2hall<<<786432/256, 256>>>(qkv_w, proj_w, fc1_w, fc2_w);
    k_conv_lif<<<512, 256>>>(x, conv_w, conv_b, lif_w);
    k_ln_lif<<<512, 256>>>(p_xt, p_h16, ln1_g, ln1_b, lif_w, 1);
    tc_gemm<1><<<dim3(12,128), 256, GEMM_SMEM>>>(p_h16, p_w + WOFF_QKV, nullptr, nullptr,
                                                 nullptr, p_q16, lif_w, 3*C_, C_);
    k_attn<<<128, 256>>>(lif_w);
    tc_gemm<0><<<dim3(4,128), 256, GEMM_SMEM>>>(p_a16, p_w + WOFF_PROJ, proj_b, p_xt,
                                                p_xt2, nullptr, lif_w, C_, C_);
    k_ln_lif<<<512, 256>>>(p_xt2, p_h16, ln2_g, ln2_b, lif_w, 6);
    tc_gemm<2><<<dim3(16,128), 256, GEMM_SMEM>>>(p_h16, p_w + WOFF_FC1, fc1_b, nullptr,
                                                 nullptr, p_m16, lif_w, HID_, C_);
    tc_gemm<3><<<dim3(4,128), 256, GEMM_SMEM>>>(p_m16, p_w + WOFF_FC2, fc2_b, p_xt2,
                                                out, nullptr, lif_w, C_, HID_);
}

// round 7
// speedup vs baseline: 1.1798x; 1.1798x over previous
#include <cuda_runtime.h>
#include <cuda_fp16.h>
#include <math.h>
#include <stdint.h>

// ---------------- problem constants ----------------
#define T_  4
#define B_  16
#define C_  512
#define H_  16
#define W_  16
#define N_  256
#define NH_ 8
#define D_  64
#define M_  (T_*B_*N_)     // 16384
#define HID_ 2048
#define ROWS_PER_T (B_*N_) // 4096

// ---------------- scratch ----------------
__device__ float  g_xt [M_*C_];
__device__ float  g_xt2[M_*C_];
__device__ __half g_h16[M_*C_];
__device__ __half g_q16[M_*3*C_];
__device__ __half g_a16[M_*C_];
__device__ __half g_m16[M_*HID_];
__device__ __half g_wall[3*C_*C_ + C_*C_ + 2*HID_*C_];  // qkv|proj|fc1|fc2 fp16

#define WOFF_QKV  0
#define WOFF_PROJ (3*C_*C_)
#define WOFF_FC1  (WOFF_PROJ + C_*C_)
#define WOFF_FC2  (WOFF_FC1 + HID_*C_)

__device__ __forceinline__ float sigm(float w){ return 1.0f/(1.0f+expf(-w)); }
__device__ __forceinline__ uint32_t s2u(const void* p){
    uint32_t a;
    asm("{ .reg .u64 t; cvta.to.shared.u64 t, %1; cvt.u32.u64 %0, t; }" : "=r"(a) : "l"(p));
    return a;
}
__device__ __forceinline__ void cp16(uint32_t s, const void* g){
    asm volatile("cp.async.cg.shared.global [%0], [%1], 16;" :: "r"(s), "l"(g));
}
__device__ __forceinline__ void ldsm4(uint32_t* r, uint32_t addr){
    asm volatile("ldmatrix.sync.aligned.m8n8.x4.shared.b16 {%0,%1,%2,%3}, [%4];"
                 : "=r"(r[0]), "=r"(r[1]), "=r"(r[2]), "=r"(r[3]) : "r"(addr));
}
__device__ __forceinline__ void mma16816(float* c, const uint32_t* a, uint32_t b0, uint32_t b1){
    asm volatile(
        "mma.sync.aligned.m16n8k16.row.col.f32.f16.f16.f32 "
        "{%0,%1,%2,%3}, {%4,%5,%6,%7}, {%8,%9}, {%0,%1,%2,%3};"
        : "+f"(c[0]), "+f"(c[1]), "+f"(c[2]), "+f"(c[3])
        : "r"(a[0]), "r"(a[1]), "r"(a[2]), "r"(a[3]), "r"(b0), "r"(b1));
}

// ---------------- HMMA GEMM, 4-stage pipeline (R5-proven shape) -------------
// logical row r = bn_token*4 + t  <->  phys row = (r&3)*4096 + (r>>2)
// MODE 0: fp32 out + bias + residual (proj)
// MODE 1: fused LIF per-512-col decay lifw[2..4] -> fp16 spikes (qkv)
// MODE 2: fused LIF decay lifw[7] + bias -> fp16 spikes (fc1)
// MODE 3: bias + residual, write fp32 transposed [T,B,C,N] direct (fc2)
#define LDT 40
#define S_  4
#define STAGE_BYTES (128*LDT*2)       // 10240
#define GEMM_SMEM (S_*2*STAGE_BYTES)  // 81920
#define STG  132
#define STG3 133

template<int MODE>
__global__ void __launch_bounds__(256, 2) tc_gemm(
        const __half* __restrict__ A, const __half* __restrict__ Wt,
        const float* __restrict__ bias, const float* __restrict__ res,
        float* __restrict__ outf, __half* __restrict__ outh,
        const float* __restrict__ lifw, int Ndim, int K){
    extern __shared__ char smraw[];
    float* stage = (float*)smraw;
    uint32_t sAu = s2u(smraw);
    uint32_t sBu = sAu + S_*STAGE_BYTES;

    int tid = threadIdx.x;
    int warp = tid >> 5, lane = tid & 31;
    int wm = (warp & 1) * 64;
    int wn = (warp >> 1) * 32;
    int bm = blockIdx.y * 128, bn = blockIdx.x * 128;
    float acc[4][4][4] = {};

    const __half* ga[2]; const __half* gb[2];
    uint32_t so[2];
    #pragma unroll
    for (int it = 0; it < 2; it++){
        int task = tid + it*256;
        int row = task >> 2, ch = task & 3;
        int pr = (row & 3)*ROWS_PER_T + (bm >> 2) + (row >> 2);
        ga[it] = A  + (size_t)pr*K + ch*8;
        gb[it] = Wt + (size_t)(bn+row)*K + ch*8;
        so[it] = (uint32_t)((row*LDT + ch*8)*2);
    }

    const int NC = K / 32;
    #pragma unroll
    for (int p = 0; p < S_-1; p++){
        #pragma unroll
        for (int it = 0; it < 2; it++){
            cp16(sAu + p*STAGE_BYTES + so[it], ga[it] + p*32);
            cp16(sBu + p*STAGE_BYTES + so[it], gb[it] + p*32);
        }
        asm volatile("cp.async.commit_group;");
    }

    int l8 = lane >> 3;
    int arow = (lane & 7) + (l8 & 1) * 8, acol = (l8 >> 1) * 8;
    int brow = (lane & 7) + (l8 >> 1) * 8, bcol = (l8 & 1) * 8;
    uint32_t abase[4], bbase[2];
    #pragma unroll
    for (int mi = 0; mi < 4; mi++)
        abase[mi] = sAu + ((wm + mi*16 + arow)*LDT + acol)*2;
    #pragma unroll
    for (int np = 0; np < 2; np++)
        bbase[np] = sBu + ((wn + np*16 + brow)*LDT + bcol)*2;

    for (int c = 0; c < NC; c++){
        uint32_t stoff = (uint32_t)(c % S_) * STAGE_BYTES;
        asm volatile("cp.async.wait_group 2;" ::: "memory");
        __syncthreads();
        if (c + S_-1 < NC){
            uint32_t poff = (uint32_t)((c + S_-1) % S_) * STAGE_BYTES;
            #pragma unroll
            for (int it = 0; it < 2; it++){
                cp16(sAu + poff + so[it], ga[it] + (c+S_-1)*32);
                cp16(sBu + poff + so[it], gb[it] + (c+S_-1)*32);
            }
        }
        asm volatile("cp.async.commit_group;");
        #pragma unroll
        for (int ks = 0; ks < 2; ks++){
            uint32_t af[4][4], bf[2][4];
            #pragma unroll
            for (int mi = 0; mi < 4; mi++)
                ldsm4(af[mi], abase[mi] + stoff + ks*32);
            #pragma unroll
            for (int np = 0; np < 2; np++)
                ldsm4(bf[np], bbase[np] + stoff + ks*32);
            #pragma unroll
            for (int mi = 0; mi < 4; mi++)
                #pragma unroll
                for (int ni = 0; ni < 4; ni++)
                    mma16816(acc[mi][ni], af[mi],
                             bf[ni>>1][2*(ni&1)], bf[ni>>1][2*(ni&1)+1]);
        }
    }

    int g = lane >> 2, i2 = (lane & 3) * 2;
    if (MODE == 0){
        #pragma unroll
        for (int mi = 0; mi < 4; mi++){
            int rl0 = bm + wm + mi*16 + g;
            int rl1 = rl0 + 8;
            int rp0 = (rl0 & 3)*ROWS_PER_T + (rl0 >> 2);
            int rp1 = (rl1 & 3)*ROWS_PER_T + (rl1 >> 2);
            #pragma unroll
            for (int ni = 0; ni < 4; ni++){
                int col = bn + wn + ni*8 + i2;
                float b0 = bias ? bias[col]   : 0.f;
                float b1 = bias ? bias[col+1] : 0.f;
                float v00 = acc[mi][ni][0] + b0, v01 = acc[mi][ni][1] + b1;
                float v10 = acc[mi][ni][2] + b0, v11 = acc[mi][ni][3] + b1;
                size_t o0 = (size_t)rp0*Ndim + col;
                size_t o1 = (size_t)rp1*Ndim + col;
                if (res){
                    v00 += res[o0]; v01 += res[o0+1];
                    v10 += res[o1]; v11 += res[o1+1];
                }
                *(float2*)&outf[o0] = make_float2(v00, v01);
                *(float2*)&outf[o1] = make_float2(v10, v11);
            }
        }
    } else if (MODE == 1 || MODE == 2){
        __syncthreads();
        #pragma unroll
        for (int mi = 0; mi < 4; mi++){
            int r0 = wm + mi*16 + g, r1 = r0 + 8;
            #pragma unroll
            for (int ni = 0; ni < 4; ni++){
                int cl = wn + ni*8 + i2;
                *(float2*)&stage[r0*STG + cl] = make_float2(acc[mi][ni][0], acc[mi][ni][1]);
                *(float2*)&stage[r1*STG + cl] = make_float2(acc[mi][ni][2], acc[mi][ni][3]);
            }
        }
        __syncthreads();
        float d0, d1 = 0.f, d2 = 0.f;
        if (MODE == 1){ d0 = sigm(lifw[2]); d1 = sigm(lifw[3]); d2 = sigm(lifw[4]); }
        else          { d0 = sigm(lifw[7]); }
        #pragma unroll
        for (int it = 0; it < 2; it++){
            int t2 = tid + it*256;
            int bnl = t2 >> 4, cg = (t2 & 15) * 8;
            int gc = bn + cg;
            float dec = (MODE == 1) ? (gc < 512 ? d0 : (gc < 1024 ? d1 : d2)) : d0;
            float bi[8];
            if (bias){
                float4 q0 = *(const float4*)&bias[gc];
                float4 q1 = *(const float4*)&bias[gc+4];
                bi[0]=q0.x; bi[1]=q0.y; bi[2]=q0.z; bi[3]=q0.w;
                bi[4]=q1.x; bi[5]=q1.y; bi[6]=q1.z; bi[7]=q1.w;
            } else {
                #pragma unroll
                for (int j = 0; j < 8; j++) bi[j] = 0.f;
            }
            float v[8];
            #pragma unroll
            for (int j = 0; j < 8; j++) v[j] = 0.f;
            #pragma unroll
            for (int t = 0; t < 4; t++){
                int r = bnl*4 + t;
                float4 x0 = *(float4*)&stage[r*STG + cg];
                float4 x1 = *(float4*)&stage[r*STG + cg + 4];
                float xv[8] = {x0.x,x0.y,x0.z,x0.w,x1.x,x1.y,x1.z,x1.w};
                union { __half h[8]; uint4 u; } pk;
                #pragma unroll
                for (int j = 0; j < 8; j++){
                    float xx = xv[j] + bi[j];
                    v[j] += (xx - v[j])*dec;
                    float sp = (v[j] >= 1.0f) ? 1.f : 0.f;
                    pk.h[j] = __float2half_rn(sp);
                    if (sp > 0.f) v[j] = 0.f;
                }
                int pr = t*ROWS_PER_T + (bm >> 2) + bnl;
                *(uint4*)&outh[(size_t)pr*Ndim + gc] = pk.u;
            }
        }
    } else {
        __syncthreads();
        #pragma unroll
        for (int mi = 0; mi < 4; mi++){
            int r0 = wm + mi*16 + g, r1 = r0 + 8;
            int rl0 = bm + r0, rl1 = bm + r1;
            int rp0 = (rl0 & 3)*ROWS_PER_T + (rl0 >> 2);
            int rp1 = (rl1 & 3)*ROWS_PER_T + (rl1 >> 2);
            #pragma unroll
            for (int ni = 0; ni < 4; ni++){
                int cl = wn + ni*8 + i2;
                int col = bn + cl;
                float b0 = bias[col], b1 = bias[col+1];
                size_t o0 = (size_t)rp0*Ndim + col;
                size_t o1 = (size_t)rp1*Ndim + col;
                stage[r0*STG3 + cl]   = acc[mi][ni][0] + b0 + res[o0];
                stage[r0*STG3 + cl+1] = acc[mi][ni][1] + b1 + res[o0+1];
                stage[r1*STG3 + cl]   = acc[mi][ni][2] + b0 + res[o1];
                stage[r1*STG3 + cl+1] = acc[mi][ni][3] + b1 + res[o1+1];
            }
        }
        __syncthreads();
        int btok = bm >> 2;
        int b = btok >> 8, n0 = btok & 255;
        #pragma unroll
        for (int it = 0; it < 16; it++){
            int f4 = tid + it*256;
            int rown = f4 >> 3;
            int n4 = f4 & 7;
            int cc = rown >> 2, t = rown & 3;
            float4 val;
            val.x = stage[((n4*4+0)*4 + t)*STG3 + cc];
            val.y = stage[((n4*4+1)*4 + t)*STG3 + cc];
            val.z = stage[((n4*4+2)*4 + t)*STG3 + cc];
            val.w = stage[((n4*4+3)*4 + t)*STG3 + cc];
            size_t dst = ((size_t)(t*B_ + b)*C_ + bn + cc)*N_ + n0 + n4*4;
            *(float4*)&outf[dst] = val;
        }
    }
}

// ---------------- all-weights f32 -> f16 convert ----------------------------
__global__ void k_f2hall(const float* __restrict__ w0, const float* __restrict__ w1,
                         const float* __restrict__ w2, const float* __restrict__ w3){
    int i = blockIdx.x*blockDim.x + threadIdx.x;
    const float* src;
    if (i < 196608){ src = w0; }
    else if (i < 262144){ src = w1 - 786432; }
    else if (i < 524288){ src = w2 - 1048576; }
    else { src = w3 - 2097152; }
    float4 f = *(const float4*)&src[i*4];
    union { __half h[4]; uint2 u; } pk;
    pk.h[0]=__float2half_rn(f.x); pk.h[1]=__float2half_rn(f.y);
    pk.h[2]=__float2half_rn(f.z); pk.h[3]=__float2half_rn(f.w);
    *(uint2*)&g_wall[(size_t)i*4] = pk.u;
}

// ---------------- fused input-LIF + depthwise conv + residual ---------------
__global__ void __launch_bounds__(256) k_conv_lif(
        const float* __restrict__ x, const float* __restrict__ cw,
        const float* __restrict__ cb, const float* __restrict__ lifw){
    __shared__ float  xs[16*257];
    __shared__ __half sp[16*264];
    __shared__ float  ws[16*9];
    __shared__ float  wb[16];
    int tid = threadIdx.x;
    int b  = blockIdx.x >> 5;
    int c0 = (blockIdx.x & 31) * 16;
    if (tid < 16*9) ws[tid] = cw[c0*9 + tid];
    if (tid < 16)   wb[tid] = cb[c0 + tid];
    float dec = sigm(lifw[0]);
    float v[16];
    #pragma unroll
    for (int i = 0; i < 16; i++) v[i] = 0.f;
    __syncthreads();
    for (int t = 0; t < T_; t++){
        int tb = t*B_ + b;
        #pragma unroll
        for (int i = 0; i < 16; i++){
            int lin = tid + i*256;
            int cl = lin >> 8, px = lin & 255;
            float xv = x[((size_t)tb*C_ + c0 + cl)*256 + px];
            xs[cl*257 + px] = xv;
            float vv = v[i] + (xv - v[i])*dec;
            float s = (vv >= 1.0f) ? 1.f : 0.f;
            v[i] = (s > 0.f) ? 0.f : vv;
            sp[cl*264 + px] = __float2half_rn(s);
        }
        __syncthreads();
        #pragma unroll
        for (int i = 0; i < 16; i++){
            int lin = tid + i*256;
            int cl = lin & 15, n = lin >> 4;
            int hh = n >> 4, wp = n & 15;
            float acc = wb[cl];
            const float* wk = &ws[cl*9];
            #pragma unroll
            for (int kh = 0; kh < 3; kh++){
                int h2 = hh + kh - 1;
                if (h2 < 0 || h2 > 15) continue;
                #pragma unroll
                for (int kw = 0; kw < 3; kw++){
                    int w2 = wp + kw - 1;
                    if (w2 < 0 || w2 > 15) continue;
                    acc += __half2float(sp[cl*264 + h2*16 + w2]) * wk[kh*3 + kw];
                }
            }
            float val = xs[cl*257 + n] + acc;
            g_xt[((size_t)tb*256 + n)*C_ + c0 + cl] = val;
        }
        __syncthreads();
    }
}

// ---------------- LayerNorm + LIF, warp-per-token ---------------------------
__global__ void __launch_bounds__(256) k_ln_lif(
        const float* __restrict__ in, __half* __restrict__ out,
        const float* __restrict__ gam, const float* __restrict__ bet,
        const float* __restrict__ lifw, int lidx){
    int tid = threadIdx.x, wid = tid >> 5, lane = tid & 31;
    int bn = blockIdx.x*8 + wid;
    int cb = lane*16;
    float dec = sigm(lifw[lidx]);
    float gg[16], bb[16];
    #pragma unroll
    for (int i = 0; i < 4; i++){
        float4 t1 = *(const float4*)&gam[cb + i*4];
        float4 t2 = *(const float4*)&bet[cb + i*4];
        gg[i*4]=t1.x; gg[i*4+1]=t1.y; gg[i*4+2]=t1.z; gg[i*4+3]=t1.w;
        bb[i*4]=t2.x; bb[i*4+1]=t2.y; bb[i*4+2]=t2.z; bb[i*4+3]=t2.w;
    }
    float v[16];
    #pragma unroll
    for (int i = 0; i < 16; i++) v[i] = 0.f;
    for (int t = 0; t < T_; t++){
        int row = t*ROWS_PER_T + bn;
        const float* xr = in + (size_t)row*C_ + cb;
        float xv[16];
        #pragma unroll
        for (int i = 0; i < 4; i++){
            float4 x4 = *(const float4*)&xr[i*4];
            xv[i*4]=x4.x; xv[i*4+1]=x4.y; xv[i*4+2]=x4.z; xv[i*4+3]=x4.w;
        }
        float s = 0.f, ss = 0.f;
        #pragma unroll
        for (int i = 0; i < 16; i++){ s += xv[i]; ss += xv[i]*xv[i]; }
        #pragma unroll
        for (int o = 16; o > 0; o >>= 1){
            s  += __shfl_xor_sync(0xffffffffu, s,  o);
            ss += __shfl_xor_sync(0xffffffffu, ss, o);
        }
        float mean = s*(1.0f/C_);
        float var  = ss*(1.0f/C_) - mean*mean;
        float rstd = rsqrtf(var + 1e-5f);
        union { __half h[16]; uint4 u[2]; } pk;
        #pragma unroll
        for (int k = 0; k < 16; k++){
            float ln = (xv[k]-mean)*rstd*gg[k] + bb[k];
            v[k] += (ln - v[k])*dec;
            float spv = (v[k] >= 1.0f) ? 1.f : 0.f;
            pk.h[k] = __float2half_rn(spv);
            if (spv > 0.f) v[k] = 0.f;
        }
        uint4* dst = (uint4*)(out + (size_t)row*C_ + cb);
        dst[0] = pk.u[0]; dst[1] = pk.u[1];
    }
}

// ---------------- fused attention: kv = k^T v, a = q@kv*scale + LIF ---------
__global__ void __launch_bounds__(256) k_attn(const float* __restrict__ lifw){
    int blk = blockIdx.x;          // 128 = B*NH
    int h = blk & (NH_-1);
    int b = blk >> 3;
    __shared__ float ks[64*64];
    __shared__ float vs[64*64];
    __shared__ float kvs[64*64];
    int tid = threadIdx.x;
    int ti = tid >> 4, tj = tid & 15;
    float dec = sigm(lifw[5]);
    float vst[64];
    #pragma unroll
    for (int j = 0; j < 64; j++) vst[j] = 0.f;

    for (int t = 0; t < T_; t++){
        int tb = t*B_ + b;
        const __half* base = g_q16 + (size_t)tb*256*(3*C_);
        float acc[4][4] = {};
        for (int n0 = 0; n0 < N_; n0 += 64){
            int tok = tid >> 2, doff = (tid & 3)*16;
            const __half* kr = base + (size_t)(n0+tok)*(3*C_) + C_   + h*D_ + doff;
            const __half* vr = base + (size_t)(n0+tok)*(3*C_) + 2*C_ + h*D_ + doff;
            #pragma unroll
            for (int i = 0; i < 16; i++){
                ks[tok*64 + doff + i] = __half2float(kr[i]);
                vs[tok*64 + doff + i] = __half2float(vr[i]);
            }
            __syncthreads();
            #pragma unroll 8
            for (int nn = 0; nn < 64; nn++){
                float ra[4], rb[4];
                #pragma unroll
                for (int i = 0; i < 4; i++) ra[i] = ks[nn*64 + ti*4 + i];
                #pragma unroll
                for (int j = 0; j < 4; j++) rb[j] = vs[nn*64 + tj*4 + j];
                #pragma unroll
                for (int i = 0; i < 4; i++)
                    #pragma unroll
                    for (int j = 0; j < 4; j++)
                        acc[i][j] += ra[i]*rb[j];
            }
            __syncthreads();
        }
        #pragma unroll
        for (int i = 0; i < 4; i++)
            #pragma unroll
            for (int j = 0; j < 4; j++)
                kvs[(ti*4+i)*64 + tj*4+j] = acc[i][j];
        __syncthreads();

        int row = tb*256 + tid;
        const __half2* qp = (const __half2*)(g_q16 + (size_t)row*(3*C_) + h*D_);
        half2 q[32];
        #pragma unroll
        for (int i = 0; i < 32; i++) q[i] = qp[i];
        #pragma unroll
        for (int jc = 0; jc < 8; jc++){
            float s[8] = {};
            #pragma unroll 8
            for (int i2 = 0; i2 < 32; i2++){
                float2 qf = __half22float2(q[i2]);
                #pragma unroll
                for (int j = 0; j < 8; j++){
                    s[j] += qf.x*kvs[(2*i2)*64 + jc*8 + j];
                    s[j] += qf.y*kvs[(2*i2+1)*64 + jc*8 + j];
                }
            }
            union { __half hh[8]; uint4 u; } pk;
            #pragma unroll
            for (int j = 0; j < 8; j++){
                int jj = jc*8 + j;
                float a = s[j]*0.125f;
                vst[jj] += (a - vst[jj])*dec;
                float sp = (vst[jj] >= 1.0f) ? 1.f : 0.f;
                pk.hh[j] = __float2half_rn(sp);
                if (sp > 0.f) vst[jj] = 0.f;
            }
            *(uint4*)(g_a16 + (size_t)row*C_ + h*D_ + jc*8) = pk.u;
        }
        __syncthreads();
    }
}

// ---------------- host orchestration ----------------------------------------
extern "C" void kernel_launch(void* const* d_in, const int* in_sizes, int n_in,
                              void* d_out, int out_size){
    const float* x      = (const float*)d_in[0];
    const float* conv_w = (const float*)d_in[1];
    const float* conv_b = (const float*)d_in[2];
    const float* ln1_g  = (const float*)d_in[3];
    const float* ln1_b  = (const float*)d_in[4];
    const float* qkv_w  = (const float*)d_in[5];
    const float* proj_w = (const float*)d_in[6];
    const float* proj_b = (const float*)d_in[7];
    const float* ln2_g  = (const float*)d_in[8];
    const float* ln2_b  = (const float*)d_in[9];
    const float* fc1_w  = (const float*)d_in[10];
    const float* fc1_b  = (const float*)d_in[11];
    const float* fc2_w  = (const float*)d_in[12];
    const float* fc2_b  = (const float*)d_in[13];
    const float* lif_w  = (const float*)d_in[14];
    float* out = (float*)d_out;

    cudaFuncSetAttribute(tc_gemm<0>, cudaFuncAttributeMaxDynamicSharedMemorySize, GEMM_SMEM);
    cudaFuncSetAttribute(tc_gemm<1>, cudaFuncAttributeMaxDynamicSharedMemorySize, GEMM_SMEM);
    cudaFuncSetAttribute(tc_gemm<2>, cudaFuncAttributeMaxDynamicSharedMemorySize, GEMM_SMEM);
    cudaFuncSetAttribute(tc_gemm<3>, cudaFuncAttributeMaxDynamicSharedMemorySize, GEMM_SMEM);

    float *p_xt, *p_xt2;
    __half *p_h16, *p_q16, *p_a16, *p_m16, *p_w;
    cudaGetSymbolAddress((void**)&p_xt,  g_xt);
    cudaGetSymbolAddress((void**)&p_xt2, g_xt2);
    cudaGetSymbolAddress((void**)&p_h16, g_h16);
    cudaGetSymbolAddress((void**)&p_q16, g_q16);
    cudaGetSymbolAddress((void**)&p_a16, g_a16);
    cudaGetSymbolAddress((void**)&p_m16, g_m16);
    cudaGetSymbolAddress((void**)&p_w,   g_wall);

    k_f2hall<<<786432/256, 256>>>(qkv_w, proj_w, fc1_w, fc2_w);
    k_conv_lif<<<512, 256>>>(x, conv_w, conv_b, lif_w);
    k_ln_lif<<<512, 256>>>(p_xt, p_h16, ln1_g, ln1_b, lif_w, 1);
    tc_gemm<1><<<dim3(12,128), 256, GEMM_SMEM>>>(p_h16, p_w + WOFF_QKV, nullptr, nullptr,
                                                 nullptr, p_q16, lif_w, 3*C_, C_);
    k_attn<<<128, 256>>>(lif_w);
    tc_gemm<0><<<dim3(4,128), 256, GEMM_SMEM>>>(p_a16, p_w + WOFF_PROJ, proj_b, p_xt,
                                                p_xt2, nullptr, lif_w, C_, C_);
    k_ln_lif<<<512, 256>>>(p_xt2, p_h16, ln2_g, ln2_b, lif_w, 6);
    tc_gemm<2><<<dim3(16,128), 256, GEMM_SMEM>>>(p_h16, p_w + WOFF_FC1, fc1_b, nullptr,
                                                 nullptr, p_m16, lif_w, HID_, C_);
    tc_gemm<3><<<dim3(4,128), 256, GEMM_SMEM>>>(p_m16, p_w + WOFF_FC2, fc2_b, p_xt2,
                                                out, nullptr, lif_w, C_, HID_);
}

// round 8
// speedup vs baseline: 1.4978x; 1.2695x over previous
#include <cuda_runtime.h>
#include <cuda_fp16.h>
#include <math.h>
#include <stdint.h>

// ---------------- problem constants ----------------
#define T_  4
#define B_  16
#define C_  512
#define H_  16
#define W_  16
#define N_  256
#define NH_ 8
#define D_  64
#define M_  (T_*B_*N_)     // 16384
#define HID_ 2048
#define ROWS_PER_T (B_*N_) // 4096

// ---------------- scratch ----------------
__device__ float  g_xt [M_*C_];
__device__ float  g_xt2[M_*C_];
__device__ __half g_h16[M_*C_];
__device__ __half g_q16[M_*3*C_];
__device__ __half g_a16[M_*C_];
__device__ __half g_m16[M_*HID_];
__device__ __half g_kvT[T_*B_*NH_*D_*D_];               // 4MB fp16 kv^T
__device__ __half g_wall[3*C_*C_ + C_*C_ + 2*HID_*C_];  // qkv|proj|fc1|fc2 fp16

#define WOFF_QKV  0
#define WOFF_PROJ (3*C_*C_)
#define WOFF_FC1  (WOFF_PROJ + C_*C_)
#define WOFF_FC2  (WOFF_FC1 + HID_*C_)

__device__ __forceinline__ float sigm(float w){ return 1.0f/(1.0f+expf(-w)); }
__device__ __forceinline__ uint32_t s2u(const void* p){
    uint32_t a;
    asm("{ .reg .u64 t; cvta.to.shared.u64 t, %1; cvt.u32.u64 %0, t; }" : "=r"(a) : "l"(p));
    return a;
}
__device__ __forceinline__ void cp16(uint32_t s, const void* g){
    asm volatile("cp.async.cg.shared.global [%0], [%1], 16;" :: "r"(s), "l"(g));
}
__device__ __forceinline__ void ldsm4(uint32_t* r, uint32_t addr){
    asm volatile("ldmatrix.sync.aligned.m8n8.x4.shared.b16 {%0,%1,%2,%3}, [%4];"
                 : "=r"(r[0]), "=r"(r[1]), "=r"(r[2]), "=r"(r[3]) : "r"(addr));
}
__device__ __forceinline__ void ldsm4t(uint32_t* r, uint32_t addr){
    asm volatile("ldmatrix.sync.aligned.m8n8.x4.trans.shared.b16 {%0,%1,%2,%3}, [%4];"
                 : "=r"(r[0]), "=r"(r[1]), "=r"(r[2]), "=r"(r[3]) : "r"(addr));
}
__device__ __forceinline__ void mma16816(float* c, const uint32_t* a, uint32_t b0, uint32_t b1){
    asm volatile(
        "mma.sync.aligned.m16n8k16.row.col.f32.f16.f16.f32 "
        "{%0,%1,%2,%3}, {%4,%5,%6,%7}, {%8,%9}, {%0,%1,%2,%3};"
        : "+f"(c[0]), "+f"(c[1]), "+f"(c[2]), "+f"(c[3])
        : "r"(a[0]), "r"(a[1]), "r"(a[2]), "r"(a[3]), "r"(b0), "r"(b1));
}

// ---------------- HMMA GEMM, 4-stage pipeline (R5/R7-proven shape) ----------
// logical row r = bn_token*4 + t  <->  phys row = (r&3)*4096 + (r>>2)
// MODE 0: fp32 out + bias + residual (proj)
// MODE 1: fused LIF per-512-col decay lifw[2..4] -> fp16 spikes (qkv)
// MODE 2: fused LIF decay lifw[7] + bias -> fp16 spikes (fc1)
// MODE 3: bias + residual, write fp32 transposed [T,B,C,N] direct (fc2)
#define LDT 40
#define S_  4
#define STAGE_BYTES (128*LDT*2)
#define GEMM_SMEM (S_*2*STAGE_BYTES)  // 81920
#define STG  132
#define STG3 133

template<int MODE>
__global__ void __launch_bounds__(256, 2) tc_gemm(
        const __half* __restrict__ A, const __half* __restrict__ Wt,
        const float* __restrict__ bias, const float* __restrict__ res,
        float* __restrict__ outf, __half* __restrict__ outh,
        const float* __restrict__ lifw, int Ndim, int K){
    extern __shared__ char smraw[];
    float* stage = (float*)smraw;
    uint32_t sAu = s2u(smraw);
    uint32_t sBu = sAu + S_*STAGE_BYTES;

    int tid = threadIdx.x;
    int warp = tid >> 5, lane = tid & 31;
    int wm = (warp & 1) * 64;
    int wn = (warp >> 1) * 32;
    int bm = blockIdx.y * 128, bn = blockIdx.x * 128;
    float acc[4][4][4] = {};

    const __half* ga[2]; const __half* gb[2];
    uint32_t so[2];
    #pragma unroll
    for (int it = 0; it < 2; it++){
        int task = tid + it*256;
        int row = task >> 2, ch = task & 3;
        int pr = (row & 3)*ROWS_PER_T + (bm >> 2) + (row >> 2);
        ga[it] = A  + (size_t)pr*K + ch*8;
        gb[it] = Wt + (size_t)(bn+row)*K + ch*8;
        so[it] = (uint32_t)((row*LDT + ch*8)*2);
    }

    const int NC = K / 32;
    #pragma unroll
    for (int p = 0; p < S_-1; p++){
        #pragma unroll
        for (int it = 0; it < 2; it++){
            cp16(sAu + p*STAGE_BYTES + so[it], ga[it] + p*32);
            cp16(sBu + p*STAGE_BYTES + so[it], gb[it] + p*32);
        }
        asm volatile("cp.async.commit_group;");
    }

    int l8 = lane >> 3;
    int arow = (lane & 7) + (l8 & 1) * 8, acol = (l8 >> 1) * 8;
    int brow = (lane & 7) + (l8 >> 1) * 8, bcol = (l8 & 1) * 8;
    uint32_t abase[4], bbase[2];
    #pragma unroll
    for (int mi = 0; mi < 4; mi++)
        abase[mi] = sAu + ((wm + mi*16 + arow)*LDT + acol)*2;
    #pragma unroll
    for (int np = 0; np < 2; np++)
        bbase[np] = sBu + ((wn + np*16 + brow)*LDT + bcol)*2;

    for (int c = 0; c < NC; c++){
        uint32_t stoff = (uint32_t)(c % S_) * STAGE_BYTES;
        asm volatile("cp.async.wait_group 2;" ::: "memory");
        __syncthreads();
        if (c + S_-1 < NC){
            uint32_t poff = (uint32_t)((c + S_-1) % S_) * STAGE_BYTES;
            #pragma unroll
            for (int it = 0; it < 2; it++){
                cp16(sAu + poff + so[it], ga[it] + (c+S_-1)*32);
                cp16(sBu + poff + so[it], gb[it] + (c+S_-1)*32);
            }
        }
        asm volatile("cp.async.commit_group;");
        #pragma unroll
        for (int ks = 0; ks < 2; ks++){
            uint32_t af[4][4], bf[2][4];
            #pragma unroll
            for (int mi = 0; mi < 4; mi++)
                ldsm4(af[mi], abase[mi] + stoff + ks*32);
            #pragma unroll
            for (int np = 0; np < 2; np++)
                ldsm4(bf[np], bbase[np] + stoff + ks*32);
            #pragma unroll
            for (int mi = 0; mi < 4; mi++)
                #pragma unroll
                for (int ni = 0; ni < 4; ni++)
                    mma16816(acc[mi][ni], af[mi],
                             bf[ni>>1][2*(ni&1)], bf[ni>>1][2*(ni&1)+1]);
        }
    }

    int g = lane >> 2, i2 = (lane & 3) * 2;
    if (MODE == 0){
        #pragma unroll
        for (int mi = 0; mi < 4; mi++){
            int rl0 = bm + wm + mi*16 + g;
            int rl1 = rl0 + 8;
            int rp0 = (rl0 & 3)*ROWS_PER_T + (rl0 >> 2);
            int rp1 = (rl1 & 3)*ROWS_PER_T + (rl1 >> 2);
            #pragma unroll
            for (int ni = 0; ni < 4; ni++){
                int col = bn + wn + ni*8 + i2;
                float b0 = bias ? bias[col]   : 0.f;
                float b1 = bias ? bias[col+1] : 0.f;
                float v00 = acc[mi][ni][0] + b0, v01 = acc[mi][ni][1] + b1;
                float v10 = acc[mi][ni][2] + b0, v11 = acc[mi][ni][3] + b1;
                size_t o0 = (size_t)rp0*Ndim + col;
                size_t o1 = (size_t)rp1*Ndim + col;
                if (res){
                    v00 += res[o0]; v01 += res[o0+1];
                    v10 += res[o1]; v11 += res[o1+1];
                }
                *(float2*)&outf[o0] = make_float2(v00, v01);
                *(float2*)&outf[o1] = make_float2(v10, v11);
            }
        }
    } else if (MODE == 1 || MODE == 2){
        __syncthreads();
        #pragma unroll
        for (int mi = 0; mi < 4; mi++){
            int r0 = wm + mi*16 + g, r1 = r0 + 8;
            #pragma unroll
            for (int ni = 0; ni < 4; ni++){
                int cl = wn + ni*8 + i2;
                *(float2*)&stage[r0*STG + cl] = make_float2(acc[mi][ni][0], acc[mi][ni][1]);
                *(float2*)&stage[r1*STG + cl] = make_float2(acc[mi][ni][2], acc[mi][ni][3]);
            }
        }
        __syncthreads();
        float d0, d1 = 0.f, d2 = 0.f;
        if (MODE == 1){ d0 = sigm(lifw[2]); d1 = sigm(lifw[3]); d2 = sigm(lifw[4]); }
        else          { d0 = sigm(lifw[7]); }
        #pragma unroll
        for (int it = 0; it < 2; it++){
            int t2 = tid + it*256;
            int bnl = t2 >> 4, cg = (t2 & 15) * 8;
            int gc = bn + cg;
            float dec = (MODE == 1) ? (gc < 512 ? d0 : (gc < 1024 ? d1 : d2)) : d0;
            float bi[8];
            if (bias){
                float4 q0 = *(const float4*)&bias[gc];
                float4 q1 = *(const float4*)&bias[gc+4];
                bi[0]=q0.x; bi[1]=q0.y; bi[2]=q0.z; bi[3]=q0.w;
                bi[4]=q1.x; bi[5]=q1.y; bi[6]=q1.z; bi[7]=q1.w;
            } else {
                #pragma unroll
                for (int j = 0; j < 8; j++) bi[j] = 0.f;
            }
            float v[8];
            #pragma unroll
            for (int j = 0; j < 8; j++) v[j] = 0.f;
            #pragma unroll
            for (int t = 0; t < 4; t++){
                int r = bnl*4 + t;
                float4 x0 = *(float4*)&stage[r*STG + cg];
                float4 x1 = *(float4*)&stage[r*STG + cg + 4];
                float xv[8] = {x0.x,x0.y,x0.z,x0.w,x1.x,x1.y,x1.z,x1.w};
                union { __half h[8]; uint4 u; } pk;
                #pragma unroll
                for (int j = 0; j < 8; j++){
                    float xx = xv[j] + bi[j];
                    v[j] += (xx - v[j])*dec;
                    float sp = (v[j] >= 1.0f) ? 1.f : 0.f;
                    pk.h[j] = __float2half_rn(sp);
                    if (sp > 0.f) v[j] = 0.f;
                }
                int pr = t*ROWS_PER_T + (bm >> 2) + bnl;
                *(uint4*)&outh[(size_t)pr*Ndim + gc] = pk.u;
            }
        }
    } else {
        __syncthreads();
        #pragma unroll
        for (int mi = 0; mi < 4; mi++){
            int r0 = wm + mi*16 + g, r1 = r0 + 8;
            int rl0 = bm + r0, rl1 = bm + r1;
            int rp0 = (rl0 & 3)*ROWS_PER_T + (rl0 >> 2);
            int rp1 = (rl1 & 3)*ROWS_PER_T + (rl1 >> 2);
            #pragma unroll
            for (int ni = 0; ni < 4; ni++){
                int cl = wn + ni*8 + i2;
                int col = bn + cl;
                float b0 = bias[col], b1 = bias[col+1];
                size_t o0 = (size_t)rp0*Ndim + col;
                size_t o1 = (size_t)rp1*Ndim + col;
                stage[r0*STG3 + cl]   = acc[mi][ni][0] + b0 + res[o0];
                stage[r0*STG3 + cl+1] = acc[mi][ni][1] + b1 + res[o0+1];
                stage[r1*STG3 + cl]   = acc[mi][ni][2] + b0 + res[o1];
                stage[r1*STG3 + cl+1] = acc[mi][ni][3] + b1 + res[o1+1];
            }
        }
        __syncthreads();
        int btok = bm >> 2;
        int b = btok >> 8, n0 = btok & 255;
        #pragma unroll
        for (int it = 0; it < 16; it++){
            int f4 = tid + it*256;
            int rown = f4 >> 3;
            int n4 = f4 & 7;
            int cc = rown >> 2, t = rown & 3;
            float4 val;
            val.x = stage[((n4*4+0)*4 + t)*STG3 + cc];
            val.y = stage[((n4*4+1)*4 + t)*STG3 + cc];
            val.z = stage[((n4*4+2)*4 + t)*STG3 + cc];
            val.w = stage[((n4*4+3)*4 + t)*STG3 + cc];
            size_t dst = ((size_t)(t*B_ + b)*C_ + bn + cc)*N_ + n0 + n4*4;
            *(float4*)&outf[dst] = val;
        }
    }
}

// ---------------- all-weights f32 -> f16 convert ----------------------------
__global__ void k_f2hall(const float* __restrict__ w0, const float* __restrict__ w1,
                         const float* __restrict__ w2, const float* __restrict__ w3){
    int i = blockIdx.x*blockDim.x + threadIdx.x;
    const float* src;
    if (i < 196608){ src = w0; }
    else if (i < 262144){ src = w1 - 786432; }
    else if (i < 524288){ src = w2 - 1048576; }
    else { src = w3 - 2097152; }
    float4 f = *(const float4*)&src[i*4];
    union { __half h[4]; uint2 u; } pk;
    pk.h[0]=__float2half_rn(f.x); pk.h[1]=__float2half_rn(f.y);
    pk.h[2]=__float2half_rn(f.z); pk.h[3]=__float2half_rn(f.w);
    *(uint2*)&g_wall[(size_t)i*4] = pk.u;
}

// ---------------- fused input-LIF + depthwise conv + residual ---------------
__global__ void __launch_bounds__(256) k_conv_lif(
        const float* __restrict__ x, const float* __restrict__ cw,
        const float* __restrict__ cb, const float* __restrict__ lifw){
    __shared__ float  xs[16*257];
    __shared__ __half sp[16*264];
    __shared__ float  ws[16*9];
    __shared__ float  wb[16];
    int tid = threadIdx.x;
    int b  = blockIdx.x >> 5;
    int c0 = (blockIdx.x & 31) * 16;
    if (tid < 16*9) ws[tid] = cw[c0*9 + tid];
    if (tid < 16)   wb[tid] = cb[c0 + tid];
    float dec = sigm(lifw[0]);
    float v[16];
    #pragma unroll
    for (int i = 0; i < 16; i++) v[i] = 0.f;
    __syncthreads();
    for (int t = 0; t < T_; t++){
        int tb = t*B_ + b;
        #pragma unroll
        for (int i = 0; i < 16; i++){
            int lin = tid + i*256;
            int cl = lin >> 8, px = lin & 255;
            float xv = x[((size_t)tb*C_ + c0 + cl)*256 + px];
            xs[cl*257 + px] = xv;
            float vv = v[i] + (xv - v[i])*dec;
            float s = (vv >= 1.0f) ? 1.f : 0.f;
            v[i] = (s > 0.f) ? 0.f : vv;
            sp[cl*264 + px] = __float2half_rn(s);
        }
        __syncthreads();
        #pragma unroll
        for (int i = 0; i < 16; i++){
            int lin = tid + i*256;
            int cl = lin & 15, n = lin >> 4;
            int hh = n >> 4, wp = n & 15;
            float acc = wb[cl];
            const float* wk = &ws[cl*9];
            #pragma unroll
            for (int kh = 0; kh < 3; kh++){
                int h2 = hh + kh - 1;
                if (h2 < 0 || h2 > 15) continue;
                #pragma unroll
                for (int kw = 0; kw < 3; kw++){
                    int w2 = wp + kw - 1;
                    if (w2 < 0 || w2 > 15) continue;
                    acc += __half2float(sp[cl*264 + h2*16 + w2]) * wk[kh*3 + kw];
                }
            }
            float val = xs[cl*257 + n] + acc;
            g_xt[((size_t)tb*256 + n)*C_ + c0 + cl] = val;
        }
        __syncthreads();
    }
}

// ---------------- LayerNorm + LIF, warp-per-token ---------------------------
__global__ void __launch_bounds__(256) k_ln_lif(
        const float* __restrict__ in, __half* __restrict__ out,
        const float* __restrict__ gam, const float* __restrict__ bet,
        const float* __restrict__ lifw, int lidx){
    int tid = threadIdx.x, wid = tid >> 5, lane = tid & 31;
    int bn = blockIdx.x*8 + wid;
    int cb = lane*16;
    float dec = sigm(lifw[lidx]);
    float gg[16], bb[16];
    #pragma unroll
    for (int i = 0; i < 4; i++){
        float4 t1 = *(const float4*)&gam[cb + i*4];
        float4 t2 = *(const float4*)&bet[cb + i*4];
        gg[i*4]=t1.x; gg[i*4+1]=t1.y; gg[i*4+2]=t1.z; gg[i*4+3]=t1.w;
        bb[i*4]=t2.x; bb[i*4+1]=t2.y; bb[i*4+2]=t2.z; bb[i*4+3]=t2.w;
    }
    float v[16];
    #pragma unroll
    for (int i = 0; i < 16; i++) v[i] = 0.f;
    for (int t = 0; t < T_; t++){
        int row = t*ROWS_PER_T + bn;
        const float* xr = in + (size_t)row*C_ + cb;
        float xv[16];
        #pragma unroll
        for (int i = 0; i < 4; i++){
            float4 x4 = *(const float4*)&xr[i*4];
            xv[i*4]=x4.x; xv[i*4+1]=x4.y; xv[i*4+2]=x4.z; xv[i*4+3]=x4.w;
        }
        float s = 0.f, ss = 0.f;
        #pragma unroll
        for (int i = 0; i < 16; i++){ s += xv[i]; ss += xv[i]*xv[i]; }
        #pragma unroll
        for (int o = 16; o > 0; o >>= 1){
            s  += __shfl_xor_sync(0xffffffffu, s,  o);
            ss += __shfl_xor_sync(0xffffffffu, ss, o);
        }
        float mean = s*(1.0f/C_);
        float var  = ss*(1.0f/C_) - mean*mean;
        float rstd = rsqrtf(var + 1e-5f);
        union { __half h[16]; uint4 u[2]; } pk;
        #pragma unroll
        for (int k = 0; k < 16; k++){
            float ln = (xv[k]-mean)*rstd*gg[k] + bb[k];
            v[k] += (ln - v[k])*dec;
            float spv = (v[k] >= 1.0f) ? 1.f : 0.f;
            pk.h[k] = __float2half_rn(spv);
            if (spv > 0.f) v[k] = 0.f;
        }
        uint4* dst = (uint4*)(out + (size_t)row*C_ + cb);
        dst[0] = pk.u[0]; dst[1] = pk.u[1];
    }
}

// ---------------- attention phase 1 (HMMA): kvT[e,d] = sum_n v[n,e] k[n,d] --
// grid 512 = tb*8 + h, 128 threads (4 warps), warp handles e-rows 16w.
#define ATT_LD 72
#define ATTKV_SMEM (2*256*ATT_LD*2)   // 73728

__global__ void __launch_bounds__(128) k_attn_kv_mma(){
    extern __shared__ __half satt[];
    __half* sk = satt;                  // [256][72] k spikes
    __half* sv = satt + 256*ATT_LD;     // [256][72] v spikes
    int blk = blockIdx.x;
    int h  = blk & 7;
    int tb = blk >> 3;
    int tid = threadIdx.x, warp = tid >> 5, lane = tid & 31;

    const __half* base = g_q16 + (size_t)tb*256*(3*C_) + h*D_;
    #pragma unroll
    for (int it = 0; it < 16; it++){
        int task = tid + it*128;            // 0..2047
        int row = task >> 3, ch = task & 7; // 256 rows x 8 chunks
        cp16(s2u(&sk[row*ATT_LD + ch*8]), base + (size_t)row*(3*C_) + C_   + ch*8);
        cp16(s2u(&sv[row*ATT_LD + ch*8]), base + (size_t)row*(3*C_) + 2*C_ + ch*8);
    }
    asm volatile("cp.async.commit_group;");
    asm volatile("cp.async.wait_group 0;" ::: "memory");
    __syncthreads();

    // trans-load lane mappings
    int l8 = lane >> 3;
    int a_r = (lane & 7) + (l8 >> 1)*8;      // token-row within 16
    int a_c = warp*16 + (l8 & 1)*8;          // e col
    int b_r = (lane & 7) + (l8 & 1)*8;       // token-row within 16
    int b_c = (l8 >> 1)*8;                   // d col offset within 16-tile

    float acc[8][4] = {};
    #pragma unroll 4
    for (int s = 0; s < 16; s++){
        uint32_t af[4];
        ldsm4t(af, s2u(&sv[(s*16 + a_r)*ATT_LD + a_c]));
        #pragma unroll
        for (int j = 0; j < 4; j++){
            uint32_t bf[4];
            ldsm4t(bf, s2u(&sk[(s*16 + b_r)*ATT_LD + j*16 + b_c]));
            mma16816(acc[2*j],   af, bf[0], bf[1]);
            mma16816(acc[2*j+1], af, bf[2], bf[3]);
        }
    }

    // store kvT (integers <=256, exact fp16) to gmem [e][d]
    __half* dst = g_kvT + (size_t)blk*(D_*D_);
    int g = lane >> 2, i2 = (lane & 3)*2;
    int r0 = warp*16 + g, r1 = r0 + 8;
    #pragma unroll
    for (int ni = 0; ni < 8; ni++){
        int col = ni*8 + i2;
        *(__half2*)&dst[r0*D_ + col] = __floats2half2_rn(acc[ni][0], acc[ni][1]);
        *(__half2*)&dst[r1*D_ + col] = __floats2half2_rn(acc[ni][2], acc[ni][3]);
    }
}

// ---------------- attention phase 2 (HMMA): a = q@kvT*scale + LIF -----------
// grid 512 = b*32 + h*4 + nt (nt = 64-token tile), 128 threads, loop T.
__global__ void __launch_bounds__(128) k_attn_av_mma(const float* __restrict__ lifw){
    __shared__ __half sq [64*ATT_LD];
    __shared__ __half skv[64*ATT_LD];
    int blk = blockIdx.x;
    int nt = blk & 3;
    int h  = (blk >> 2) & 7;
    int b  = blk >> 5;
    int tid = threadIdx.x, warp = tid >> 5, lane = tid & 31;
    float dec = sigm(lifw[5]);

    int l8 = lane >> 3;
    int arow = (lane & 7) + (l8 & 1)*8, acol = (l8 >> 1)*8;
    int brow = (lane & 7) + (l8 >> 1)*8, bcol = (l8 & 1)*8;
    int g = lane >> 2, i2 = (lane & 3)*2;

    float vst[8][4];
    #pragma unroll
    for (int ni = 0; ni < 8; ni++)
        #pragma unroll
        for (int c = 0; c < 4; c++) vst[ni][c] = 0.f;

    for (int t = 0; t < T_; t++){
        int tb = t*B_ + b;
        const __half* qb = g_q16 + ((size_t)tb*256 + nt*64)*(3*C_) + h*D_;
        const __half* kb = g_kvT + (size_t)(tb*NH_ + h)*(D_*D_);
        #pragma unroll
        for (int it = 0; it < 4; it++){
            int task = tid + it*128;            // 0..511
            int row = task >> 3, ch = task & 7;
            cp16(s2u(&sq [row*ATT_LD + ch*8]), qb + (size_t)row*(3*C_) + ch*8);
            cp16(s2u(&skv[row*ATT_LD + ch*8]), kb + row*D_ + ch*8);
        }
        asm volatile("cp.async.commit_group;");
        asm volatile("cp.async.wait_group 0;" ::: "memory");
        __syncthreads();

        float acc[8][4] = {};
        #pragma unroll
        for (int s = 0; s < 4; s++){
            uint32_t af[4];
            ldsm4(af, s2u(&sq[(warp*16 + arow)*ATT_LD + s*16 + acol]));
            #pragma unroll
            for (int j = 0; j < 4; j++){
                uint32_t bf[4];
                ldsm4(bf, s2u(&skv[(j*16 + brow)*ATT_LD + s*16 + bcol]));
                mma16816(acc[2*j],   af, bf[0], bf[1]);
                mma16816(acc[2*j+1], af, bf[2], bf[3]);
            }
        }

        // LIF + spike store
        int row0 = tb*256 + nt*64 + warp*16 + g;
        #pragma unroll
        for (int ni = 0; ni < 8; ni++){
            int col = h*D_ + ni*8 + i2;
            __half sp[4];
            #pragma unroll
            for (int c = 0; c < 4; c++){
                float a = acc[ni][c]*0.125f;
                float* v = &vst[ni][c];
                *v += (a - *v)*dec;
                float s = (*v >= 1.0f) ? 1.f : 0.f;
                sp[c] = __float2half_rn(s);
                if (s > 0.f) *v = 0.f;
            }
            *(__half2*)&g_a16[(size_t)row0*C_ + col]     = *(__half2*)&sp[0];
            *(__half2*)&g_a16[(size_t)(row0+8)*C_ + col] = *(__half2*)&sp[2];
        }
        __syncthreads();
    }
}

// ---------------- host orchestration ----------------------------------------
extern "C" void kernel_launch(void* const* d_in, const int* in_sizes, int n_in,
                              void* d_out, int out_size){
    const float* x      = (const float*)d_in[0];
    const float* conv_w = (const float*)d_in[1];
    const float* conv_b = (const float*)d_in[2];
    const float* ln1_g  = (const float*)d_in[3];
    const float* ln1_b  = (const float*)d_in[4];
    const float* qkv_w  = (const float*)d_in[5];
    const float* proj_w = (const float*)d_in[6];
    const float* proj_b = (const float*)d_in[7];
    const float* ln2_g  = (const float*)d_in[8];
    const float* ln2_b  = (const float*)d_in[9];
    const float* fc1_w  = (const float*)d_in[10];
    const float* fc1_b  = (const float*)d_in[11];
    const float* fc2_w  = (const float*)d_in[12];
    const float* fc2_b  = (const float*)d_in[13];
    const float* lif_w  = (const float*)d_in[14];
    float* out = (float*)d_out;

    cudaFuncSetAttribute(tc_gemm<0>, cudaFuncAttributeMaxDynamicSharedMemorySize, GEMM_SMEM);
    cudaFuncSetAttribute(tc_gemm<1>, cudaFuncAttributeMaxDynamicSharedMemorySize, GEMM_SMEM);
    cudaFuncSetAttribute(tc_gemm<2>, cudaFuncAttributeMaxDynamicSharedMemorySize, GEMM_SMEM);
    cudaFuncSetAttribute(tc_gemm<3>, cudaFuncAttributeMaxDynamicSharedMemorySize, GEMM_SMEM);
    cudaFuncSetAttribute(k_attn_kv_mma, cudaFuncAttributeMaxDynamicSharedMemorySize, ATTKV_SMEM);

    float *p_xt, *p_xt2;
    __half *p_h16, *p_q16, *p_a16, *p_m16, *p_w;
    cudaGetSymbolAddress((void**)&p_xt,  g_xt);
    cudaGetSymbolAddress((void**)&p_xt2, g_xt2);
    cudaGetSymbolAddress((void**)&p_h16, g_h16);
    cudaGetSymbolAddress((void**)&p_q16, g_q16);
    cudaGetSymbolAddress((void**)&p_a16, g_a16);
    cudaGetSymbolAddress((void**)&p_m16, g_m16);
    cudaGetSymbolAddress((void**)&p_w,   g_wall);

    k_f2hall<<<786432/256, 256>>>(qkv_w, proj_w, fc1_w, fc2_w);
    k_conv_lif<<<512, 256>>>(x, conv_w, conv_b, lif_w);
    k_ln_lif<<<512, 256>>>(p_xt, p_h16, ln1_g, ln1_b, lif_w, 1);
    tc_gemm<1><<<dim3(12,128), 256, GEMM_SMEM>>>(p_h16, p_w + WOFF_QKV, nullptr, nullptr,
                                                 nullptr, p_q16, lif_w, 3*C_, C_);
    k_attn_kv_mma<<<512, 128, ATTKV_SMEM>>>();
    k_attn_av_mma<<<512, 128>>>(lif_w);
    tc_gemm<0><<<dim3(4,128), 256, GEMM_SMEM>>>(p_a16, p_w + WOFF_PROJ, proj_b, p_xt,
                                                p_xt2, nullptr, lif_w, C_, C_);
    k_ln_lif<<<512, 256>>>(p_xt2, p_h16, ln2_g, ln2_b, lif_w, 6);
    tc_gemm<2><<<dim3(16,128), 256, GEMM_SMEM>>>(p_h16, p_w + WOFF_FC1, fc1_b, nullptr,
                                                 nullptr, p_m16, lif_w, HID_, C_);
    tc_gemm<3><<<dim3(4,128), 256, GEMM_SMEM>>>(p_m16, p_w + WOFF_FC2, fc2_b, p_xt2,
                                                out, nullptr, lif_w, C_, HID_);
}

// round 10
// speedup vs baseline: 1.5567x; 1.0394x over previous
#include <cuda_runtime.h>
#include <cuda_fp16.h>
#include <math.h>
#include <stdint.h>

// ---------------- problem constants ----------------
#define T_  4
#define B_  16
#define C_  512
#define H_  16
#define W_  16
#define N_  256
#define NH_ 8
#define D_  64
#define M_  (T_*B_*N_)     // 16384
#define HID_ 2048
#define ROWS_PER_T (B_*N_) // 4096

// ---------------- scratch ----------------
__device__ float  g_xt [M_*C_];
__device__ float  g_xt2[M_*C_];
__device__ __half g_h16[M_*C_];
__device__ __half g_q16[M_*3*C_];
__device__ __half g_a16[M_*C_];
__device__ __half g_m16[M_*HID_];
__device__ __half g_kvT[T_*B_*NH_*D_*D_];
__device__ __half g_wall[3*C_*C_ + C_*C_ + 2*HID_*C_];

#define WOFF_QKV  0
#define WOFF_PROJ (3*C_*C_)
#define WOFF_FC1  (WOFF_PROJ + C_*C_)
#define WOFF_FC2  (WOFF_FC1 + HID_*C_)

__device__ __forceinline__ float sigm(float w){ return 1.0f/(1.0f+expf(-w)); }
__device__ __forceinline__ uint32_t s2u(const void* p){
    uint32_t a;
    asm("{ .reg .u64 t; cvta.to.shared.u64 t, %1; cvt.u32.u64 %0, t; }" : "=r"(a) : "l"(p));
    return a;
}
__device__ __forceinline__ void cp16(uint32_t s, const void* g){
    asm volatile("cp.async.cg.shared.global [%0], [%1], 16;" :: "r"(s), "l"(g));
}
__device__ __forceinline__ void ldsm4(uint32_t* r, uint32_t addr){
    asm volatile("ldmatrix.sync.aligned.m8n8.x4.shared.b16 {%0,%1,%2,%3}, [%4];"
                 : "=r"(r[0]), "=r"(r[1]), "=r"(r[2]), "=r"(r[3]) : "r"(addr));
}
__device__ __forceinline__ void ldsm4t(uint32_t* r, uint32_t addr){
    asm volatile("ldmatrix.sync.aligned.m8n8.x4.trans.shared.b16 {%0,%1,%2,%3}, [%4];"
                 : "=r"(r[0]), "=r"(r[1]), "=r"(r[2]), "=r"(r[3]) : "r"(addr));
}
__device__ __forceinline__ void mma16816(float* c, const uint32_t* a, uint32_t b0, uint32_t b1){
    asm volatile(
        "mma.sync.aligned.m16n8k16.row.col.f32.f16.f16.f32 "
        "{%0,%1,%2,%3}, {%4,%5,%6,%7}, {%8,%9}, {%0,%1,%2,%3};"
        : "+f"(c[0]), "+f"(c[1]), "+f"(c[2]), "+f"(c[3])
        : "r"(a[0]), "r"(a[1]), "r"(a[2]), "r"(a[3]), "r"(b0), "r"(b1));
}

// ---------------- HMMA GEMM, BK=64, 3-stage ring ----------------------------
// logical row r = bn_token*4 + t  <->  phys row = (r&3)*4096 + (r>>2)
// MODE 0: fp32 out + bias + residual (proj)
// MODE 1: fused LIF per-512-col decay lifw[2..4] -> fp16 spikes (qkv)
// MODE 2: fused LIF decay lifw[7] + bias -> fp16 spikes (fc1)
// MODE 3: bias + residual, write fp32 transposed [T,B,C,N] direct (fc2)
#define LDT 72
#define S_  3
#define BKC 64
#define STAGE_BYTES (128*LDT*2)       // 18432
#define GEMM_SMEM (S_*2*STAGE_BYTES)  // 110592
#define STG  132
#define STG3 133

template<int MODE>
__global__ void __launch_bounds__(256, 2) tc_gemm(
        const __half* __restrict__ A, const __half* __restrict__ Wt,
        const float* __restrict__ bias, const float* __restrict__ res,
        float* __restrict__ outf, __half* __restrict__ outh,
        const float* __restrict__ lifw, int Ndim, int K){
    extern __shared__ char smraw[];
    float* stage = (float*)smraw;
    uint32_t sAu = s2u(smraw);
    uint32_t sBu = sAu + S_*STAGE_BYTES;

    int tid = threadIdx.x;
    int warp = tid >> 5, lane = tid & 31;
    int wm = (warp & 1) * 64;
    int wn = (warp >> 1) * 32;
    int bm = blockIdx.y * 128, bn = blockIdx.x * 128;
    float acc[4][4][4] = {};

    // base load task: row0 = tid>>3 (0..31), ch = tid&7; task it adds 32 rows
    int row0 = tid >> 3, ch = tid & 7;
    int pr0 = (row0 & 3)*ROWS_PER_T + (bm >> 2) + (row0 >> 2);
    const __half* ga0 = A  + (size_t)pr0*K + ch*8;          // +it*8*K  (pr +8)
    const __half* gb0 = Wt + (size_t)(bn+row0)*K + ch*8;    // +it*32*K
    uint32_t so0 = (uint32_t)((row0*LDT + ch*8)*2);         // +it*32*LDT*2

    const int NC = K / BKC;
    #pragma unroll
    for (int p = 0; p < S_-1; p++){
        #pragma unroll
        for (int it = 0; it < 4; it++){
            cp16(sAu + p*STAGE_BYTES + so0 + it*(32*LDT*2), ga0 + p*BKC + (size_t)it*8*K);
            cp16(sBu + p*STAGE_BYTES + so0 + it*(32*LDT*2), gb0 + p*BKC + (size_t)it*32*K);
        }
        asm volatile("cp.async.commit_group;");
    }

    int l8 = lane >> 3;
    int arow = (lane & 7) + (l8 & 1) * 8, acol = (l8 >> 1) * 8;
    int brow = (lane & 7) + (l8 >> 1) * 8, bcol = (l8 & 1) * 8;
    uint32_t abase[4], bbase[2];
    #pragma unroll
    for (int mi = 0; mi < 4; mi++)
        abase[mi] = sAu + ((wm + mi*16 + arow)*LDT + acol)*2;
    #pragma unroll
    for (int np = 0; np < 2; np++)
        bbase[np] = sBu + ((wn + np*16 + brow)*LDT + bcol)*2;

    for (int c = 0; c < NC; c++){
        uint32_t stoff = (uint32_t)(c % S_) * STAGE_BYTES;
        asm volatile("cp.async.wait_group 1;" ::: "memory");
        __syncthreads();
        if (c + 2 < NC){
            uint32_t poff = (uint32_t)((c + 2) % S_) * STAGE_BYTES;
            int koff = (c + 2)*BKC;
            #pragma unroll
            for (int it = 0; it < 4; it++){
                cp16(sAu + poff + so0 + it*(32*LDT*2), ga0 + koff + (size_t)it*8*K);
                cp16(sBu + poff + so0 + it*(32*LDT*2), gb0 + koff + (size_t)it*32*K);
            }
        }
        asm volatile("cp.async.commit_group;");
        #pragma unroll
        for (int ks = 0; ks < 4; ks++){
            uint32_t af[4][4], bf[2][4];
            #pragma unroll
            for (int mi = 0; mi < 4; mi++)
                ldsm4(af[mi], abase[mi] + stoff + ks*32);
            #pragma unroll
            for (int np = 0; np < 2; np++)
                ldsm4(bf[np], bbase[np] + stoff + ks*32);
            #pragma unroll
            for (int mi = 0; mi < 4; mi++)
                #pragma unroll
                for (int ni = 0; ni < 4; ni++)
                    mma16816(acc[mi][ni], af[mi],
                             bf[ni>>1][2*(ni&1)], bf[ni>>1][2*(ni&1)+1]);
        }
    }

    int g = lane >> 2, i2 = (lane & 3) * 2;
    if (MODE == 0){
        #pragma unroll
        for (int mi = 0; mi < 4; mi++){
            int rl0 = bm + wm + mi*16 + g;
            int rl1 = rl0 + 8;
            int rp0 = (rl0 & 3)*ROWS_PER_T + (rl0 >> 2);
            int rp1 = (rl1 & 3)*ROWS_PER_T + (rl1 >> 2);
            #pragma unroll
            for (int ni = 0; ni < 4; ni++){
                int col = bn + wn + ni*8 + i2;
                float b0 = bias ? bias[col]   : 0.f;
                float b1 = bias ? bias[col+1] : 0.f;
                float v00 = acc[mi][ni][0] + b0, v01 = acc[mi][ni][1] + b1;
                float v10 = acc[mi][ni][2] + b0, v11 = acc[mi][ni][3] + b1;
                size_t o0 = (size_t)rp0*Ndim + col;
                size_t o1 = (size_t)rp1*Ndim + col;
                if (res){
                    v00 += res[o0]; v01 += res[o0+1];
                    v10 += res[o1]; v11 += res[o1+1];
                }
                *(float2*)&outf[o0] = make_float2(v00, v01);
                *(float2*)&outf[o1] = make_float2(v10, v11);
            }
        }
    } else if (MODE == 1 || MODE == 2){
        __syncthreads();
        #pragma unroll
        for (int mi = 0; mi < 4; mi++){
            int r0 = wm + mi*16 + g, r1 = r0 + 8;
            #pragma unroll
            for (int ni = 0; ni < 4; ni++){
                int cl = wn + ni*8 + i2;
                *(float2*)&stage[r0*STG + cl] = make_float2(acc[mi][ni][0], acc[mi][ni][1]);
                *(float2*)&stage[r1*STG + cl] = make_float2(acc[mi][ni][2], acc[mi][ni][3]);
            }
        }
        __syncthreads();
        float d0, d1 = 0.f, d2 = 0.f;
        if (MODE == 1){ d0 = sigm(lifw[2]); d1 = sigm(lifw[3]); d2 = sigm(lifw[4]); }
        else          { d0 = sigm(lifw[7]); }
        #pragma unroll
        for (int it = 0; it < 2; it++){
            int t2 = tid + it*256;
            int bnl = t2 >> 4, cg = (t2 & 15) * 8;
            int gc = bn + cg;
            float dec = (MODE == 1) ? (gc < 512 ? d0 : (gc < 1024 ? d1 : d2)) : d0;
            float bi[8];
            if (bias){
                float4 q0 = *(const float4*)&bias[gc];
                float4 q1 = *(const float4*)&bias[gc+4];
                bi[0]=q0.x; bi[1]=q0.y; bi[2]=q0.z; bi[3]=q0.w;
                bi[4]=q1.x; bi[5]=q1.y; bi[6]=q1.z; bi[7]=q1.w;
            } else {
                #pragma unroll
                for (int j = 0; j < 8; j++) bi[j] = 0.f;
            }
            float v[8];
            #pragma unroll
            for (int j = 0; j < 8; j++) v[j] = 0.f;
            #pragma unroll
            for (int t = 0; t < 4; t++){
                int r = bnl*4 + t;
                float4 x0 = *(float4*)&stage[r*STG + cg];
                float4 x1 = *(float4*)&stage[r*STG + cg + 4];
                float xv[8] = {x0.x,x0.y,x0.z,x0.w,x1.x,x1.y,x1.z,x1.w};
                union { __half h[8]; uint4 u; } pk;
                #pragma unroll
                for (int j = 0; j < 8; j++){
                    float xx = xv[j] + bi[j];
                    v[j] += (xx - v[j])*dec;
                    float sp = (v[j] >= 1.0f) ? 1.f : 0.f;
                    pk.h[j] = __float2half_rn(sp);
                    if (sp > 0.f) v[j] = 0.f;
                }
                int pr = t*ROWS_PER_T + (bm >> 2) + bnl;
                *(uint4*)&outh[(size_t)pr*Ndim + gc] = pk.u;
            }
        }
    } else {
        __syncthreads();
        #pragma unroll
        for (int mi = 0; mi < 4; mi++){
            int r0 = wm + mi*16 + g, r1 = r0 + 8;
            int rl0 = bm + r0, rl1 = bm + r1;
            int rp0 = (rl0 & 3)*ROWS_PER_T + (rl0 >> 2);
            int rp1 = (rl1 & 3)*ROWS_PER_T + (rl1 >> 2);
            #pragma unroll
            for (int ni = 0; ni < 4; ni++){
                int cl = wn + ni*8 + i2;
                int col = bn + cl;
                float b0 = bias[col], b1 = bias[col+1];
                size_t o0 = (size_t)rp0*Ndim + col;
                size_t o1 = (size_t)rp1*Ndim + col;
                stage[r0*STG3 + cl]   = acc[mi][ni][0] + b0 + res[o0];
                stage[r0*STG3 + cl+1] = acc[mi][ni][1] + b1 + res[o0+1];
                stage[r1*STG3 + cl]   = acc[mi][ni][2] + b0 + res[o1];
                stage[r1*STG3 + cl+1] = acc[mi][ni][3] + b1 + res[o1+1];
            }
        }
        __syncthreads();
        int btok = bm >> 2;
        int b = btok >> 8, n0 = btok & 255;
        #pragma unroll
        for (int it = 0; it < 16; it++){
            int f4 = tid + it*256;
            int rown = f4 >> 3;
            int n4 = f4 & 7;
            int cc = rown >> 2, t = rown & 3;
            float4 val;
            val.x = stage[((n4*4+0)*4 + t)*STG3 + cc];
            val.y = stage[((n4*4+1)*4 + t)*STG3 + cc];
            val.z = stage[((n4*4+2)*4 + t)*STG3 + cc];
            val.w = stage[((n4*4+3)*4 + t)*STG3 + cc];
            size_t dst = ((size_t)(t*B_ + b)*C_ + bn + cc)*N_ + n0 + n4*4;
            *(float4*)&outf[dst] = val;
        }
    }
}

// ---------------- all-weights f32 -> f16 convert ----------------------------
__global__ void k_f2hall(const float* __restrict__ w0, const float* __restrict__ w1,
                         const float* __restrict__ w2, const float* __restrict__ w3){
    int i = blockIdx.x*blockDim.x + threadIdx.x;
    const float* src;
    if (i < 196608){ src = w0; }
    else if (i < 262144){ src = w1 - 786432; }
    else if (i < 524288){ src = w2 - 1048576; }
    else { src = w3 - 2097152; }
    float4 f = *(const float4*)&src[i*4];
    union { __half h[4]; uint2 u; } pk;
    pk.h[0]=__float2half_rn(f.x); pk.h[1]=__float2half_rn(f.y);
    pk.h[2]=__float2half_rn(f.z); pk.h[3]=__float2half_rn(f.w);
    *(uint2*)&g_wall[(size_t)i*4] = pk.u;
}

// ---------------- fused input-LIF + depthwise conv + residual ---------------
__global__ void __launch_bounds__(256) k_conv_lif(
        const float* __restrict__ x, const float* __restrict__ cw,
        const float* __restrict__ cb, const float* __restrict__ lifw){
    __shared__ float  xs[16*257];
    __shared__ __half sp[16*264];
    __shared__ float  ws[16*9];
    __shared__ float  wb[16];
    int tid = threadIdx.x;
    int b  = blockIdx.x >> 5;
    int c0 = (blockIdx.x & 31) * 16;
    if (tid < 16*9) ws[tid] = cw[c0*9 + tid];
    if (tid < 16)   wb[tid] = cb[c0 + tid];
    float dec = sigm(lifw[0]);
    float v[16];
    #pragma unroll
    for (int i = 0; i < 16; i++) v[i] = 0.f;
    __syncthreads();
    for (int t = 0; t < T_; t++){
        int tb = t*B_ + b;
        #pragma unroll
        for (int i = 0; i < 16; i++){
            int lin = tid + i*256;
            int cl = lin >> 8, px = lin & 255;
            float xv = x[((size_t)tb*C_ + c0 + cl)*256 + px];
            xs[cl*257 + px] = xv;
            float vv = v[i] + (xv - v[i])*dec;
            float s = (vv >= 1.0f) ? 1.f : 0.f;
            v[i] = (s > 0.f) ? 0.f : vv;
            sp[cl*264 + px] = __float2half_rn(s);
        }
        __syncthreads();
        #pragma unroll
        for (int i = 0; i < 16; i++){
            int lin = tid + i*256;
            int cl = lin & 15, n = lin >> 4;
            int hh = n >> 4, wp = n & 15;
            float acc = wb[cl];
            const float* wk = &ws[cl*9];
            #pragma unroll
            for (int kh = 0; kh < 3; kh++){
                int h2 = hh + kh - 1;
                if (h2 < 0 || h2 > 15) continue;
                #pragma unroll
                for (int kw = 0; kw < 3; kw++){
                    int w2 = wp + kw - 1;
                    if (w2 < 0 || w2 > 15) continue;
                    acc += __half2float(sp[cl*264 + h2*16 + w2]) * wk[kh*3 + kw];
                }
            }
            float val = xs[cl*257 + n] + acc;
            g_xt[((size_t)tb*256 + n)*C_ + c0 + cl] = val;
        }
        __syncthreads();
    }
}

// ---------------- LayerNorm + LIF, warp-per-token ---------------------------
__global__ void __launch_bounds__(256) k_ln_lif(
        const float* __restrict__ in, __half* __restrict__ out,
        const float* __restrict__ gam, const float* __restrict__ bet,
        const float* __restrict__ lifw, int lidx){
    int tid = threadIdx.x, wid = tid >> 5, lane = tid & 31;
    int bn = blockIdx.x*8 + wid;
    int cb = lane*16;
    float dec = sigm(lifw[lidx]);
    float gg[16], bb[16];
    #pragma unroll
    for (int i = 0; i < 4; i++){
        float4 t1 = *(const float4*)&gam[cb + i*4];
        float4 t2 = *(const float4*)&bet[cb + i*4];
        gg[i*4]=t1.x; gg[i*4+1]=t1.y; gg[i*4+2]=t1.z; gg[i*4+3]=t1.w;
        bb[i*4]=t2.x; bb[i*4+1]=t2.y; bb[i*4+2]=t2.z; bb[i*4+3]=t2.w;
    }
    float v[16];
    #pragma unroll
    for (int i = 0; i < 16; i++) v[i] = 0.f;
    for (int t = 0; t < T_; t++){
        int row = t*ROWS_PER_T + bn;
        const float* xr = in + (size_t)row*C_ + cb;
        float xv[16];
        #pragma unroll
        for (int i = 0; i < 4; i++){
            float4 x4 = *(const float4*)&xr[i*4];
            xv[i*4]=x4.x; xv[i*4+1]=x4.y; xv[i*4+2]=x4.z; xv[i*4+3]=x4.w;
        }
        float s = 0.f, ss = 0.f;
        #pragma unroll
        for (int i = 0; i < 16; i++){ s += xv[i]; ss += xv[i]*xv[i]; }
        #pragma unroll
        for (int o = 16; o > 0; o >>= 1){
            s  += __shfl_xor_sync(0xffffffffu, s,  o);
            ss += __shfl_xor_sync(0xffffffffu, ss, o);
        }
        float mean = s*(1.0f/C_);
        float var  = ss*(1.0f/C_) - mean*mean;
        float rstd = rsqrtf(var + 1e-5f);
        union { __half h[16]; uint4 u[2]; } pk;
        #pragma unroll
        for (int k = 0; k < 16; k++){
            float ln = (xv[k]-mean)*rstd*gg[k] + bb[k];
            v[k] += (ln - v[k])*dec;
            float spv = (v[k] >= 1.0f) ? 1.f : 0.f;
            pk.h[k] = __float2half_rn(spv);
            if (spv > 0.f) v[k] = 0.f;
        }
        uint4* dst = (uint4*)(out + (size_t)row*C_ + cb);
        dst[0] = pk.u[0]; dst[1] = pk.u[1];
    }
}

// ---------------- attention phase 1 (HMMA): kvT[e,d] = sum_n v[n,e] k[n,d] --
#define ATT_LD 72
#define ATTKV_SMEM (2*256*ATT_LD*2)   // 73728

__global__ void __launch_bounds__(128) k_attn_kv_mma(){
    extern __shared__ __half satt[];
    __half* sk = satt;
    __half* sv = satt + 256*ATT_LD;
    int blk = blockIdx.x;
    int h  = blk & 7;
    int tb = blk >> 3;
    int tid = threadIdx.x, warp = tid >> 5, lane = tid & 31;

    const __half* base = g_q16 + (size_t)tb*256*(3*C_) + h*D_;
    #pragma unroll
    for (int it = 0; it < 16; it++){
        int task = tid + it*128;
        int row = task >> 3, ch = task & 7;
        cp16(s2u(&sk[row*ATT_LD + ch*8]), base + (size_t)row*(3*C_) + C_   + ch*8);
        cp16(s2u(&sv[row*ATT_LD + ch*8]), base + (size_t)row*(3*C_) + 2*C_ + ch*8);
    }
    asm volatile("cp.async.commit_group;");
    asm volatile("cp.async.wait_group 0;" ::: "memory");
    __syncthreads();

    int l8 = lane >> 3;
    int a_r = (lane & 7) + (l8 >> 1)*8;
    int a_c = warp*16 + (l8 & 1)*8;
    int b_r = (lane & 7) + (l8 & 1)*8;
    int b_c = (l8 >> 1)*8;

    float acc[8][4] = {};
    #pragma unroll 4
    for (int s = 0; s < 16; s++){
        uint32_t af[4];
        ldsm4t(af, s2u(&sv[(s*16 + a_r)*ATT_LD + a_c]));
        #pragma unroll
        for (int j = 0; j < 4; j++){
            uint32_t bf[4];
            ldsm4t(bf, s2u(&sk[(s*16 + b_r)*ATT_LD + j*16 + b_c]));
            mma16816(acc[2*j],   af, bf[0], bf[1]);
            mma16816(acc[2*j+1], af, bf[2], bf[3]);
        }
    }

    __half* dst = g_kvT + (size_t)blk*(D_*D_);
    int g = lane >> 2, i2 = (lane & 3)*2;
    int r0 = warp*16 + g, r1 = r0 + 8;
    #pragma unroll
    for (int ni = 0; ni < 8; ni++){
        int col = ni*8 + i2;
        *(__half2*)&dst[r0*D_ + col] = __floats2half2_rn(acc[ni][0], acc[ni][1]);
        *(__half2*)&dst[r1*D_ + col] = __floats2half2_rn(acc[ni][2], acc[ni][3]);
    }
}

// ---------------- attention phase 2 (HMMA): a = q@kvT*scale + LIF -----------
__global__ void __launch_bounds__(128) k_attn_av_mma(const float* __restrict__ lifw){
    __shared__ __half sq [64*ATT_LD];
    __shared__ __half skv[64*ATT_LD];
    int blk = blockIdx.x;
    int nt = blk & 3;
    int h  = (blk >> 2) & 7;
    int b  = blk >> 5;
    int tid = threadIdx.x, warp = tid >> 5, lane = tid & 31;
    float dec = sigm(lifw[5]);

    int l8 = lane >> 3;
    int arow = (lane & 7) + (l8 & 1)*8, acol = (l8 >> 1)*8;
    int brow = (lane & 7) + (l8 >> 1)*8, bcol = (l8 & 1)*8;
    int g = lane >> 2, i2 = (lane & 3)*2;

    float vst[8][4];
    #pragma unroll
    for (int ni = 0; ni < 8; ni++)
        #pragma unroll
        for (int c = 0; c < 4; c++) vst[ni][c] = 0.f;

    for (int t = 0; t < T_; t++){
        int tb = t*B_ + b;
        const __half* qb = g_q16 + ((size_t)tb*256 + nt*64)*(3*C_) + h*D_;
        const __half* kb = g_kvT + (size_t)(tb*NH_ + h)*(D_*D_);
        #pragma unroll
        for (int it = 0; it < 4; it++){
            int task = tid + it*128;
            int row = task >> 3, ch = task & 7;
            cp16(s2u(&sq [row*ATT_LD + ch*8]), qb + (size_t)row*(3*C_) + ch*8);
            cp16(s2u(&skv[row*ATT_LD + ch*8]), kb + row*D_ + ch*8);
        }
        asm volatile("cp.async.commit_group;");
        asm volatile("cp.async.wait_group 0;" ::: "memory");
        __syncthreads();

        float acc[8][4] = {};
        #pragma unroll
        for (int s = 0; s < 4; s++){
            uint32_t af[4];
            ldsm4(af, s2u(&sq[(warp*16 + arow)*ATT_LD + s*16 + acol]));
            #pragma unroll
            for (int j = 0; j < 4; j++){
                uint32_t bf[4];
                ldsm4(bf, s2u(&skv[(j*16 + brow)*ATT_LD + s*16 + bcol]));
                mma16816(acc[2*j],   af, bf[0], bf[1]);
                mma16816(acc[2*j+1], af, bf[2], bf[3]);
            }
        }

        int row0 = tb*256 + nt*64 + warp*16 + g;
        #pragma unroll
        for (int ni = 0; ni < 8; ni++){
            int col = h*D_ + ni*8 + i2;
            __half sp[4];
            #pragma unroll
            for (int c = 0; c < 4; c++){
                float a = acc[ni][c]*0.125f;
                float* v = &vst[ni][c];
                *v += (a - *v)*dec;
                float s = (*v >= 1.0f) ? 1.f : 0.f;
                sp[c] = __float2half_rn(s);
                if (s > 0.f) *v = 0.f;
            }
            *(__half2*)&g_a16[(size_t)row0*C_ + col]     = *(__half2*)&sp[0];
            *(__half2*)&g_a16[(size_t)(row0+8)*C_ + col] = *(__half2*)&sp[2];
        }
        __syncthreads();
    }
}

// ---------------- host orchestration ----------------------------------------
extern "C" void kernel_launch(void* const* d_in, const int* in_sizes, int n_in,
                              void* d_out, int out_size){
    const float* x      = (const float*)d_in[0];
    const float* conv_w = (const float*)d_in[1];
    const float* conv_b = (const float*)d_in[2];
    const float* ln1_g  = (const float*)d_in[3];
    const float* ln1_b  = (const float*)d_in[4];
    const float* qkv_w  = (const float*)d_in[5];
    const float* proj_w = (const float*)d_in[6];
    const float* proj_b = (const float*)d_in[7];
    const float* ln2_g  = (const float*)d_in[8];
    const float* ln2_b  = (const float*)d_in[9];
    const float* fc1_w  = (const float*)d_in[10];
    const float* fc1_b  = (const float*)d_in[11];
    const float* fc2_w  = (const float*)d_in[12];
    const float* fc2_b  = (const float*)d_in[13];
    const float* lif_w  = (const float*)d_in[14];
    float* out = (float*)d_out;

    cudaFuncSetAttribute(tc_gemm<0>, cudaFuncAttributeMaxDynamicSharedMemorySize, GEMM_SMEM);
    cudaFuncSetAttribute(tc_gemm<1>, cudaFuncAttributeMaxDynamicSharedMemorySize, GEMM_SMEM);
    cudaFuncSetAttribute(tc_gemm<2>, cudaFuncAttributeMaxDynamicSharedMemorySize, GEMM_SMEM);
    cudaFuncSetAttribute(tc_gemm<3>, cudaFuncAttributeMaxDynamicSharedMemorySize, GEMM_SMEM);
    cudaFuncSetAttribute(k_attn_kv_mma, cudaFuncAttributeMaxDynamicSharedMemorySize, ATTKV_SMEM);

    float *p_xt, *p_xt2;
    __half *p_h16, *p_q16, *p_a16, *p_m16, *p_w;
    cudaGetSymbolAddress((void**)&p_xt,  g_xt);
    cudaGetSymbolAddress((void**)&p_xt2, g_xt2);
    cudaGetSymbolAddress((void**)&p_h16, g_h16);
    cudaGetSymbolAddress((void**)&p_q16, g_q16);
    cudaGetSymbolAddress((void**)&p_a16, g_a16);
    cudaGetSymbolAddress((void**)&p_m16, g_m16);
    cudaGetSymbolAddress((void**)&p_w,   g_wall);

    k_f2hall<<<786432/256, 256>>>(qkv_w, proj_w, fc1_w, fc2_w);
    k_conv_lif<<<512, 256>>>(x, conv_w, conv_b, lif_w);
    k_ln_lif<<<512, 256>>>(p_xt, p_h16, ln1_g, ln1_b, lif_w, 1);
    tc_gemm<1><<<dim3(12,128), 256, GEMM_SMEM>>>(p_h16, p_w + WOFF_QKV, nullptr, nullptr,
                                                 nullptr, p_q16, lif_w, 3*C_, C_);
    k_attn_kv_mma<<<512, 128, ATTKV_SMEM>>>();
    k_attn_av_mma<<<512, 128>>>(lif_w);
    tc_gemm<0><<<dim3(4,128), 256, GEMM_SMEM>>>(p_a16, p_w + WOFF_PROJ, proj_b, p_xt,
                                                p_xt2, nullptr, lif_w, C_, C_);
    k_ln_lif<<<512, 256>>>(p_xt2, p_h16, ln2_g, ln2_b, lif_w, 6);
    tc_gemm<2><<<dim3(16,128), 256, GEMM_SMEM>>>(p_h16, p_w + WOFF_FC1, fc1_b, nullptr,
                                                 nullptr, p_m16, lif_w, HID_, C_);
    tc_gemm<3><<<dim3(4,128), 256, GEMM_SMEM>>>(p_m16, p_w + WOFF_FC2, fc2_b, p_xt2,
                                                out, nullptr, lif_w, C_, HID_);
}

// round 11
// speedup vs baseline: 1.5585x; 1.0011x over previous
#include <cuda_runtime.h>
#include <cuda_fp16.h>
#include <math.h>
#include <stdint.h>

// ---------------- problem constants ----------------
#define T_  4
#define B_  16
#define C_  512
#define H_  16
#define W_  16
#define N_  256
#define NH_ 8
#define D_  64
#define M_  (T_*B_*N_)     // 16384
#define HID_ 2048
#define ROWS_PER_T (B_*N_) // 4096

// ---------------- scratch ----------------
__device__ float  g_xt [M_*C_];
__device__ float  g_xt2[M_*C_];
__device__ __half g_h16[M_*C_];
__device__ __half g_q16[M_*3*C_];
__device__ __half g_a16[M_*C_];
__device__ __half g_m16[M_*HID_];
__device__ __half g_kvT[T_*B_*NH_*D_*D_];
__device__ __half g_wall[3*C_*C_ + C_*C_ + 2*HID_*C_];

#define WOFF_QKV  0
#define WOFF_PROJ (3*C_*C_)
#define WOFF_FC1  (WOFF_PROJ + C_*C_)
#define WOFF_FC2  (WOFF_FC1 + HID_*C_)

__device__ __forceinline__ float sigm(float w){ return 1.0f/(1.0f+expf(-w)); }
__device__ __forceinline__ uint32_t s2u(const void* p){
    uint32_t a;
    asm("{ .reg .u64 t; cvta.to.shared.u64 t, %1; cvt.u32.u64 %0, t; }" : "=r"(a) : "l"(p));
    return a;
}
__device__ __forceinline__ void cp16(uint32_t s, const void* g){
    asm volatile("cp.async.cg.shared.global [%0], [%1], 16;" :: "r"(s), "l"(g));
}
__device__ __forceinline__ void ldsm4(uint32_t* r, uint32_t addr){
    asm volatile("ldmatrix.sync.aligned.m8n8.x4.shared.b16 {%0,%1,%2,%3}, [%4];"
                 : "=r"(r[0]), "=r"(r[1]), "=r"(r[2]), "=r"(r[3]) : "r"(addr));
}
__device__ __forceinline__ void ldsm4t(uint32_t* r, uint32_t addr){
    asm volatile("ldmatrix.sync.aligned.m8n8.x4.trans.shared.b16 {%0,%1,%2,%3}, [%4];"
                 : "=r"(r[0]), "=r"(r[1]), "=r"(r[2]), "=r"(r[3]) : "r"(addr));
}
__device__ __forceinline__ void mma16816(float* c, const uint32_t* a, uint32_t b0, uint32_t b1){
    asm volatile(
        "mma.sync.aligned.m16n8k16.row.col.f32.f16.f16.f32 "
        "{%0,%1,%2,%3}, {%4,%5,%6,%7}, {%8,%9}, {%0,%1,%2,%3};"
        : "+f"(c[0]), "+f"(c[1]), "+f"(c[2]), "+f"(c[3])
        : "r"(a[0]), "r"(a[1]), "r"(a[2]), "r"(a[3]), "r"(b0), "r"(b1));
}

// ---------------- HMMA GEMM, BK=64, 3-stage ring, staggered ldsm ------------
// logical row r = bn_token*4 + t  <->  phys row = (r&3)*4096 + (r>>2)
// MODE 0: fp32 out + bias + residual (proj)
// MODE 1: fused LIF per-512-col decay lifw[2..4] -> fp16 spikes (qkv)
// MODE 2: fused LIF decay lifw[7] + bias -> fp16 spikes (fc1)
// MODE 3: bias + residual, write fp32 transposed [T,B,C,N] direct (fc2)
#define LDT 72
#define S_  3
#define BKC 64
#define STAGE_BYTES (128*LDT*2)       // 18432
#define GEMM_SMEM (S_*2*STAGE_BYTES)  // 110592
#define STG  132
#define STG3 133

template<int MODE>
__global__ void __launch_bounds__(256, 2) tc_gemm(
        const __half* __restrict__ A, const __half* __restrict__ Wt,
        const float* __restrict__ bias, const float* __restrict__ res,
        float* __restrict__ outf, __half* __restrict__ outh,
        const float* __restrict__ lifw, int Ndim, int K){
    extern __shared__ char smraw[];
    float* stage = (float*)smraw;
    uint32_t sAu = s2u(smraw);
    uint32_t sBu = sAu + S_*STAGE_BYTES;

    int tid = threadIdx.x;
    int warp = tid >> 5, lane = tid & 31;
    int wm = (warp & 1) * 64;
    int wn = (warp >> 1) * 32;
    int bm = blockIdx.y * 128, bn = blockIdx.x * 128;
    float acc[4][4][4] = {};

    int row0 = tid >> 3, ch = tid & 7;
    int pr0 = (row0 & 3)*ROWS_PER_T + (bm >> 2) + (row0 >> 2);
    const __half* ga0 = A  + (size_t)pr0*K + ch*8;
    const __half* gb0 = Wt + (size_t)(bn+row0)*K + ch*8;
    uint32_t so0 = (uint32_t)((row0*LDT + ch*8)*2);

    const int NC = K / BKC;
    #pragma unroll
    for (int p = 0; p < S_-1; p++){
        #pragma unroll
        for (int it = 0; it < 4; it++){
            cp16(sAu + p*STAGE_BYTES + so0 + it*(32*LDT*2), ga0 + p*BKC + (size_t)it*8*K);
            cp16(sBu + p*STAGE_BYTES + so0 + it*(32*LDT*2), gb0 + p*BKC + (size_t)it*32*K);
        }
        asm volatile("cp.async.commit_group;");
    }

    int l8 = lane >> 3;
    int arow = (lane & 7) + (l8 & 1) * 8, acol = (l8 >> 1) * 8;
    int brow = (lane & 7) + (l8 >> 1) * 8, bcol = (l8 & 1) * 8;
    uint32_t abase[4], bbase[2];
    #pragma unroll
    for (int mi = 0; mi < 4; mi++)
        abase[mi] = sAu + ((wm + mi*16 + arow)*LDT + acol)*2;
    #pragma unroll
    for (int np = 0; np < 2; np++)
        bbase[np] = sBu + ((wn + np*16 + brow)*LDT + bcol)*2;

    for (int c = 0; c < NC; c++){
        uint32_t stoff = (uint32_t)(c % S_) * STAGE_BYTES;
        asm volatile("cp.async.wait_group 1;" ::: "memory");
        __syncthreads();
        if (c + 2 < NC){
            uint32_t poff = (uint32_t)((c + 2) % S_) * STAGE_BYTES;
            int koff = (c + 2)*BKC;
            #pragma unroll
            for (int it = 0; it < 4; it++){
                cp16(sAu + poff + so0 + it*(32*LDT*2), ga0 + koff + (size_t)it*8*K);
                cp16(sBu + poff + so0 + it*(32*LDT*2), gb0 + koff + (size_t)it*32*K);
            }
        }
        asm volatile("cp.async.commit_group;");
        #pragma unroll
        for (int ks = 0; ks < 4; ks++){
            uint32_t af[4][4], bf[2][4];
            ldsm4(af[0], abase[0] + stoff + ks*32);
            ldsm4(bf[0], bbase[0] + stoff + ks*32);
            ldsm4(bf[1], bbase[1] + stoff + ks*32);
            #pragma unroll
            for (int mi = 0; mi < 4; mi++){
                if (mi < 3) ldsm4(af[mi+1], abase[mi+1] + stoff + ks*32);
                #pragma unroll
                for (int ni = 0; ni < 4; ni++)
                    mma16816(acc[mi][ni], af[mi],
                             bf[ni>>1][2*(ni&1)], bf[ni>>1][2*(ni&1)+1]);
            }
        }
    }

    int g = lane >> 2, i2 = (lane & 3) * 2;
    if (MODE == 0){
        #pragma unroll
        for (int mi = 0; mi < 4; mi++){
            int rl0 = bm + wm + mi*16 + g;
            int rl1 = rl0 + 8;
            int rp0 = (rl0 & 3)*ROWS_PER_T + (rl0 >> 2);
            int rp1 = (rl1 & 3)*ROWS_PER_T + (rl1 >> 2);
            #pragma unroll
            for (int ni = 0; ni < 4; ni++){
                int col = bn + wn + ni*8 + i2;
                float b0 = bias ? bias[col]   : 0.f;
                float b1 = bias ? bias[col+1] : 0.f;
                float v00 = acc[mi][ni][0] + b0, v01 = acc[mi][ni][1] + b1;
                float v10 = acc[mi][ni][2] + b0, v11 = acc[mi][ni][3] + b1;
                size_t o0 = (size_t)rp0*Ndim + col;
                size_t o1 = (size_t)rp1*Ndim + col;
                if (res){
                    v00 += res[o0]; v01 += res[o0+1];
                    v10 += res[o1]; v11 += res[o1+1];
                }
                *(float2*)&outf[o0] = make_float2(v00, v01);
                *(float2*)&outf[o1] = make_float2(v10, v11);
            }
        }
    } else if (MODE == 1 || MODE == 2){
        __syncthreads();
        #pragma unroll
        for (int mi = 0; mi < 4; mi++){
            int r0 = wm + mi*16 + g, r1 = r0 + 8;
            #pragma unroll
            for (int ni = 0; ni < 4; ni++){
                int cl = wn + ni*8 + i2;
                *(float2*)&stage[r0*STG + cl] = make_float2(acc[mi][ni][0], acc[mi][ni][1]);
                *(float2*)&stage[r1*STG + cl] = make_float2(acc[mi][ni][2], acc[mi][ni][3]);
            }
        }
        __syncthreads();
        float d0, d1 = 0.f, d2 = 0.f;
        if (MODE == 1){ d0 = sigm(lifw[2]); d1 = sigm(lifw[3]); d2 = sigm(lifw[4]); }
        else          { d0 = sigm(lifw[7]); }
        #pragma unroll
        for (int it = 0; it < 2; it++){
            int t2 = tid + it*256;
            int bnl = t2 >> 4, cg = (t2 & 15) * 8;
            int gc = bn + cg;
            float dec = (MODE == 1) ? (gc < 512 ? d0 : (gc < 1024 ? d1 : d2)) : d0;
            float bi[8];
            if (bias){
                float4 q0 = *(const float4*)&bias[gc];
                float4 q1 = *(const float4*)&bias[gc+4];
                bi[0]=q0.x; bi[1]=q0.y; bi[2]=q0.z; bi[3]=q0.w;
                bi[4]=q1.x; bi[5]=q1.y; bi[6]=q1.z; bi[7]=q1.w;
            } else {
                #pragma unroll
                for (int j = 0; j < 8; j++) bi[j] = 0.f;
            }
            float v[8];
            #pragma unroll
            for (int j = 0; j < 8; j++) v[j] = 0.f;
            #pragma unroll
            for (int t = 0; t < 4; t++){
                int r = bnl*4 + t;
                float4 x0 = *(float4*)&stage[r*STG + cg];
                float4 x1 = *(float4*)&stage[r*STG + cg + 4];
                float xv[8] = {x0.x,x0.y,x0.z,x0.w,x1.x,x1.y,x1.z,x1.w};
                union { __half h[8]; uint4 u; } pk;
                #pragma unroll
                for (int j = 0; j < 8; j++){
                    float xx = xv[j] + bi[j];
                    v[j] += (xx - v[j])*dec;
                    float sp = (v[j] >= 1.0f) ? 1.f : 0.f;
                    pk.h[j] = __float2half_rn(sp);
                    if (sp > 0.f) v[j] = 0.f;
                }
                int pr = t*ROWS_PER_T + (bm >> 2) + bnl;
                *(uint4*)&outh[(size_t)pr*Ndim + gc] = pk.u;
            }
        }
    } else {
        __syncthreads();
        #pragma unroll
        for (int mi = 0; mi < 4; mi++){
            int r0 = wm + mi*16 + g, r1 = r0 + 8;
            int rl0 = bm + r0, rl1 = bm + r1;
            int rp0 = (rl0 & 3)*ROWS_PER_T + (rl0 >> 2);
            int rp1 = (rl1 & 3)*ROWS_PER_T + (rl1 >> 2);
            #pragma unroll
            for (int ni = 0; ni < 4; ni++){
                int cl = wn + ni*8 + i2;
                int col = bn + cl;
                float b0 = bias[col], b1 = bias[col+1];
                size_t o0 = (size_t)rp0*Ndim + col;
                size_t o1 = (size_t)rp1*Ndim + col;
                stage[r0*STG3 + cl]   = acc[mi][ni][0] + b0 + res[o0];
                stage[r0*STG3 + cl+1] = acc[mi][ni][1] + b1 + res[o0+1];
                stage[r1*STG3 + cl]   = acc[mi][ni][2] + b0 + res[o1];
                stage[r1*STG3 + cl+1] = acc[mi][ni][3] + b1 + res[o1+1];
            }
        }
        __syncthreads();
        int btok = bm >> 2;
        int b = btok >> 8, n0 = btok & 255;
        #pragma unroll
        for (int it = 0; it < 16; it++){
            int f4 = tid + it*256;
            int rown = f4 >> 3;
            int n4 = f4 & 7;
            int cc = rown >> 2, t = rown & 3;
            float4 val;
            val.x = stage[((n4*4+0)*4 + t)*STG3 + cc];
            val.y = stage[((n4*4+1)*4 + t)*STG3 + cc];
            val.z = stage[((n4*4+2)*4 + t)*STG3 + cc];
            val.w = stage[((n4*4+3)*4 + t)*STG3 + cc];
            size_t dst = ((size_t)(t*B_ + b)*C_ + bn + cc)*N_ + n0 + n4*4;
            *(float4*)&outf[dst] = val;
        }
    }
}

// ---------------- all-weights f32 -> f16 convert ----------------------------
__global__ void k_f2hall(const float* __restrict__ w0, const float* __restrict__ w1,
                         const float* __restrict__ w2, const float* __restrict__ w3){
    int i = blockIdx.x*blockDim.x + threadIdx.x;
    const float* src;
    if (i < 196608){ src = w0; }
    else if (i < 262144){ src = w1 - 786432; }
    else if (i < 524288){ src = w2 - 1048576; }
    else { src = w3 - 2097152; }
    float4 f = *(const float4*)&src[i*4];
    union { __half h[4]; uint2 u; } pk;
    pk.h[0]=__float2half_rn(f.x); pk.h[1]=__float2half_rn(f.y);
    pk.h[2]=__float2half_rn(f.z); pk.h[3]=__float2half_rn(f.w);
    *(uint2*)&g_wall[(size_t)i*4] = pk.u;
}

// ---------------- fused input-LIF + depthwise conv + residual ---------------
__global__ void __launch_bounds__(256) k_conv_lif(
        const float* __restrict__ x, const float* __restrict__ cw,
        const float* __restrict__ cb, const float* __restrict__ lifw){
    __shared__ float  xs[16*257];
    __shared__ __half sp[16*264];
    __shared__ float  ws[16*9];
    __shared__ float  wb[16];
    int tid = threadIdx.x;
    int b  = blockIdx.x >> 5;
    int c0 = (blockIdx.x & 31) * 16;
    if (tid < 16*9) ws[tid] = cw[c0*9 + tid];
    if (tid < 16)   wb[tid] = cb[c0 + tid];
    float dec = sigm(lifw[0]);
    float v[4][4];
    #pragma unroll
    for (int i = 0; i < 4; i++)
        #pragma unroll
        for (int j = 0; j < 4; j++) v[i][j] = 0.f;
    __syncthreads();
    for (int t = 0; t < T_; t++){
        int tb = t*B_ + b;
        #pragma unroll
        for (int i = 0; i < 4; i++){
            int f4 = tid + i*256;              // 0..1023
            int cl = f4 >> 6, p4 = (f4 & 63)*4;
            float4 xv = *(const float4*)&x[((size_t)tb*C_ + c0 + cl)*256 + p4];
            float xa[4] = {xv.x, xv.y, xv.z, xv.w};
            union { __half h[4]; uint2 u; } pk;
            #pragma unroll
            for (int j = 0; j < 4; j++){
                xs[cl*257 + p4 + j] = xa[j];
                float vv = v[i][j] + (xa[j] - v[i][j])*dec;
                float s = (vv >= 1.0f) ? 1.f : 0.f;
                v[i][j] = (s > 0.f) ? 0.f : vv;
                pk.h[j] = __float2half_rn(s);
            }
            *(uint2*)&sp[cl*264 + p4] = pk.u;
        }
        __syncthreads();
        #pragma unroll
        for (int i = 0; i < 16; i++){
            int lin = tid + i*256;
            int cl = lin & 15, n = lin >> 4;
            int hh = n >> 4, wp = n & 15;
            float acc = wb[cl];
            const float* wk = &ws[cl*9];
            #pragma unroll
            for (int kh = 0; kh < 3; kh++){
                int h2 = hh + kh - 1;
                if (h2 < 0 || h2 > 15) continue;
                #pragma unroll
                for (int kw = 0; kw < 3; kw++){
                    int w2 = wp + kw - 1;
                    if (w2 < 0 || w2 > 15) continue;
                    acc += __half2float(sp[cl*264 + h2*16 + w2]) * wk[kh*3 + kw];
                }
            }
            float val = xs[cl*257 + n] + acc;
            g_xt[((size_t)tb*256 + n)*C_ + c0 + cl] = val;
        }
        __syncthreads();
    }
}

// ---------------- LayerNorm + LIF, warp-per-token ---------------------------
__global__ void __launch_bounds__(256) k_ln_lif(
        const float* __restrict__ in, __half* __restrict__ out,
        const float* __restrict__ gam, const float* __restrict__ bet,
        const float* __restrict__ lifw, int lidx){
    int tid = threadIdx.x, wid = tid >> 5, lane = tid & 31;
    int bn = blockIdx.x*8 + wid;
    int cb = lane*16;
    float dec = sigm(lifw[lidx]);
    float gg[16], bb[16];
    #pragma unroll
    for (int i = 0; i < 4; i++){
        float4 t1 = *(const float4*)&gam[cb + i*4];
        float4 t2 = *(const float4*)&bet[cb + i*4];
        gg[i*4]=t1.x; gg[i*4+1]=t1.y; gg[i*4+2]=t1.z; gg[i*4+3]=t1.w;
        bb[i*4]=t2.x; bb[i*4+1]=t2.y; bb[i*4+2]=t2.z; bb[i*4+3]=t2.w;
    }
    float v[16];
    #pragma unroll
    for (int i = 0; i < 16; i++) v[i] = 0.f;
    for (int t = 0; t < T_; t++){
        int row = t*ROWS_PER_T + bn;
        const float* xr = in + (size_t)row*C_ + cb;
        float xv[16];
        #pragma unroll
        for (int i = 0; i < 4; i++){
            float4 x4 = *(const float4*)&xr[i*4];
            xv[i*4]=x4.x; xv[i*4+1]=x4.y; xv[i*4+2]=x4.z; xv[i*4+3]=x4.w;
        }
        float s = 0.f, ss = 0.f;
        #pragma unroll
        for (int i = 0; i < 16; i++){ s += xv[i]; ss += xv[i]*xv[i]; }
        #pragma unroll
        for (int o = 16; o > 0; o >>= 1){
            s  += __shfl_xor_sync(0xffffffffu, s,  o);
            ss += __shfl_xor_sync(0xffffffffu, ss, o);
        }
        float mean = s*(1.0f/C_);
        float var  = ss*(1.0f/C_) - mean*mean;
        float rstd = rsqrtf(var + 1e-5f);
        union { __half h[16]; uint4 u[2]; } pk;
        #pragma unroll
        for (int k = 0; k < 16; k++){
            float ln = (xv[k]-mean)*rstd*gg[k] + bb[k];
            v[k] += (ln - v[k])*dec;
            float spv = (v[k] >= 1.0f) ? 1.f : 0.f;
            pk.h[k] = __float2half_rn(spv);
            if (spv > 0.f) v[k] = 0.f;
        }
        uint4* dst = (uint4*)(out + (size_t)row*C_ + cb);
        dst[0] = pk.u[0]; dst[1] = pk.u[1];
    }
}

// ---------------- attention phase 1 (HMMA): kvT[e,d] = sum_n v[n,e] k[n,d] --
#define ATT_LD 72
#define ATTKV_SMEM (2*256*ATT_LD*2)   // 73728

__global__ void __launch_bounds__(128) k_attn_kv_mma(){
    extern __shared__ __half satt[];
    __half* sk = satt;
    __half* sv = satt + 256*ATT_LD;
    int blk = blockIdx.x;
    int h  = blk & 7;
    int tb = blk >> 3;
    int tid = threadIdx.x, warp = tid >> 5, lane = tid & 31;

    const __half* base = g_q16 + (size_t)tb*256*(3*C_) + h*D_;
    #pragma unroll
    for (int it = 0; it < 16; it++){
        int task = tid + it*128;
        int row = task >> 3, ch = task & 7;
        cp16(s2u(&sk[row*ATT_LD + ch*8]), base + (size_t)row*(3*C_) + C_   + ch*8);
        cp16(s2u(&sv[row*ATT_LD + ch*8]), base + (size_t)row*(3*C_) + 2*C_ + ch*8);
    }
    asm volatile("cp.async.commit_group;");
    asm volatile("cp.async.wait_group 0;" ::: "memory");
    __syncthreads();

    int l8 = lane >> 3;
    int a_r = (lane & 7) + (l8 >> 1)*8;
    int a_c = warp*16 + (l8 & 1)*8;
    int b_r = (lane & 7) + (l8 & 1)*8;
    int b_c = (l8 >> 1)*8;

    float acc[8][4] = {};
    #pragma unroll 4
    for (int s = 0; s < 16; s++){
        uint32_t af[4];
        ldsm4t(af, s2u(&sv[(s*16 + a_r)*ATT_LD + a_c]));
        #pragma unroll
        for (int j = 0; j < 4; j++){
            uint32_t bf[4];
            ldsm4t(bf, s2u(&sk[(s*16 + b_r)*ATT_LD + j*16 + b_c]));
            mma16816(acc[2*j],   af, bf[0], bf[1]);
            mma16816(acc[2*j+1], af, bf[2], bf[3]);
        }
    }

    __half* dst = g_kvT + (size_t)blk*(D_*D_);
    int g = lane >> 2, i2 = (lane & 3)*2;
    int r0 = warp*16 + g, r1 = r0 + 8;
    #pragma unroll
    for (int ni = 0; ni < 8; ni++){
        int col = ni*8 + i2;
        *(__half2*)&dst[r0*D_ + col] = __floats2half2_rn(acc[ni][0], acc[ni][1]);
        *(__half2*)&dst[r1*D_ + col] = __floats2half2_rn(acc[ni][2], acc[ni][3]);
    }
}

// ---------------- attention phase 2 (HMMA): a = q@kvT*scale + LIF -----------
// double-buffered over T: prefetch t+1 while computing t.
__global__ void __launch_bounds__(128) k_attn_av_mma(const float* __restrict__ lifw){
    __shared__ __half sq [2][64*ATT_LD];
    __shared__ __half skv[2][64*ATT_LD];
    int blk = blockIdx.x;
    int nt = blk & 3;
    int h  = (blk >> 2) & 7;
    int b  = blk >> 5;
    int tid = threadIdx.x, warp = tid >> 5, lane = tid & 31;
    float dec = sigm(lifw[5]);

    int l8 = lane >> 3;
    int arow = (lane & 7) + (l8 & 1)*8, acol = (l8 >> 1)*8;
    int brow = (lane & 7) + (l8 >> 1)*8, bcol = (l8 & 1)*8;
    int g = lane >> 2, i2 = (lane & 3)*2;

    float vst[8][4];
    #pragma unroll
    for (int ni = 0; ni < 8; ni++)
        #pragma unroll
        for (int c = 0; c < 4; c++) vst[ni][c] = 0.f;

    // prologue: load t=0 into buffer 0
    {
        const __half* qb = g_q16 + ((size_t)(0*B_ + b)*256 + nt*64)*(3*C_) + h*D_;
        const __half* kb = g_kvT + (size_t)((0*B_ + b)*NH_ + h)*(D_*D_);
        #pragma unroll
        for (int it = 0; it < 4; it++){
            int task = tid + it*128;
            int row = task >> 3, ch = task & 7;
            cp16(s2u(&sq [0][row*ATT_LD + ch*8]), qb + (size_t)row*(3*C_) + ch*8);
            cp16(s2u(&skv[0][row*ATT_LD + ch*8]), kb + row*D_ + ch*8);
        }
        asm volatile("cp.async.commit_group;");
    }

    for (int t = 0; t < T_; t++){
        int buf = t & 1;
        if (t + 1 < T_){
            int tb1 = (t+1)*B_ + b;
            const __half* qb = g_q16 + ((size_t)tb1*256 + nt*64)*(3*C_) + h*D_;
            const __half* kb = g_kvT + (size_t)(tb1*NH_ + h)*(D_*D_);
            #pragma unroll
            for (int it = 0; it < 4; it++){
                int task = tid + it*128;
                int row = task >> 3, ch = task & 7;
                cp16(s2u(&sq [buf^1][row*ATT_LD + ch*8]), qb + (size_t)row*(3*C_) + ch*8);
                cp16(s2u(&skv[buf^1][row*ATT_LD + ch*8]), kb + row*D_ + ch*8);
            }
            asm volatile("cp.async.commit_group;");
            asm volatile("cp.async.wait_group 1;" ::: "memory");
        } else {
            asm volatile("cp.async.wait_group 0;" ::: "memory");
        }
        __syncthreads();

        int tb = t*B_ + b;
        float acc[8][4] = {};
        #pragma unroll
        for (int s = 0; s < 4; s++){
            uint32_t af[4];
            ldsm4(af, s2u(&sq[buf][(warp*16 + arow)*ATT_LD + s*16 + acol]));
            #pragma unroll
            for (int j = 0; j < 4; j++){
                uint32_t bf[4];
                ldsm4(bf, s2u(&skv[buf][(j*16 + brow)*ATT_LD + s*16 + bcol]));
                mma16816(acc[2*j],   af, bf[0], bf[1]);
                mma16816(acc[2*j+1], af, bf[2], bf[3]);
            }
        }

        int row0 = tb*256 + nt*64 + warp*16 + g;
        #pragma unroll
        for (int ni = 0; ni < 8; ni++){
            int col = h*D_ + ni*8 + i2;
            __half sp[4];
            #pragma unroll
            for (int c = 0; c < 4; c++){
                float a = acc[ni][c]*0.125f;
                float* v = &vst[ni][c];
                *v += (a - *v)*dec;
                float s = (*v >= 1.0f) ? 1.f : 0.f;
                sp[c] = __float2half_rn(s);
                if (s > 0.f) *v = 0.f;
            }
            *(__half2*)&g_a16[(size_t)row0*C_ + col]     = *(__half2*)&sp[0];
            *(__half2*)&g_a16[(size_t)(row0+8)*C_ + col] = *(__half2*)&sp[2];
        }
        __syncthreads();
    }
}

// ---------------- host orchestration ----------------------------------------
extern "C" void kernel_launch(void* const* d_in, const int* in_sizes, int n_in,
                              void* d_out, int out_size){
    const float* x      = (const float*)d_in[0];
    const float* conv_w = (const float*)d_in[1];
    const float* conv_b = (const float*)d_in[2];
    const float* ln1_g  = (const float*)d_in[3];
    const float* ln1_b  = (const float*)d_in[4];
    const float* qkv_w  = (const float*)d_in[5];
    const float* proj_w = (const float*)d_in[6];
    const float* proj_b = (const float*)d_in[7];
    const float* ln2_g  = (const float*)d_in[8];
    const float* ln2_b  = (const float*)d_in[9];
    const float* fc1_w  = (const float*)d_in[10];
    const float* fc1_b  = (const float*)d_in[11];
    const float* fc2_w  = (const float*)d_in[12];
    const float* fc2_b  = (const float*)d_in[13];
    const float* lif_w  = (const float*)d_in[14];
    float* out = (float*)d_out;

    cudaFuncSetAttribute(tc_gemm<0>, cudaFuncAttributeMaxDynamicSharedMemorySize, GEMM_SMEM);
    cudaFuncSetAttribute(tc_gemm<1>, cudaFuncAttributeMaxDynamicSharedMemorySize, GEMM_SMEM);
    cudaFuncSetAttribute(tc_gemm<2>, cudaFuncAttributeMaxDynamicSharedMemorySize, GEMM_SMEM);
    cudaFuncSetAttribute(tc_gemm<3>, cudaFuncAttributeMaxDynamicSharedMemorySize, GEMM_SMEM);
    cudaFuncSetAttribute(k_attn_kv_mma, cudaFuncAttributeMaxDynamicSharedMemorySize, ATTKV_SMEM);

    float *p_xt, *p_xt2;
    __half *p_h16, *p_q16, *p_a16, *p_m16, *p_w;
    cudaGetSymbolAddress((void**)&p_xt,  g_xt);
    cudaGetSymbolAddress((void**)&p_xt2, g_xt2);
    cudaGetSymbolAddress((void**)&p_h16, g_h16);
    cudaGetSymbolAddress((void**)&p_q16, g_q16);
    cudaGetSymbolAddress((void**)&p_a16, g_a16);
    cudaGetSymbolAddress((void**)&p_m16, g_m16);
    cudaGetSymbolAddress((void**)&p_w,   g_wall);

    k_f2hall<<<786432/256, 256>>>(qkv_w, proj_w, fc1_w, fc2_w);
    k_conv_lif<<<512, 256>>>(x, conv_w, conv_b, lif_w);
    k_ln_lif<<<512, 256>>>(p_xt, p_h16, ln1_g, ln1_b, lif_w, 1);
    tc_gemm<1><<<dim3(12,128), 256, GEMM_SMEM>>>(p_h16, p_w + WOFF_QKV, nullptr, nullptr,
                                                 nullptr, p_q16, lif_w, 3*C_, C_);
    k_attn_kv_mma<<<512, 128, ATTKV_SMEM>>>();
    k_attn_av_mma<<<512, 128>>>(lif_w);
    tc_gemm<0><<<dim3(4,128), 256, GEMM_SMEM>>>(p_a16, p_w + WOFF_PROJ, proj_b, p_xt,
                                                p_xt2, nullptr, lif_w, C_, C_);
    k_ln_lif<<<512, 256>>>(p_xt2, p_h16, ln2_g, ln2_b, lif_w, 6);
    tc_gemm<2><<<dim3(16,128), 256, GEMM_SMEM>>>(p_h16, p_w + WOFF_FC1, fc1_b, nullptr,
                                                 nullptr, p_m16, lif_w, HID_, C_);
    tc_gemm<3><<<dim3(4,128), 256, GEMM_SMEM>>>(p_m16, p_w + WOFF_FC2, fc2_b, p_xt2,
                                                out, nullptr, lif_w, C_, HID_);
}

// round 12
// speedup vs baseline: 1.5874x; 1.0186x over previous
#include <cuda_runtime.h>
#include <cuda_fp16.h>
#include <math.h>
#include <stdint.h>

// ---------------- problem constants ----------------
#define T_  4
#define B_  16
#define C_  512
#define H_  16
#define W_  16
#define N_  256
#define NH_ 8
#define D_  64
#define M_  (T_*B_*N_)     // 16384
#define HID_ 2048
#define ROWS_PER_T (B_*N_) // 4096

// ---------------- scratch ----------------
__device__ __half g_xt [M_*C_];          // residual stream 1 (fp16)
__device__ __half g_xt2[M_*C_];          // residual stream 2 (fp16)
__device__ __half g_h16[M_*C_];
__device__ __half g_q16[M_*3*C_];
__device__ __half g_a16[M_*C_];
__device__ __half g_m16[M_*HID_];
__device__ __half g_kvT[T_*B_*NH_*D_*D_];
__device__ __half g_wall[3*C_*C_ + C_*C_ + 2*HID_*C_];

#define WOFF_QKV  0
#define WOFF_PROJ (3*C_*C_)
#define WOFF_FC1  (WOFF_PROJ + C_*C_)
#define WOFF_FC2  (WOFF_FC1 + HID_*C_)

__device__ __forceinline__ float sigm(float w){ return 1.0f/(1.0f+expf(-w)); }
__device__ __forceinline__ uint32_t s2u(const void* p){
    uint32_t a;
    asm("{ .reg .u64 t; cvta.to.shared.u64 t, %1; cvt.u32.u64 %0, t; }" : "=r"(a) : "l"(p));
    return a;
}
__device__ __forceinline__ void cp16(uint32_t s, const void* g){
    asm volatile("cp.async.cg.shared.global [%0], [%1], 16;" :: "r"(s), "l"(g));
}
__device__ __forceinline__ void ldsm4(uint32_t* r, uint32_t addr){
    asm volatile("ldmatrix.sync.aligned.m8n8.x4.shared.b16 {%0,%1,%2,%3}, [%4];"
                 : "=r"(r[0]), "=r"(r[1]), "=r"(r[2]), "=r"(r[3]) : "r"(addr));
}
__device__ __forceinline__ void ldsm4t(uint32_t* r, uint32_t addr){
    asm volatile("ldmatrix.sync.aligned.m8n8.x4.trans.shared.b16 {%0,%1,%2,%3}, [%4];"
                 : "=r"(r[0]), "=r"(r[1]), "=r"(r[2]), "=r"(r[3]) : "r"(addr));
}
__device__ __forceinline__ void mma16816(float* c, const uint32_t* a, uint32_t b0, uint32_t b1){
    asm volatile(
        "mma.sync.aligned.m16n8k16.row.col.f32.f16.f16.f32 "
        "{%0,%1,%2,%3}, {%4,%5,%6,%7}, {%8,%9}, {%0,%1,%2,%3};"
        : "+f"(c[0]), "+f"(c[1]), "+f"(c[2]), "+f"(c[3])
        : "r"(a[0]), "r"(a[1]), "r"(a[2]), "r"(a[3]), "r"(b0), "r"(b1));
}

// ---------------- HMMA GEMM, BK=64, 3-stage ring ----------------------------
// logical row r = bn_token*4 + t  <->  phys row = (r&3)*4096 + (r>>2)
// MODE 0: bias + fp16 residual -> fp16 out (proj)
// MODE 1: fused LIF per-512-col decay lifw[2..4] -> fp16 spikes (qkv)
// MODE 2: fused LIF decay lifw[7] + bias -> fp16 spikes (fc1)
// MODE 3: bias + fp16 residual, write fp32 transposed [T,B,C,N] direct (fc2)
#define LDT 72
#define S_  3
#define BKC 64
#define STAGE_BYTES (128*LDT*2)       // 18432
#define GEMM_SMEM (S_*2*STAGE_BYTES)  // 110592
#define STG  132
#define STG3 133

template<int MODE>
__global__ void __launch_bounds__(256, 2) tc_gemm(
        const __half* __restrict__ A, const __half* __restrict__ Wt,
        const float* __restrict__ bias, const __half* __restrict__ res,
        float* __restrict__ outf, __half* __restrict__ outh,
        const float* __restrict__ lifw, int Ndim, int K){
    extern __shared__ char smraw[];
    float* stage = (float*)smraw;
    uint32_t sAu = s2u(smraw);
    uint32_t sBu = sAu + S_*STAGE_BYTES;

    int tid = threadIdx.x;
    int warp = tid >> 5, lane = tid & 31;
    int wm = (warp & 1) * 64;
    int wn = (warp >> 1) * 32;
    int bm = blockIdx.y * 128, bn = blockIdx.x * 128;
    float acc[4][4][4] = {};

    int row0 = tid >> 3, ch = tid & 7;
    int pr0 = (row0 & 3)*ROWS_PER_T + (bm >> 2) + (row0 >> 2);
    const __half* ga0 = A  + (size_t)pr0*K + ch*8;
    const __half* gb0 = Wt + (size_t)(bn+row0)*K + ch*8;
    uint32_t so0 = (uint32_t)((row0*LDT + ch*8)*2);

    const int NC = K / BKC;
    #pragma unroll
    for (int p = 0; p < S_-1; p++){
        #pragma unroll
        for (int it = 0; it < 4; it++){
            cp16(sAu + p*STAGE_BYTES + so0 + it*(32*LDT*2), ga0 + p*BKC + (size_t)it*8*K);
            cp16(sBu + p*STAGE_BYTES + so0 + it*(32*LDT*2), gb0 + p*BKC + (size_t)it*32*K);
        }
        asm volatile("cp.async.commit_group;");
    }

    int l8 = lane >> 3;
    int arow = (lane & 7) + (l8 & 1) * 8, acol = (l8 >> 1) * 8;
    int brow = (lane & 7) + (l8 >> 1) * 8, bcol = (l8 & 1) * 8;
    uint32_t abase[4], bbase[2];
    #pragma unroll
    for (int mi = 0; mi < 4; mi++)
        abase[mi] = sAu + ((wm + mi*16 + arow)*LDT + acol)*2;
    #pragma unroll
    for (int np = 0; np < 2; np++)
        bbase[np] = sBu + ((wn + np*16 + brow)*LDT + bcol)*2;

    for (int c = 0; c < NC; c++){
        uint32_t stoff = (uint32_t)(c % S_) * STAGE_BYTES;
        asm volatile("cp.async.wait_group 1;" ::: "memory");
        __syncthreads();
        if (c + 2 < NC){
            uint32_t poff = (uint32_t)((c + 2) % S_) * STAGE_BYTES;
            int koff = (c + 2)*BKC;
            #pragma unroll
            for (int it = 0; it < 4; it++){
                cp16(sAu + poff + so0 + it*(32*LDT*2), ga0 + koff + (size_t)it*8*K);
                cp16(sBu + poff + so0 + it*(32*LDT*2), gb0 + koff + (size_t)it*32*K);
            }
        }
        asm volatile("cp.async.commit_group;");
        #pragma unroll
        for (int ks = 0; ks < 4; ks++){
            uint32_t af[4][4], bf[2][4];
            ldsm4(af[0], abase[0] + stoff + ks*32);
            ldsm4(bf[0], bbase[0] + stoff + ks*32);
            ldsm4(bf[1], bbase[1] + stoff + ks*32);
            #pragma unroll
            for (int mi = 0; mi < 4; mi++){
                if (mi < 3) ldsm4(af[mi+1], abase[mi+1] + stoff + ks*32);
                #pragma unroll
                for (int ni = 0; ni < 4; ni++)
                    mma16816(acc[mi][ni], af[mi],
                             bf[ni>>1][2*(ni&1)], bf[ni>>1][2*(ni&1)+1]);
            }
        }
    }

    int g = lane >> 2, i2 = (lane & 3) * 2;
    if (MODE == 0){
        #pragma unroll
        for (int mi = 0; mi < 4; mi++){
            int rl0 = bm + wm + mi*16 + g;
            int rl1 = rl0 + 8;
            int rp0 = (rl0 & 3)*ROWS_PER_T + (rl0 >> 2);
            int rp1 = (rl1 & 3)*ROWS_PER_T + (rl1 >> 2);
            #pragma unroll
            for (int ni = 0; ni < 4; ni++){
                int col = bn + wn + ni*8 + i2;
                float b0 = bias[col], b1 = bias[col+1];
                size_t o0 = (size_t)rp0*Ndim + col;
                size_t o1 = (size_t)rp1*Ndim + col;
                float2 r0 = __half22float2(*(const __half2*)&res[o0]);
                float2 r1 = __half22float2(*(const __half2*)&res[o1]);
                float v00 = acc[mi][ni][0] + b0 + r0.x;
                float v01 = acc[mi][ni][1] + b1 + r0.y;
                float v10 = acc[mi][ni][2] + b0 + r1.x;
                float v11 = acc[mi][ni][3] + b1 + r1.y;
                *(__half2*)&outh[o0] = __floats2half2_rn(v00, v01);
                *(__half2*)&outh[o1] = __floats2half2_rn(v10, v11);
            }
        }
    } else if (MODE == 1 || MODE == 2){
        __syncthreads();
        #pragma unroll
        for (int mi = 0; mi < 4; mi++){
            int r0 = wm + mi*16 + g, r1 = r0 + 8;
            #pragma unroll
            for (int ni = 0; ni < 4; ni++){
                int cl = wn + ni*8 + i2;
                *(float2*)&stage[r0*STG + cl] = make_float2(acc[mi][ni][0], acc[mi][ni][1]);
                *(float2*)&stage[r1*STG + cl] = make_float2(acc[mi][ni][2], acc[mi][ni][3]);
            }
        }
        __syncthreads();
        float d0, d1 = 0.f, d2 = 0.f;
        if (MODE == 1){ d0 = sigm(lifw[2]); d1 = sigm(lifw[3]); d2 = sigm(lifw[4]); }
        else          { d0 = sigm(lifw[7]); }
        #pragma unroll
        for (int it = 0; it < 2; it++){
            int t2 = tid + it*256;
            int bnl = t2 >> 4, cg = (t2 & 15) * 8;
            int gc = bn + cg;
            float dec = (MODE == 1) ? (gc < 512 ? d0 : (gc < 1024 ? d1 : d2)) : d0;
            float bi[8];
            if (bias){
                float4 q0 = *(const float4*)&bias[gc];
                float4 q1 = *(const float4*)&bias[gc+4];
                bi[0]=q0.x; bi[1]=q0.y; bi[2]=q0.z; bi[3]=q0.w;
                bi[4]=q1.x; bi[5]=q1.y; bi[6]=q1.z; bi[7]=q1.w;
            } else {
                #pragma unroll
                for (int j = 0; j < 8; j++) bi[j] = 0.f;
            }
            float v[8];
            #pragma unroll
            for (int j = 0; j < 8; j++) v[j] = 0.f;
            #pragma unroll
            for (int t = 0; t < 4; t++){
                int r = bnl*4 + t;
                float4 x0 = *(float4*)&stage[r*STG + cg];
                float4 x1 = *(float4*)&stage[r*STG + cg + 4];
                float xv[8] = {x0.x,x0.y,x0.z,x0.w,x1.x,x1.y,x1.z,x1.w};
                union { __half h[8]; uint4 u; } pk;
                #pragma unroll
                for (int j = 0; j < 8; j++){
                    float xx = xv[j] + bi[j];
                    v[j] += (xx - v[j])*dec;
                    float sp = (v[j] >= 1.0f) ? 1.f : 0.f;
                    pk.h[j] = __float2half_rn(sp);
                    if (sp > 0.f) v[j] = 0.f;
                }
                int pr = t*ROWS_PER_T + (bm >> 2) + bnl;
                *(uint4*)&outh[(size_t)pr*Ndim + gc] = pk.u;
            }
        }
    } else {
        __syncthreads();
        #pragma unroll
        for (int mi = 0; mi < 4; mi++){
            int r0 = wm + mi*16 + g, r1 = r0 + 8;
            int rl0 = bm + r0, rl1 = bm + r1;
            int rp0 = (rl0 & 3)*ROWS_PER_T + (rl0 >> 2);
            int rp1 = (rl1 & 3)*ROWS_PER_T + (rl1 >> 2);
            #pragma unroll
            for (int ni = 0; ni < 4; ni++){
                int cl = wn + ni*8 + i2;
                int col = bn + cl;
                float b0 = bias[col], b1 = bias[col+1];
                size_t o0 = (size_t)rp0*Ndim + col;
                size_t o1 = (size_t)rp1*Ndim + col;
                float2 rr0 = __half22float2(*(const __half2*)&res[o0]);
                float2 rr1 = __half22float2(*(const __half2*)&res[o1]);
                stage[r0*STG3 + cl]   = acc[mi][ni][0] + b0 + rr0.x;
                stage[r0*STG3 + cl+1] = acc[mi][ni][1] + b1 + rr0.y;
                stage[r1*STG3 + cl]   = acc[mi][ni][2] + b0 + rr1.x;
                stage[r1*STG3 + cl+1] = acc[mi][ni][3] + b1 + rr1.y;
            }
        }
        __syncthreads();
        int btok = bm >> 2;
        int b = btok >> 8, n0 = btok & 255;
        #pragma unroll
        for (int it = 0; it < 16; it++){
            int f4 = tid + it*256;
            int rown = f4 >> 3;
            int n4 = f4 & 7;
            int cc = rown >> 2, t = rown & 3;
            float4 val;
            val.x = stage[((n4*4+0)*4 + t)*STG3 + cc];
            val.y = stage[((n4*4+1)*4 + t)*STG3 + cc];
            val.z = stage[((n4*4+2)*4 + t)*STG3 + cc];
            val.w = stage[((n4*4+3)*4 + t)*STG3 + cc];
            size_t dst = ((size_t)(t*B_ + b)*C_ + bn + cc)*N_ + n0 + n4*4;
            *(float4*)&outf[dst] = val;
        }
    }
}

// ---------------- all-weights f32 -> f16 convert ----------------------------
__global__ void k_f2hall(const float* __restrict__ w0, const float* __restrict__ w1,
                         const float* __restrict__ w2, const float* __restrict__ w3){
    int i = blockIdx.x*blockDim.x + threadIdx.x;
    const float* src;
    if (i < 196608){ src = w0; }
    else if (i < 262144){ src = w1 - 786432; }
    else if (i < 524288){ src = w2 - 1048576; }
    else { src = w3 - 2097152; }
    float4 f = *(const float4*)&src[i*4];
    union { __half h[4]; uint2 u; } pk;
    pk.h[0]=__float2half_rn(f.x); pk.h[1]=__float2half_rn(f.y);
    pk.h[2]=__float2half_rn(f.z); pk.h[3]=__float2half_rn(f.w);
    *(uint2*)&g_wall[(size_t)i*4] = pk.u;
}

// ---------------- fused input-LIF + depthwise conv + residual (fp16 out) ----
__global__ void __launch_bounds__(256) k_conv_lif(
        const float* __restrict__ x, const float* __restrict__ cw,
        const float* __restrict__ cb, const float* __restrict__ lifw){
    __shared__ float  xs[16*257];
    __shared__ __half sp[16*264];
    __shared__ float  ws[16*9];
    __shared__ float  wb[16];
    int tid = threadIdx.x;
    int b  = blockIdx.x >> 5;
    int c0 = (blockIdx.x & 31) * 16;
    if (tid < 16*9) ws[tid] = cw[c0*9 + tid];
    if (tid < 16)   wb[tid] = cb[c0 + tid];
    float dec = sigm(lifw[0]);
    float v[4][4];
    #pragma unroll
    for (int i = 0; i < 4; i++)
        #pragma unroll
        for (int j = 0; j < 4; j++) v[i][j] = 0.f;
    __syncthreads();
    for (int t = 0; t < T_; t++){
        int tb = t*B_ + b;
        #pragma unroll
        for (int i = 0; i < 4; i++){
            int f4 = tid + i*256;
            int cl = f4 >> 6, p4 = (f4 & 63)*4;
            float4 xv = *(const float4*)&x[((size_t)tb*C_ + c0 + cl)*256 + p4];
            float xa[4] = {xv.x, xv.y, xv.z, xv.w};
            union { __half h[4]; uint2 u; } pk;
            #pragma unroll
            for (int j = 0; j < 4; j++){
                xs[cl*257 + p4 + j] = xa[j];
                float vv = v[i][j] + (xa[j] - v[i][j])*dec;
                float s = (vv >= 1.0f) ? 1.f : 0.f;
                v[i][j] = (s > 0.f) ? 0.f : vv;
                pk.h[j] = __float2half_rn(s);
            }
            *(uint2*)&sp[cl*264 + p4] = pk.u;
        }
        __syncthreads();
        #pragma unroll
        for (int i = 0; i < 16; i++){
            int lin = tid + i*256;
            int cl = lin & 15, n = lin >> 4;
            int hh = n >> 4, wp = n & 15;
            float acc = wb[cl];
            const float* wk = &ws[cl*9];
            #pragma unroll
            for (int kh = 0; kh < 3; kh++){
                int h2 = hh + kh - 1;
                if (h2 < 0 || h2 > 15) continue;
                #pragma unroll
                for (int kw = 0; kw < 3; kw++){
                    int w2 = wp + kw - 1;
                    if (w2 < 0 || w2 > 15) continue;
                    acc += __half2float(sp[cl*264 + h2*16 + w2]) * wk[kh*3 + kw];
                }
            }
            float val = xs[cl*257 + n] + acc;
            g_xt[((size_t)tb*256 + n)*C_ + c0 + cl] = __float2half_rn(val);
        }
        __syncthreads();
    }
}

// ---------------- LayerNorm + LIF, warp-per-token (fp16 in) -----------------
__global__ void __launch_bounds__(256) k_ln_lif(
        const __half* __restrict__ in, __half* __restrict__ out,
        const float* __restrict__ gam, const float* __restrict__ bet,
        const float* __restrict__ lifw, int lidx){
    int tid = threadIdx.x, wid = tid >> 5, lane = tid & 31;
    int bn = blockIdx.x*8 + wid;
    int cb = lane*16;
    float dec = sigm(lifw[lidx]);
    float gg[16], bb[16];
    #pragma unroll
    for (int i = 0; i < 4; i++){
        float4 t1 = *(const float4*)&gam[cb + i*4];
        float4 t2 = *(const float4*)&bet[cb + i*4];
        gg[i*4]=t1.x; gg[i*4+1]=t1.y; gg[i*4+2]=t1.z; gg[i*4+3]=t1.w;
        bb[i*4]=t2.x; bb[i*4+1]=t2.y; bb[i*4+2]=t2.z; bb[i*4+3]=t2.w;
    }
    float v[16];
    #pragma unroll
    for (int i = 0; i < 16; i++) v[i] = 0.f;
    for (int t = 0; t < T_; t++){
        int row = t*ROWS_PER_T + bn;
        const __half2* xr = (const __half2*)(in + (size_t)row*C_ + cb);
        float xv[16];
        #pragma unroll
        for (int i = 0; i < 8; i++){
            float2 f2 = __half22float2(xr[i]);
            xv[i*2] = f2.x; xv[i*2+1] = f2.y;
        }
        float s = 0.f, ss = 0.f;
        #pragma unroll
        for (int i = 0; i < 16; i++){ s += xv[i]; ss += xv[i]*xv[i]; }
        #pragma unroll
        for (int o = 16; o > 0; o >>= 1){
            s  += __shfl_xor_sync(0xffffffffu, s,  o);
            ss += __shfl_xor_sync(0xffffffffu, ss, o);
        }
        float mean = s*(1.0f/C_);
        float var  = ss*(1.0f/C_) - mean*mean;
        float rstd = rsqrtf(var + 1e-5f);
        union { __half h[16]; uint4 u[2]; } pk;
        #pragma unroll
        for (int k = 0; k < 16; k++){
            float ln = (xv[k]-mean)*rstd*gg[k] + bb[k];
            v[k] += (ln - v[k])*dec;
            float spv = (v[k] >= 1.0f) ? 1.f : 0.f;
            pk.h[k] = __float2half_rn(spv);
            if (spv > 0.f) v[k] = 0.f;
        }
        uint4* dst = (uint4*)(out + (size_t)row*C_ + cb);
        dst[0] = pk.u[0]; dst[1] = pk.u[1];
    }
}

// ---------------- attention phase 1 (HMMA): kvT[e,d] = sum_n v[n,e] k[n,d] --
#define ATT_LD 72
#define ATTKV_SMEM (2*256*ATT_LD*2)   // 73728

__global__ void __launch_bounds__(128) k_attn_kv_mma(){
    extern __shared__ __half satt[];
    __half* sk = satt;
    __half* sv = satt + 256*ATT_LD;
    int blk = blockIdx.x;
    int h  = blk & 7;
    int tb = blk >> 3;
    int tid = threadIdx.x, warp = tid >> 5, lane = tid & 31;

    const __half* base = g_q16 + (size_t)tb*256*(3*C_) + h*D_;
    #pragma unroll
    for (int it = 0; it < 16; it++){
        int task = tid + it*128;
        int row = task >> 3, ch = task & 7;
        cp16(s2u(&sk[row*ATT_LD + ch*8]), base + (size_t)row*(3*C_) + C_   + ch*8);
        cp16(s2u(&sv[row*ATT_LD + ch*8]), base + (size_t)row*(3*C_) + 2*C_ + ch*8);
    }
    asm volatile("cp.async.commit_group;");
    asm volatile("cp.async.wait_group 0;" ::: "memory");
    __syncthreads();

    int l8 = lane >> 3;
    int a_r = (lane & 7) + (l8 >> 1)*8;
    int a_c = warp*16 + (l8 & 1)*8;
    int b_r = (lane & 7) + (l8 & 1)*8;
    int b_c = (l8 >> 1)*8;

    float acc[8][4] = {};
    #pragma unroll 4
    for (int s = 0; s < 16; s++){
        uint32_t af[4];
        ldsm4t(af, s2u(&sv[(s*16 + a_r)*ATT_LD + a_c]));
        #pragma unroll
        for (int j = 0; j < 4; j++){
            uint32_t bf[4];
            ldsm4t(bf, s2u(&sk[(s*16 + b_r)*ATT_LD + j*16 + b_c]));
            mma16816(acc[2*j],   af, bf[0], bf[1]);
            mma16816(acc[2*j+1], af, bf[2], bf[3]);
        }
    }

    __half* dst = g_kvT + (size_t)blk*(D_*D_);
    int g = lane >> 2, i2 = (lane & 3)*2;
    int r0 = warp*16 + g, r1 = r0 + 8;
    #pragma unroll
    for (int ni = 0; ni < 8; ni++){
        int col = ni*8 + i2;
        *(__half2*)&dst[r0*D_ + col] = __floats2half2_rn(acc[ni][0], acc[ni][1]);
        *(__half2*)&dst[r1*D_ + col] = __floats2half2_rn(acc[ni][2], acc[ni][3]);
    }
}

// ---------------- attention phase 2 (HMMA): a = q@kvT*scale + LIF -----------
__global__ void __launch_bounds__(128) k_attn_av_mma(const float* __restrict__ lifw){
    __shared__ __half sq [2][64*ATT_LD];
    __shared__ __half skv[2][64*ATT_LD];
    int blk = blockIdx.x;
    int nt = blk & 3;
    int h  = (blk >> 2) & 7;
    int b  = blk >> 5;
    int tid = threadIdx.x, warp = tid >> 5, lane = tid & 31;
    float dec = sigm(lifw[5]);

    int l8 = lane >> 3;
    int arow = (lane & 7) + (l8 & 1)*8, acol = (l8 >> 1)*8;
    int brow = (lane & 7) + (l8 >> 1)*8, bcol = (l8 & 1)*8;
    int g = lane >> 2, i2 = (lane & 3)*2;

    float vst[8][4];
    #pragma unroll
    for (int ni = 0; ni < 8; ni++)
        #pragma unroll
        for (int c = 0; c < 4; c++) vst[ni][c] = 0.f;

    {
        const __half* qb = g_q16 + ((size_t)(0*B_ + b)*256 + nt*64)*(3*C_) + h*D_;
        const __half* kb = g_kvT + (size_t)((0*B_ + b)*NH_ + h)*(D_*D_);
        #pragma unroll
        for (int it = 0; it < 4; it++){
            int task = tid + it*128;
            int row = task >> 3, ch = task & 7;
            cp16(s2u(&sq [0][row*ATT_LD + ch*8]), qb + (size_t)row*(3*C_) + ch*8);
            cp16(s2u(&skv[0][row*ATT_LD + ch*8]), kb + row*D_ + ch*8);
        }
        asm volatile("cp.async.commit_group;");
    }

    for (int t = 0; t < T_; t++){
        int buf = t & 1;
        if (t + 1 < T_){
            int tb1 = (t+1)*B_ + b;
            const __half* qb = g_q16 + ((size_t)tb1*256 + nt*64)*(3*C_) + h*D_;
            const __half* kb = g_kvT + (size_t)(tb1*NH_ + h)*(D_*D_);
            #pragma unroll
            for (int it = 0; it < 4; it++){
                int task = tid + it*128;
                int row = task >> 3, ch = task & 7;
                cp16(s2u(&sq [buf^1][row*ATT_LD + ch*8]), qb + (size_t)row*(3*C_) + ch*8);
                cp16(s2u(&skv[buf^1][row*ATT_LD + ch*8]), kb + row*D_ + ch*8);
            }
            asm volatile("cp.async.commit_group;");
            asm volatile("cp.async.wait_group 1;" ::: "memory");
        } else {
            asm volatile("cp.async.wait_group 0;" ::: "memory");
        }
        __syncthreads();

        int tb = t*B_ + b;
        float acc[8][4] = {};
        #pragma unroll
        for (int s = 0; s < 4; s++){
            uint32_t af[4];
            ldsm4(af, s2u(&sq[buf][(warp*16 + arow)*ATT_LD + s*16 + acol]));
            #pragma unroll
            for (int j = 0; j < 4; j++){
                uint32_t bf[4];
                ldsm4(bf, s2u(&skv[buf][(j*16 + brow)*ATT_LD + s*16 + bcol]));
                mma16816(acc[2*j],   af, bf[0], bf[1]);
                mma16816(acc[2*j+1], af, bf[2], bf[3]);
            }
        }

        int row0 = tb*256 + nt*64 + warp*16 + g;
        #pragma unroll
        for (int ni = 0; ni < 8; ni++){
            int col = h*D_ + ni*8 + i2;
            __half sp[4];
            #pragma unroll
            for (int c = 0; c < 4; c++){
                float a = acc[ni][c]*0.125f;
                float* v = &vst[ni][c];
                *v += (a - *v)*dec;
                float s = (*v >= 1.0f) ? 1.f : 0.f;
                sp[c] = __float2half_rn(s);
                if (s > 0.f) *v = 0.f;
            }
            *(__half2*)&g_a16[(size_t)row0*C_ + col]     = *(__half2*)&sp[0];
            *(__half2*)&g_a16[(size_t)(row0+8)*C_ + col] = *(__half2*)&sp[2];
        }
        __syncthreads();
    }
}

// ---------------- host orchestration ----------------------------------------
extern "C" void kernel_launch(void* const* d_in, const int* in_sizes, int n_in,
                              void* d_out, int out_size){
    const float* x      = (const float*)d_in[0];
    const float* conv_w = (const float*)d_in[1];
    const float* conv_b = (const float*)d_in[2];
    const float* ln1_g  = (const float*)d_in[3];
    const float* ln1_b  = (const float*)d_in[4];
    const float* qkv_w  = (const float*)d_in[5];
    const float* proj_w = (const float*)d_in[6];
    const float* proj_b = (const float*)d_in[7];
    const float* ln2_g  = (const float*)d_in[8];
    const float* ln2_b  = (const float*)d_in[9];
    const float* fc1_w  = (const float*)d_in[10];
    const float* fc1_b  = (const float*)d_in[11];
    const float* fc2_w  = (const float*)d_in[12];
    const float* fc2_b  = (const float*)d_in[13];
    const float* lif_w  = (const float*)d_in[14];
    float* out = (float*)d_out;

    cudaFuncSetAttribute(tc_gemm<0>, cudaFuncAttributeMaxDynamicSharedMemorySize, GEMM_SMEM);
    cudaFuncSetAttribute(tc_gemm<1>, cudaFuncAttributeMaxDynamicSharedMemorySize, GEMM_SMEM);
    cudaFuncSetAttribute(tc_gemm<2>, cudaFuncAttributeMaxDynamicSharedMemorySize, GEMM_SMEM);
    cudaFuncSetAttribute(tc_gemm<3>, cudaFuncAttributeMaxDynamicSharedMemorySize, GEMM_SMEM);
    cudaFuncSetAttribute(k_attn_kv_mma, cudaFuncAttributeMaxDynamicSharedMemorySize, ATTKV_SMEM);

    __half *p_xt, *p_xt2, *p_h16, *p_q16, *p_a16, *p_m16, *p_w;
    cudaGetSymbolAddress((void**)&p_xt,  g_xt);
    cudaGetSymbolAddress((void**)&p_xt2, g_xt2);
    cudaGetSymbolAddress((void**)&p_h16, g_h16);
    cudaGetSymbolAddress((void**)&p_q16, g_q16);
    cudaGetSymbolAddress((void**)&p_a16, g_a16);
    cudaGetSymbolAddress((void**)&p_m16, g_m16);
    cudaGetSymbolAddress((void**)&p_w,   g_wall);

    k_f2hall<<<786432/256, 256>>>(qkv_w, proj_w, fc1_w, fc2_w);
    k_conv_lif<<<512, 256>>>(x, conv_w, conv_b, lif_w);
    k_ln_lif<<<512, 256>>>(p_xt, p_h16, ln1_g, ln1_b, lif_w, 1);
    tc_gemm<1><<<dim3(12,128), 256, GEMM_SMEM>>>(p_h16, p_w + WOFF_QKV, nullptr, nullptr,
                                                 nullptr, p_q16, lif_w, 3*C_, C_);
    k_attn_kv_mma<<<512, 128, ATTKV_SMEM>>>();
    k_attn_av_mma<<<512, 128>>>(lif_w);
    tc_gemm<0><<<dim3(4,128), 256, GEMM_SMEM>>>(p_a16, p_w + WOFF_PROJ, proj_b, p_xt,
                                                nullptr, p_xt2, lif_w, C_, C_);
    k_ln_lif<<<512, 256>>>(p_xt2, p_h16, ln2_g, ln2_b, lif_w, 6);
    tc_gemm<2><<<dim3(16,128), 256, GEMM_SMEM>>>(p_h16, p_w + WOFF_FC1, fc1_b, nullptr,
                                                 nullptr, p_m16, lif_w, HID_, C_);
    tc_gemm<3><<<dim3(4,128), 256, GEMM_SMEM>>>(p_m16, p_w + WOFF_FC2, fc2_b, p_xt2,
                                                out, nullptr, lif_w, C_, HID_);
}

// round 13
// speedup vs baseline: 1.6448x; 1.0362x over previous
#include <cuda_runtime.h>
#include <cuda_fp16.h>
#include <math.h>
#include <stdint.h>

// ---------------- problem constants ----------------
#define T_  4
#define B_  16
#define C_  512
#define H_  16
#define W_  16
#define N_  256
#define NH_ 8
#define D_  64
#define M_  (T_*B_*N_)     // 16384
#define HID_ 2048
#define ROWS_PER_T (B_*N_) // 4096

// ---------------- scratch ----------------
__device__ __half g_xt [M_*C_];          // residual stream 1 (fp16)
__device__ __half g_xt2[M_*C_];          // residual stream 2 (fp16)
__device__ __half g_h16[M_*C_];
__device__ __half g_q16[M_*3*C_];
__device__ __half g_a16[M_*C_];
__device__ __half g_m16[M_*HID_];
__device__ __half g_kvT[T_*B_*NH_*D_*D_];
__device__ __half g_wall[3*C_*C_ + C_*C_ + 2*HID_*C_];

#define WOFF_QKV  0
#define WOFF_PROJ (3*C_*C_)
#define WOFF_FC1  (WOFF_PROJ + C_*C_)
#define WOFF_FC2  (WOFF_FC1 + HID_*C_)

__device__ __forceinline__ float sigm(float w){ return 1.0f/(1.0f+expf(-w)); }
__device__ __forceinline__ uint32_t s2u(const void* p){
    uint32_t a;
    asm("{ .reg .u64 t; cvta.to.shared.u64 t, %1; cvt.u32.u64 %0, t; }" : "=r"(a) : "l"(p));
    return a;
}
__device__ __forceinline__ void cp16(uint32_t s, const void* g){
    asm volatile("cp.async.cg.shared.global [%0], [%1], 16;" :: "r"(s), "l"(g));
}
__device__ __forceinline__ void ldsm4(uint32_t* r, uint32_t addr){
    asm volatile("ldmatrix.sync.aligned.m8n8.x4.shared.b16 {%0,%1,%2,%3}, [%4];"
                 : "=r"(r[0]), "=r"(r[1]), "=r"(r[2]), "=r"(r[3]) : "r"(addr));
}
__device__ __forceinline__ void ldsm4t(uint32_t* r, uint32_t addr){
    asm volatile("ldmatrix.sync.aligned.m8n8.x4.trans.shared.b16 {%0,%1,%2,%3}, [%4];"
                 : "=r"(r[0]), "=r"(r[1]), "=r"(r[2]), "=r"(r[3]) : "r"(addr));
}
__device__ __forceinline__ void mma16816(float* c, const uint32_t* a, uint32_t b0, uint32_t b1){
    asm volatile(
        "mma.sync.aligned.m16n8k16.row.col.f32.f16.f16.f32 "
        "{%0,%1,%2,%3}, {%4,%5,%6,%7}, {%8,%9}, {%0,%1,%2,%3};"
        : "+f"(c[0]), "+f"(c[1]), "+f"(c[2]), "+f"(c[3])
        : "r"(a[0]), "r"(a[1]), "r"(a[2]), "r"(a[3]), "r"(b0), "r"(b1));
}

// ---------------- HMMA GEMM, BK=64, 3-stage ring ----------------------------
// logical row r = bn_token*4 + t  <->  phys row = (r&3)*4096 + (r>>2)
// MODE 0: bias + fp16 residual -> fp16 out (proj)
// MODE 1: fused LIF per-512-col decay lifw[2..4] -> fp16 spikes (qkv)
// MODE 2: fused LIF decay lifw[7] + bias -> fp16 spikes (fc1)
// MODE 3: bias + fp16 residual, write fp32 transposed [T,B,C,N] direct (fc2)
#define LDT 72
#define S_  3
#define BKC 64
#define STAGE_BYTES (128*LDT*2)       // 18432
#define RING_BYTES  (S_*STAGE_BYTES)
#define GEMM_SMEM (S_*2*STAGE_BYTES)  // 110592
#define STG  132
#define STG3 133

template<int MODE>
__global__ void __launch_bounds__(256, 2) tc_gemm(
        const __half* __restrict__ A, const __half* __restrict__ Wt,
        const float* __restrict__ bias, const __half* __restrict__ res,
        float* __restrict__ outf, __half* __restrict__ outh,
        const float* __restrict__ lifw, int Ndim, int K){
    extern __shared__ char smraw[];
    float* stage = (float*)smraw;
    uint32_t sAu = s2u(smraw);
    uint32_t sBu = sAu + RING_BYTES;

    int tid = threadIdx.x;
    int warp = tid >> 5, lane = tid & 31;
    int wm = (warp & 1) * 64;
    int wn = (warp >> 1) * 32;
    int bm = blockIdx.y * 128, bn = blockIdx.x * 128;
    float acc[4][4][4] = {};

    int row0 = tid >> 3, ch = tid & 7;
    int pr0 = (row0 & 3)*ROWS_PER_T + (bm >> 2) + (row0 >> 2);
    const __half* ga0 = A  + (size_t)pr0*K + ch*8;
    const __half* gb0 = Wt + (size_t)(bn+row0)*K + ch*8;
    uint32_t so0 = (uint32_t)((row0*LDT + ch*8)*2);

    const int NC = K / BKC;
    #pragma unroll
    for (int p = 0; p < S_-1; p++){
        #pragma unroll
        for (int it = 0; it < 4; it++){
            cp16(sAu + p*STAGE_BYTES + so0 + it*(32*LDT*2), ga0 + p*BKC + (size_t)it*8*K);
            cp16(sBu + p*STAGE_BYTES + so0 + it*(32*LDT*2), gb0 + p*BKC + (size_t)it*32*K);
        }
        asm volatile("cp.async.commit_group;");
    }

    int l8 = lane >> 3;
    int arow = (lane & 7) + (l8 & 1) * 8, acol = (l8 >> 1) * 8;
    int brow = (lane & 7) + (l8 >> 1) * 8, bcol = (l8 & 1) * 8;
    uint32_t abase[4], bbase[2];
    #pragma unroll
    for (int mi = 0; mi < 4; mi++)
        abase[mi] = sAu + ((wm + mi*16 + arow)*LDT + acol)*2;
    #pragma unroll
    for (int np = 0; np < 2; np++)
        bbase[np] = sBu + ((wn + np*16 + brow)*LDT + bcol)*2;

    uint32_t stoff = 0;                        // consume cursor
    uint32_t poff  = (S_-1)*STAGE_BYTES;       // produce cursor
    for (int c = 0; c < NC; c++){
        asm volatile("cp.async.wait_group 1;" ::: "memory");
        __syncthreads();
        if (c + 2 < NC){
            int koff = (c + 2)*BKC;
            #pragma unroll
            for (int it = 0; it < 4; it++){
                cp16(sAu + poff + so0 + it*(32*LDT*2), ga0 + koff + (size_t)it*8*K);
                cp16(sBu + poff + so0 + it*(32*LDT*2), gb0 + koff + (size_t)it*32*K);
            }
        }
        asm volatile("cp.async.commit_group;");
        poff += STAGE_BYTES; if (poff == RING_BYTES) poff = 0;
        #pragma unroll
        for (int ks = 0; ks < 4; ks++){
            uint32_t af[4][4], bf[2][4];
            ldsm4(af[0], abase[0] + stoff + ks*32);
            ldsm4(bf[0], bbase[0] + stoff + ks*32);
            ldsm4(bf[1], bbase[1] + stoff + ks*32);
            #pragma unroll
            for (int mi = 0; mi < 4; mi++){
                if (mi < 3) ldsm4(af[mi+1], abase[mi+1] + stoff + ks*32);
                #pragma unroll
                for (int ni = 0; ni < 4; ni++)
                    mma16816(acc[mi][ni], af[mi],
                             bf[ni>>1][2*(ni&1)], bf[ni>>1][2*(ni&1)+1]);
            }
        }
        stoff += STAGE_BYTES; if (stoff == RING_BYTES) stoff = 0;
    }

    int g = lane >> 2, i2 = (lane & 3) * 2;
    if (MODE == 0){
        #pragma unroll
        for (int mi = 0; mi < 4; mi++){
            int rl0 = bm + wm + mi*16 + g;
            int rl1 = rl0 + 8;
            int rp0 = (rl0 & 3)*ROWS_PER_T + (rl0 >> 2);
            int rp1 = (rl1 & 3)*ROWS_PER_T + (rl1 >> 2);
            #pragma unroll
            for (int ni = 0; ni < 4; ni++){
                int col = bn + wn + ni*8 + i2;
                float b0 = bias[col], b1 = bias[col+1];
                size_t o0 = (size_t)rp0*Ndim + col;
                size_t o1 = (size_t)rp1*Ndim + col;
                float2 r0 = __half22float2(*(const __half2*)&res[o0]);
                float2 r1 = __half22float2(*(const __half2*)&res[o1]);
                float v00 = acc[mi][ni][0] + b0 + r0.x;
                float v01 = acc[mi][ni][1] + b1 + r0.y;
                float v10 = acc[mi][ni][2] + b0 + r1.x;
                float v11 = acc[mi][ni][3] + b1 + r1.y;
                *(__half2*)&outh[o0] = __floats2half2_rn(v00, v01);
                *(__half2*)&outh[o1] = __floats2half2_rn(v10, v11);
            }
        }
    } else if (MODE == 1 || MODE == 2){
        __syncthreads();
        #pragma unroll
        for (int mi = 0; mi < 4; mi++){
            int r0 = wm + mi*16 + g, r1 = r0 + 8;
            #pragma unroll
            for (int ni = 0; ni < 4; ni++){
                int cl = wn + ni*8 + i2;
                *(float2*)&stage[r0*STG + cl] = make_float2(acc[mi][ni][0], acc[mi][ni][1]);
                *(float2*)&stage[r1*STG + cl] = make_float2(acc[mi][ni][2], acc[mi][ni][3]);
            }
        }
        __syncthreads();
        float d0, d1 = 0.f, d2 = 0.f;
        if (MODE == 1){ d0 = sigm(lifw[2]); d1 = sigm(lifw[3]); d2 = sigm(lifw[4]); }
        else          { d0 = sigm(lifw[7]); }
        #pragma unroll
        for (int it = 0; it < 2; it++){
            int t2 = tid + it*256;
            int bnl = t2 >> 4, cg = (t2 & 15) * 8;
            int gc = bn + cg;
            float dec = (MODE == 1) ? (gc < 512 ? d0 : (gc < 1024 ? d1 : d2)) : d0;
            float bi[8];
            if (bias){
                float4 q0 = *(const float4*)&bias[gc];
                float4 q1 = *(const float4*)&bias[gc+4];
                bi[0]=q0.x; bi[1]=q0.y; bi[2]=q0.z; bi[3]=q0.w;
                bi[4]=q1.x; bi[5]=q1.y; bi[6]=q1.z; bi[7]=q1.w;
            } else {
                #pragma unroll
                for (int j = 0; j < 8; j++) bi[j] = 0.f;
            }
            float v[8];
            #pragma unroll
            for (int j = 0; j < 8; j++) v[j] = 0.f;
            #pragma unroll
            for (int t = 0; t < 4; t++){
                int r = bnl*4 + t;
                float4 x0 = *(float4*)&stage[r*STG + cg];
                float4 x1 = *(float4*)&stage[r*STG + cg + 4];
                float xv[8] = {x0.x,x0.y,x0.z,x0.w,x1.x,x1.y,x1.z,x1.w};
                union { __half h[8]; uint4 u; } pk;
                #pragma unroll
                for (int j = 0; j < 8; j++){
                    float xx = xv[j] + bi[j];
                    v[j] += (xx - v[j])*dec;
                    float sp = (v[j] >= 1.0f) ? 1.f : 0.f;
                    pk.h[j] = __float2half_rn(sp);
                    if (sp > 0.f) v[j] = 0.f;
                }
                int pr = t*ROWS_PER_T + (bm >> 2) + bnl;
                *(uint4*)&outh[(size_t)pr*Ndim + gc] = pk.u;
            }
        }
    } else {
        __syncthreads();
        #pragma unroll
        for (int mi = 0; mi < 4; mi++){
            int r0 = wm + mi*16 + g, r1 = r0 + 8;
            int rl0 = bm + r0, rl1 = bm + r1;
            int rp0 = (rl0 & 3)*ROWS_PER_T + (rl0 >> 2);
            int rp1 = (rl1 & 3)*ROWS_PER_T + (rl1 >> 2);
            #pragma unroll
            for (int ni = 0; ni < 4; ni++){
                int cl = wn + ni*8 + i2;
                int col = bn + cl;
                float b0 = bias[col], b1 = bias[col+1];
                size_t o0 = (size_t)rp0*Ndim + col;
                size_t o1 = (size_t)rp1*Ndim + col;
                float2 rr0 = __half22float2(*(const __half2*)&res[o0]);
                float2 rr1 = __half22float2(*(const __half2*)&res[o1]);
                stage[r0*STG3 + cl]   = acc[mi][ni][0] + b0 + rr0.x;
                stage[r0*STG3 + cl+1] = acc[mi][ni][1] + b1 + rr0.y;
                stage[r1*STG3 + cl]   = acc[mi][ni][2] + b0 + rr1.x;
                stage[r1*STG3 + cl+1] = acc[mi][ni][3] + b1 + rr1.y;
            }
        }
        __syncthreads();
        int btok = bm >> 2;
        int b = btok >> 8, n0 = btok & 255;
        #pragma unroll
        for (int it = 0; it < 16; it++){
            int f4 = tid + it*256;
            int rown = f4 >> 3;
            int n4 = f4 & 7;
            int cc = rown >> 2, t = rown & 3;
            float4 val;
            val.x = stage[((n4*4+0)*4 + t)*STG3 + cc];
            val.y = stage[((n4*4+1)*4 + t)*STG3 + cc];
            val.z = stage[((n4*4+2)*4 + t)*STG3 + cc];
            val.w = stage[((n4*4+3)*4 + t)*STG3 + cc];
            size_t dst = ((size_t)(t*B_ + b)*C_ + bn + cc)*N_ + n0 + n4*4;
            *(float4*)&outf[dst] = val;
        }
    }
}

// ---------------- fused weight-convert + input-LIF + conv + residual --------
__global__ void __launch_bounds__(256) k_conv_lif(
        const float* __restrict__ x, const float* __restrict__ cw,
        const float* __restrict__ cb, const float* __restrict__ lifw,
        const float* __restrict__ w0, const float* __restrict__ w1,
        const float* __restrict__ w2, const float* __restrict__ w3){
    __shared__ float  xs[16*257];
    __shared__ __half sp[16*264];
    __shared__ float  ws[16*9];
    __shared__ float  wb[16];
    int tid = threadIdx.x;
    int b  = blockIdx.x >> 5;
    int c0 = (blockIdx.x & 31) * 16;

    // weight fp32 -> fp16 conversion (6 float4 tasks per thread, 786432 total)
    {
        int gtid = blockIdx.x*256 + tid;        // 0..131071
        #pragma unroll
        for (int i = 0; i < 6; i++){
            int idx = gtid + i*131072;
            const float* src;
            if (idx < 196608)      src = w0;
            else if (idx < 262144) src = w1 - 786432;
            else if (idx < 524288) src = w2 - 1048576;
            else                   src = w3 - 2097152;
            float4 f = *(const float4*)&src[(size_t)idx*4];
            union { __half h[4]; uint2 u; } pk;
            pk.h[0]=__float2half_rn(f.x); pk.h[1]=__float2half_rn(f.y);
            pk.h[2]=__float2half_rn(f.z); pk.h[3]=__float2half_rn(f.w);
            *(uint2*)&g_wall[(size_t)idx*4] = pk.u;
        }
    }

    if (tid < 16*9) ws[tid] = cw[c0*9 + tid];
    if (tid < 16)   wb[tid] = cb[c0 + tid];
    float dec = sigm(lifw[0]);
    float v[4][4];
    #pragma unroll
    for (int i = 0; i < 4; i++)
        #pragma unroll
        for (int j = 0; j < 4; j++) v[i][j] = 0.f;
    __syncthreads();
    for (int t = 0; t < T_; t++){
        int tb = t*B_ + b;
        #pragma unroll
        for (int i = 0; i < 4; i++){
            int f4 = tid + i*256;
            int cl = f4 >> 6, p4 = (f4 & 63)*4;
            float4 xv = *(const float4*)&x[((size_t)tb*C_ + c0 + cl)*256 + p4];
            float xa[4] = {xv.x, xv.y, xv.z, xv.w};
            union { __half h[4]; uint2 u; } pk;
            #pragma unroll
            for (int j = 0; j < 4; j++){
                xs[cl*257 + p4 + j] = xa[j];
                float vv = v[i][j] + (xa[j] - v[i][j])*dec;
                float s = (vv >= 1.0f) ? 1.f : 0.f;
                v[i][j] = (s > 0.f) ? 0.f : vv;
                pk.h[j] = __float2half_rn(s);
            }
            *(uint2*)&sp[cl*264 + p4] = pk.u;
        }
        __syncthreads();
        #pragma unroll
        for (int i = 0; i < 16; i++){
            int lin = tid + i*256;
            int cl = lin & 15, n = lin >> 4;
            int hh = n >> 4, wp = n & 15;
            float acc = wb[cl];
            const float* wk = &ws[cl*9];
            #pragma unroll
            for (int kh = 0; kh < 3; kh++){
                int h2 = hh + kh - 1;
                if (h2 < 0 || h2 > 15) continue;
                #pragma unroll
                for (int kw = 0; kw < 3; kw++){
                    int w2 = wp + kw - 1;
                    if (w2 < 0 || w2 > 15) continue;
                    acc += __half2float(sp[cl*264 + h2*16 + w2]) * wk[kh*3 + kw];
                }
            }
            float val = xs[cl*257 + n] + acc;
            g_xt[((size_t)tb*256 + n)*C_ + c0 + cl] = __float2half_rn(val);
        }
        __syncthreads();
    }
}

// ---------------- LayerNorm + LIF, warp-per-token (fp16 in) -----------------
__global__ void __launch_bounds__(256) k_ln_lif(
        const __half* __restrict__ in, __half* __restrict__ out,
        const float* __restrict__ gam, const float* __restrict__ bet,
        const float* __restrict__ lifw, int lidx){
    int tid = threadIdx.x, wid = tid >> 5, lane = tid & 31;
    int bn = blockIdx.x*8 + wid;
    int cb = lane*16;
    float dec = sigm(lifw[lidx]);
    float gg[16], bb[16];
    #pragma unroll
    for (int i = 0; i < 4; i++){
        float4 t1 = *(const float4*)&gam[cb + i*4];
        float4 t2 = *(const float4*)&bet[cb + i*4];
        gg[i*4]=t1.x; gg[i*4+1]=t1.y; gg[i*4+2]=t1.z; gg[i*4+3]=t1.w;
        bb[i*4]=t2.x; bb[i*4+1]=t2.y; bb[i*4+2]=t2.z; bb[i*4+3]=t2.w;
    }
    float v[16];
    #pragma unroll
    for (int i = 0; i < 16; i++) v[i] = 0.f;
    for (int t = 0; t < T_; t++){
        int row = t*ROWS_PER_T + bn;
        const __half2* xr = (const __half2*)(in + (size_t)row*C_ + cb);
        float xv[16];
        #pragma unroll
        for (int i = 0; i < 8; i++){
            float2 f2 = __half22float2(xr[i]);
            xv[i*2] = f2.x; xv[i*2+1] = f2.y;
        }
        float s = 0.f, ss = 0.f;
        #pragma unroll
        for (int i = 0; i < 16; i++){ s += xv[i]; ss += xv[i]*xv[i]; }
        #pragma unroll
        for (int o = 16; o > 0; o >>= 1){
            s  += __shfl_xor_sync(0xffffffffu, s,  o);
            ss += __shfl_xor_sync(0xffffffffu, ss, o);
        }
        float mean = s*(1.0f/C_);
        float var  = ss*(1.0f/C_) - mean*mean;
        float rstd = rsqrtf(var + 1e-5f);
        union { __half h[16]; uint4 u[2]; } pk;
        #pragma unroll
        for (int k = 0; k < 16; k++){
            float ln = (xv[k]-mean)*rstd*gg[k] + bb[k];
            v[k] += (ln - v[k])*dec;
            float spv = (v[k] >= 1.0f) ? 1.f : 0.f;
            pk.h[k] = __float2half_rn(spv);
            if (spv > 0.f) v[k] = 0.f;
        }
        uint4* dst = (uint4*)(out + (size_t)row*C_ + cb);
        dst[0] = pk.u[0]; dst[1] = pk.u[1];
    }
}

// ---------------- attention phase 1 (HMMA): kvT[e,d] = sum_n v[n,e] k[n,d] --
#define ATT_LD 72
#define ATTKV_SMEM (2*256*ATT_LD*2)   // 73728

__global__ void __launch_bounds__(128) k_attn_kv_mma(){
    extern __shared__ __half satt[];
    __half* sk = satt;
    __half* sv = satt + 256*ATT_LD;
    int blk = blockIdx.x;
    int h  = blk & 7;
    int tb = blk >> 3;
    int tid = threadIdx.x, warp = tid >> 5, lane = tid & 31;

    const __half* base = g_q16 + (size_t)tb*256*(3*C_) + h*D_;
    #pragma unroll
    for (int it = 0; it < 16; it++){
        int task = tid + it*128;
        int row = task >> 3, ch = task & 7;
        cp16(s2u(&sk[row*ATT_LD + ch*8]), base + (size_t)row*(3*C_) + C_   + ch*8);
        cp16(s2u(&sv[row*ATT_LD + ch*8]), base + (size_t)row*(3*C_) + 2*C_ + ch*8);
    }
    asm volatile("cp.async.commit_group;");
    asm volatile("cp.async.wait_group 0;" ::: "memory");
    __syncthreads();

    int l8 = lane >> 3;
    int a_r = (lane & 7) + (l8 >> 1)*8;
    int a_c = warp*16 + (l8 & 1)*8;
    int b_r = (lane & 7) + (l8 & 1)*8;
    int b_c = (l8 >> 1)*8;

    float acc[8][4] = {};
    #pragma unroll 4
    for (int s = 0; s < 16; s++){
        uint32_t af[4];
        ldsm4t(af, s2u(&sv[(s*16 + a_r)*ATT_LD + a_c]));
        #pragma unroll
        for (int j = 0; j < 4; j++){
            uint32_t bf[4];
            ldsm4t(bf, s2u(&sk[(s*16 + b_r)*ATT_LD + j*16 + b_c]));
            mma16816(acc[2*j],   af, bf[0], bf[1]);
            mma16816(acc[2*j+1], af, bf[2], bf[3]);
        }
    }

    __half* dst = g_kvT + (size_t)blk*(D_*D_);
    int g = lane >> 2, i2 = (lane & 3)*2;
    int r0 = warp*16 + g, r1 = r0 + 8;
    #pragma unroll
    for (int ni = 0; ni < 8; ni++){
        int col = ni*8 + i2;
        *(__half2*)&dst[r0*D_ + col] = __floats2half2_rn(acc[ni][0], acc[ni][1]);
        *(__half2*)&dst[r1*D_ + col] = __floats2half2_rn(acc[ni][2], acc[ni][3]);
    }
}

// ---------------- attention phase 2 (HMMA): a = q@kvT*scale + LIF -----------
__global__ void __launch_bounds__(128) k_attn_av_mma(const float* __restrict__ lifw){
    __shared__ __half sq [2][64*ATT_LD];
    __shared__ __half skv[2][64*ATT_LD];
    int blk = blockIdx.x;
    int nt = blk & 3;
    int h  = (blk >> 2) & 7;
    int b  = blk >> 5;
    int tid = threadIdx.x, warp = tid >> 5, lane = tid & 31;
    float dec = sigm(lifw[5]);

    int l8 = lane >> 3;
    int arow = (lane & 7) + (l8 & 1)*8, acol = (l8 >> 1)*8;
    int brow = (lane & 7) + (l8 >> 1)*8, bcol = (l8 & 1)*8;
    int g = lane >> 2, i2 = (lane & 3)*2;

    float vst[8][4];
    #pragma unroll
    for (int ni = 0; ni < 8; ni++)
        #pragma unroll
        for (int c = 0; c < 4; c++) vst[ni][c] = 0.f;

    {
        const __half* qb = g_q16 + ((size_t)(0*B_ + b)*256 + nt*64)*(3*C_) + h*D_;
        const __half* kb = g_kvT + (size_t)((0*B_ + b)*NH_ + h)*(D_*D_);
        #pragma unroll
        for (int it = 0; it < 4; it++){
            int task = tid + it*128;
            int row = task >> 3, ch = task & 7;
            cp16(s2u(&sq [0][row*ATT_LD + ch*8]), qb + (size_t)row*(3*C_) + ch*8);
            cp16(s2u(&skv[0][row*ATT_LD + ch*8]), kb + row*D_ + ch*8);
        }
        asm volatile("cp.async.commit_group;");
    }

    for (int t = 0; t < T_; t++){
        int buf = t & 1;
        if (t + 1 < T_){
            int tb1 = (t+1)*B_ + b;
            const __half* qb = g_q16 + ((size_t)tb1*256 + nt*64)*(3*C_) + h*D_;
            const __half* kb = g_kvT + (size_t)(tb1*NH_ + h)*(D_*D_);
            #pragma unroll
            for (int it = 0; it < 4; it++){
                int task = tid + it*128;
                int row = task >> 3, ch = task & 7;
                cp16(s2u(&sq [buf^1][row*ATT_LD + ch*8]), qb + (size_t)row*(3*C_) + ch*8);
                cp16(s2u(&skv[buf^1][row*ATT_LD + ch*8]), kb + row*D_ + ch*8);
            }
            asm volatile("cp.async.commit_group;");
            asm volatile("cp.async.wait_group 1;" ::: "memory");
        } else {
            asm volatile("cp.async.wait_group 0;" ::: "memory");
        }
        __syncthreads();

        int tb = t*B_ + b;
        float acc[8][4] = {};
        #pragma unroll
        for (int s = 0; s < 4; s++){
            uint32_t af[4];
            ldsm4(af, s2u(&sq[buf][(warp*16 + arow)*ATT_LD + s*16 + acol]));
            #pragma unroll
            for (int j = 0; j < 4; j++){
                uint32_t bf[4];
                ldsm4(bf, s2u(&skv[buf][(j*16 + brow)*ATT_LD + s*16 + bcol]));
                mma16816(acc[2*j],   af, bf[0], bf[1]);
                mma16816(acc[2*j+1], af, bf[2], bf[3]);
            }
        }

        int row0 = tb*256 + nt*64 + warp*16 + g;
        #pragma unroll
        for (int ni = 0; ni < 8; ni++){
            int col = h*D_ + ni*8 + i2;
            __half sp[4];
            #pragma unroll
            for (int c = 0; c < 4; c++){
                float a = acc[ni][c]*0.125f;
                float* v = &vst[ni][c];
                *v += (a - *v)*dec;
                float s = (*v >= 1.0f) ? 1.f : 0.f;
                sp[c] = __float2half_rn(s);
                if (s > 0.f) *v = 0.f;
            }
            *(__half2*)&g_a16[(size_t)row0*C_ + col]     = *(__half2*)&sp[0];
            *(__half2*)&g_a16[(size_t)(row0+8)*C_ + col] = *(__half2*)&sp[2];
        }
        __syncthreads();
    }
}

// ---------------- host orchestration ----------------------------------------
extern "C" void kernel_launch(void* const* d_in, const int* in_sizes, int n_in,
                              void* d_out, int out_size){
    const float* x      = (const float*)d_in[0];
    const float* conv_w = (const float*)d_in[1];
    const float* conv_b = (const float*)d_in[2];
    const float* ln1_g  = (const float*)d_in[3];
    const float* ln1_b  = (const float*)d_in[4];
    const float* qkv_w  = (const float*)d_in[5];
    const float* proj_w = (const float*)d_in[6];
    const float* proj_b = (const float*)d_in[7];
    const float* ln2_g  = (const float*)d_in[8];
    const float* ln2_b  = (const float*)d_in[9];
    const float* fc1_w  = (const float*)d_in[10];
    const float* fc1_b  = (const float*)d_in[11];
    const float* fc2_w  = (const float*)d_in[12];
    const float* fc2_b  = (const float*)d_in[13];
    const float* lif_w  = (const float*)d_in[14];
    float* out = (float*)d_out;

    cudaFuncSetAttribute(tc_gemm<0>, cudaFuncAttributeMaxDynamicSharedMemorySize, GEMM_SMEM);
    cudaFuncSetAttribute(tc_gemm<1>, cudaFuncAttributeMaxDynamicSharedMemorySize, GEMM_SMEM);
    cudaFuncSetAttribute(tc_gemm<2>, cudaFuncAttributeMaxDynamicSharedMemorySize, GEMM_SMEM);
    cudaFuncSetAttribute(tc_gemm<3>, cudaFuncAttributeMaxDynamicSharedMemorySize, GEMM_SMEM);
    cudaFuncSetAttribute(k_attn_kv_mma, cudaFuncAttributeMaxDynamicSharedMemorySize, ATTKV_SMEM);

    __half *p_xt, *p_xt2, *p_h16, *p_q16, *p_a16, *p_m16, *p_w;
    cudaGetSymbolAddress((void**)&p_xt,  g_xt);
    cudaGetSymbolAddress((void**)&p_xt2, g_xt2);
    cudaGetSymbolAddress((void**)&p_h16, g_h16);
    cudaGetSymbolAddress((void**)&p_q16, g_q16);
    cudaGetSymbolAddress((void**)&p_a16, g_a16);
    cudaGetSymbolAddress((void**)&p_m16, g_m16);
    cudaGetSymbolAddress((void**)&p_w,   g_wall);

    k_conv_lif<<<512, 256>>>(x, conv_w, conv_b, lif_w, qkv_w, proj_w, fc1_w, fc2_w);
    k_ln_lif<<<512, 256>>>(p_xt, p_h16, ln1_g, ln1_b, lif_w, 1);
    tc_gemm<1><<<dim3(12,128), 256, GEMM_SMEM>>>(p_h16, p_w + WOFF_QKV, nullptr, nullptr,
                                                 nullptr, p_q16, lif_w, 3*C_, C_);
    k_attn_kv_mma<<<512, 128, ATTKV_SMEM>>>();
    k_attn_av_mma<<<512, 128>>>(lif_w);
    tc_gemm<0><<<dim3(4,128), 256, GEMM_SMEM>>>(p_a16, p_w + WOFF_PROJ, proj_b, p_xt,
                                                nullptr, p_xt2, lif_w, C_, C_);
    k_ln_lif<<<512, 256>>>(p_xt2, p_h16, ln2_g, ln2_b, lif_w, 6);
    tc_gemm<2><<<dim3(16,128), 256, GEMM_SMEM>>>(p_h16, p_w + WOFF_FC1, fc1_b, nullptr,
                                                 nullptr, p_m16, lif_w, HID_, C_);
    tc_gemm<3><<<dim3(4,128), 256, GEMM_SMEM>>>(p_m16, p_w + WOFF_FC2, fc2_b, p_xt2,
                                                out, nullptr, lif_w, C_, HID_);
}

// round 16
// speedup vs baseline: 1.6550x; 1.0062x over previous
#include <cuda_runtime.h>
#include <cuda_fp16.h>
#include <math.h>
#include <stdint.h>

// ---------------- problem constants ----------------
#define T_  4
#define B_  16
#define C_  512
#define H_  16
#define W_  16
#define N_  256
#define NH_ 8
#define D_  64
#define M_  (T_*B_*N_)     // 16384
#define HID_ 2048
#define ROWS_PER_T (B_*N_) // 4096

// ---------------- scratch ----------------
__device__ __half g_xt [M_*C_];
__device__ __half g_xt2[M_*C_];
__device__ __half g_h16[M_*C_];
__device__ __half g_q16[M_*3*C_];
__device__ __half g_a16[M_*C_];
__device__ __half g_m16[M_*HID_];
__device__ __half g_kvT[T_*B_*NH_*D_*D_];
__device__ __half g_wall[3*C_*C_ + C_*C_ + 2*HID_*C_];

#define WOFF_QKV  0
#define WOFF_PROJ (3*C_*C_)
#define WOFF_FC1  (WOFF_PROJ + C_*C_)
#define WOFF_FC2  (WOFF_FC1 + HID_*C_)

__device__ __forceinline__ float sigm(float w){ return 1.0f/(1.0f+expf(-w)); }
__device__ __forceinline__ uint32_t s2u(const void* p){
    uint32_t a;
    asm("{ .reg .u64 t; cvta.to.shared.u64 t, %1; cvt.u32.u64 %0, t; }" : "=r"(a) : "l"(p));
    return a;
}
__device__ __forceinline__ void cp16(uint32_t s, const void* g){
    asm volatile("cp.async.cg.shared.global [%0], [%1], 16;" :: "r"(s), "l"(g));
}
__device__ __forceinline__ void ldsm4(uint32_t* r, uint32_t addr){
    asm volatile("ldmatrix.sync.aligned.m8n8.x4.shared.b16 {%0,%1,%2,%3}, [%4];"
                 : "=r"(r[0]), "=r"(r[1]), "=r"(r[2]), "=r"(r[3]) : "r"(addr));
}
__device__ __forceinline__ void ldsm4t(uint32_t* r, uint32_t addr){
    asm volatile("ldmatrix.sync.aligned.m8n8.x4.trans.shared.b16 {%0,%1,%2,%3}, [%4];"
                 : "=r"(r[0]), "=r"(r[1]), "=r"(r[2]), "=r"(r[3]) : "r"(addr));
}
__device__ __forceinline__ void mma16816(float* c, const uint32_t* a, uint32_t b0, uint32_t b1){
    asm volatile(
        "mma.sync.aligned.m16n8k16.row.col.f32.f16.f16.f32 "
        "{%0,%1,%2,%3}, {%4,%5,%6,%7}, {%8,%9}, {%0,%1,%2,%3};"
        : "+f"(c[0]), "+f"(c[1]), "+f"(c[2]), "+f"(c[3])
        : "r"(a[0]), "r"(a[1]), "r"(a[2]), "r"(a[3]), "r"(b0), "r"(b1));
}

// ---------------- HMMA GEMM, BK=64, 3-stage ring ----------------------------
#define LDT 72
#define S_  3
#define BKC 64
#define STAGE_BYTES (128*LDT*2)       // 18432
#define RING_BYTES  (S_*STAGE_BYTES)
#define GEMM_SMEM (S_*2*STAGE_BYTES)  // 110592
#define STG  132
#define STG3 133

template<int MODE>
__global__ void __launch_bounds__(256, 2) tc_gemm(
        const __half* __restrict__ A, const __half* __restrict__ Wt,
        const float* __restrict__ bias, const __half* __restrict__ res,
        float* __restrict__ outf, __half* __restrict__ outh,
        const float* __restrict__ lifw, int Ndim, int K){
    extern __shared__ char smraw[];
    float* stage = (float*)smraw;
    uint32_t sAu = s2u(smraw);
    uint32_t sBu = sAu + RING_BYTES;

    int tid = threadIdx.x;
    int warp = tid >> 5, lane = tid & 31;
    int wm = (warp & 1) * 64;
    int wn = (warp >> 1) * 32;
    int bm = blockIdx.y * 128, bn = blockIdx.x * 128;
    float acc[4][4][4] = {};

    int row0 = tid >> 3, ch = tid & 7;
    int pr0 = (row0 & 3)*ROWS_PER_T + (bm >> 2) + (row0 >> 2);
    const __half* ga0 = A  + (size_t)pr0*K + ch*8;
    const __half* gb0 = Wt + (size_t)(bn+row0)*K + ch*8;
    uint32_t so0 = (uint32_t)((row0*LDT + ch*8)*2);

    const int NC = K / BKC;
    #pragma unroll
    for (int p = 0; p < S_-1; p++){
        #pragma unroll
        for (int it = 0; it < 4; it++){
            cp16(sAu + p*STAGE_BYTES + so0 + it*(32*LDT*2), ga0 + p*BKC + (size_t)it*8*K);
            cp16(sBu + p*STAGE_BYTES + so0 + it*(32*LDT*2), gb0 + p*BKC + (size_t)it*32*K);
        }
        asm volatile("cp.async.commit_group;");
    }

    int l8 = lane >> 3;
    int arow = (lane & 7) + (l8 & 1) * 8, acol = (l8 >> 1) * 8;
    int brow = (lane & 7) + (l8 >> 1) * 8, bcol = (l8 & 1) * 8;
    uint32_t abase[4], bbase[2];
    #pragma unroll
    for (int mi = 0; mi < 4; mi++)
        abase[mi] = sAu + ((wm + mi*16 + arow)*LDT + acol)*2;
    #pragma unroll
    for (int np = 0; np < 2; np++)
        bbase[np] = sBu + ((wn + np*16 + brow)*LDT + bcol)*2;

    uint32_t stoff = 0;
    uint32_t poff  = (S_-1)*STAGE_BYTES;
    for (int c = 0; c < NC; c++){
        asm volatile("cp.async.wait_group 1;" ::: "memory");
        __syncthreads();
        if (c + 2 < NC){
            int koff = (c + 2)*BKC;
            #pragma unroll
            for (int it = 0; it < 4; it++){
                cp16(sAu + poff + so0 + it*(32*LDT*2), ga0 + koff + (size_t)it*8*K);
                cp16(sBu + poff + so0 + it*(32*LDT*2), gb0 + koff + (size_t)it*32*K);
            }
        }
        asm volatile("cp.async.commit_group;");
        poff += STAGE_BYTES; if (poff == RING_BYTES) poff = 0;
        #pragma unroll
        for (int ks = 0; ks < 4; ks++){
            uint32_t af[4][4], bf[2][4];
            ldsm4(af[0], abase[0] + stoff + ks*32);
            ldsm4(bf[0], bbase[0] + stoff + ks*32);
            ldsm4(bf[1], bbase[1] + stoff + ks*32);
            #pragma unroll
            for (int mi = 0; mi < 4; mi++){
                if (mi < 3) ldsm4(af[mi+1], abase[mi+1] + stoff + ks*32);
                #pragma unroll
                for (int ni = 0; ni < 4; ni++)
                    mma16816(acc[mi][ni], af[mi],
                             bf[ni>>1][2*(ni&1)], bf[ni>>1][2*(ni&1)+1]);
            }
        }
        stoff += STAGE_BYTES; if (stoff == RING_BYTES) stoff = 0;
    }

    int g = lane >> 2, i2 = (lane & 3) * 2;
    if (MODE == 0){
        #pragma unroll
        for (int mi = 0; mi < 4; mi++){
            int rl0 = bm + wm + mi*16 + g;
            int rl1 = rl0 + 8;
            int rp0 = (rl0 & 3)*ROWS_PER_T + (rl0 >> 2);
            int rp1 = (rl1 & 3)*ROWS_PER_T + (rl1 >> 2);
            #pragma unroll
            for (int ni = 0; ni < 4; ni++){
                int col = bn + wn + ni*8 + i2;
                float b0 = bias[col], b1 = bias[col+1];
                size_t o0 = (size_t)rp0*Ndim + col;
                size_t o1 = (size_t)rp1*Ndim + col;
                float2 r0 = __half22float2(*(const __half2*)&res[o0]);
                float2 r1 = __half22float2(*(const __half2*)&res[o1]);
                float v00 = acc[mi][ni][0] + b0 + r0.x;
                float v01 = acc[mi][ni][1] + b1 + r0.y;
                float v10 = acc[mi][ni][2] + b0 + r1.x;
                float v11 = acc[mi][ni][3] + b1 + r1.y;
                *(__half2*)&outh[o0] = __floats2half2_rn(v00, v01);
                *(__half2*)&outh[o1] = __floats2half2_rn(v10, v11);
            }
        }
    } else if (MODE == 1 || MODE == 2){
        __syncthreads();
        #pragma unroll
        for (int mi = 0; mi < 4; mi++){
            int r0 = wm + mi*16 + g, r1 = r0 + 8;
            #pragma unroll
            for (int ni = 0; ni < 4; ni++){
                int cl = wn + ni*8 + i2;
                *(float2*)&stage[r0*STG + cl] = make_float2(acc[mi][ni][0], acc[mi][ni][1]);
                *(float2*)&stage[r1*STG + cl] = make_float2(acc[mi][ni][2], acc[mi][ni][3]);
            }
        }
        __syncthreads();
        float d0, d1 = 0.f, d2 = 0.f;
        if (MODE == 1){ d0 = sigm(lifw[2]); d1 = sigm(lifw[3]); d2 = sigm(lifw[4]); }
        else          { d0 = sigm(lifw[7]); }
        #pragma unroll
        for (int it = 0; it < 2; it++){
            int t2 = tid + it*256;
            int bnl = t2 >> 4, cg = (t2 & 15) * 8;
            int gc = bn + cg;
            float dec = (MODE == 1) ? (gc < 512 ? d0 : (gc < 1024 ? d1 : d2)) : d0;
            float bi[8];
            if (bias){
                float4 q0 = *(const float4*)&bias[gc];
                float4 q1 = *(const float4*)&bias[gc+4];
                bi[0]=q0.x; bi[1]=q0.y; bi[2]=q0.z; bi[3]=q0.w;
                bi[4]=q1.x; bi[5]=q1.y; bi[6]=q1.z; bi[7]=q1.w;
            } else {
                #pragma unroll
                for (int j = 0; j < 8; j++) bi[j] = 0.f;
            }
            float v[8];
            #pragma unroll
            for (int j = 0; j < 8; j++) v[j] = 0.f;
            #pragma unroll
            for (int t = 0; t < 4; t++){
                int r = bnl*4 + t;
                float4 x0 = *(float4*)&stage[r*STG + cg];
                float4 x1 = *(float4*)&stage[r*STG + cg + 4];
                float xv[8] = {x0.x,x0.y,x0.z,x0.w,x1.x,x1.y,x1.z,x1.w};
                union { __half h[8]; uint4 u; } pk;
                #pragma unroll
                for (int j = 0; j < 8; j++){
                    float xx = xv[j] + bi[j];
                    v[j] += (xx - v[j])*dec;
                    float sp = (v[j] >= 1.0f) ? 1.f : 0.f;
                    pk.h[j] = __float2half_rn(sp);
                    if (sp > 0.f) v[j] = 0.f;
                }
                int pr = t*ROWS_PER_T + (bm >> 2) + bnl;
                *(uint4*)&outh[(size_t)pr*Ndim + gc] = pk.u;
            }
        }
    } else {
        __syncthreads();
        #pragma unroll
        for (int mi = 0; mi < 4; mi++){
            int r0 = wm + mi*16 + g, r1 = r0 + 8;
            int rl0 = bm + r0, rl1 = bm + r1;
            int rp0 = (rl0 & 3)*ROWS_PER_T + (rl0 >> 2);
            int rp1 = (rl1 & 3)*ROWS_PER_T + (rl1 >> 2);
            #pragma unroll
            for (int ni = 0; ni < 4; ni++){
                int cl = wn + ni*8 + i2;
                int col = bn + cl;
                float b0 = bias[col], b1 = bias[col+1];
                size_t o0 = (size_t)rp0*Ndim + col;
                size_t o1 = (size_t)rp1*Ndim + col;
                float2 rr0 = __half22float2(*(const __half2*)&res[o0]);
                float2 rr1 = __half22float2(*(const __half2*)&res[o1]);
                stage[r0*STG3 + cl]   = acc[mi][ni][0] + b0 + rr0.x;
                stage[r0*STG3 + cl+1] = acc[mi][ni][1] + b1 + rr0.y;
                stage[r1*STG3 + cl]   = acc[mi][ni][2] + b0 + rr1.x;
                stage[r1*STG3 + cl+1] = acc[mi][ni][3] + b1 + rr1.y;
            }
        }
        __syncthreads();
        int btok = bm >> 2;
        int b = btok >> 8, n0 = btok & 255;
        #pragma unroll
        for (int it = 0; it < 16; it++){
            int f4 = tid + it*256;
            int rown = f4 >> 3;
            int n4 = f4 & 7;
            int cc = rown >> 2, t = rown & 3;
            float4 val;
            val.x = stage[((n4*4+0)*4 + t)*STG3 + cc];
            val.y = stage[((n4*4+1)*4 + t)*STG3 + cc];
            val.z = stage[((n4*4+2)*4 + t)*STG3 + cc];
            val.w = stage[((n4*4+3)*4 + t)*STG3 + cc];
            size_t dst = ((size_t)(t*B_ + b)*C_ + bn + cc)*N_ + n0 + n4*4;
            *(float4*)&outf[dst] = val;
        }
    }
}

// ---------------- fused weight-convert + input-LIF + conv + residual --------
__global__ void __launch_bounds__(256) k_conv_lif(
        const float* __restrict__ x, const float* __restrict__ cw,
        const float* __restrict__ cb, const float* __restrict__ lifw,
        const float* __restrict__ w0, const float* __restrict__ w1,
        const float* __restrict__ w2, const float* __restrict__ w3){
    __shared__ float  xs[16*257];
    __shared__ __half sp[16*264];
    __shared__ float  ws[16*9];
    __shared__ float  wb[16];
    int tid = threadIdx.x;
    int b  = blockIdx.x >> 5;
    int c0 = (blockIdx.x & 31) * 16;

    {
        int gtid = blockIdx.x*256 + tid;
        #pragma unroll
        for (int i = 0; i < 6; i++){
            int idx = gtid + i*131072;
            const float* src;
            if (idx < 196608)      src = w0;
            else if (idx < 262144) src = w1 - 786432;
            else if (idx < 524288) src = w2 - 1048576;
            else                   src = w3 - 2097152;
            float4 f = *(const float4*)&src[(size_t)idx*4];
            union { __half h[4]; uint2 u; } pk;
            pk.h[0]=__float2half_rn(f.x); pk.h[1]=__float2half_rn(f.y);
            pk.h[2]=__float2half_rn(f.z); pk.h[3]=__float2half_rn(f.w);
            *(uint2*)&g_wall[(size_t)idx*4] = pk.u;
        }
    }

    if (tid < 16*9) ws[tid] = cw[c0*9 + tid];
    if (tid < 16)   wb[tid] = cb[c0 + tid];
    float dec = sigm(lifw[0]);
    float v[4][4];
    #pragma unroll
    for (int i = 0; i < 4; i++)
        #pragma unroll
        for (int j = 0; j < 4; j++) v[i][j] = 0.f;
    __syncthreads();
    for (int t = 0; t < T_; t++){
        int tb = t*B_ + b;
        #pragma unroll
        for (int i = 0; i < 4; i++){
            int f4 = tid + i*256;
            int cl = f4 >> 6, p4 = (f4 & 63)*4;
            float4 xv = *(const float4*)&x[((size_t)tb*C_ + c0 + cl)*256 + p4];
            float xa[4] = {xv.x, xv.y, xv.z, xv.w};
            union { __half h[4]; uint2 u; } pk;
            #pragma unroll
            for (int j = 0; j < 4; j++){
                xs[cl*257 + p4 + j] = xa[j];
                float vv = v[i][j] + (xa[j] - v[i][j])*dec;
                float s = (vv >= 1.0f) ? 1.f : 0.f;
                v[i][j] = (s > 0.f) ? 0.f : vv;
                pk.h[j] = __float2half_rn(s);
            }
            *(uint2*)&sp[cl*264 + p4] = pk.u;
        }
        __syncthreads();
        #pragma unroll
        for (int i = 0; i < 16; i++){
            int lin = tid + i*256;
            int cl = lin & 15, n = lin >> 4;
            int hh = n >> 4, wp = n & 15;
            float acc = wb[cl];
            const float* wk = &ws[cl*9];
            #pragma unroll
            for (int kh = 0; kh < 3; kh++){
                int h2 = hh + kh - 1;
                if (h2 < 0 || h2 > 15) continue;
                #pragma unroll
                for (int kw = 0; kw < 3; kw++){
                    int w2 = wp + kw - 1;
                    if (w2 < 0 || w2 > 15) continue;
                    acc += __half2float(sp[cl*264 + h2*16 + w2]) * wk[kh*3 + kw];
                }
            }
            float val = xs[cl*257 + n] + acc;
            g_xt[((size_t)tb*256 + n)*C_ + c0 + cl] = __float2half_rn(val);
        }
        __syncthreads();
    }
}

// ---------------- LayerNorm + LIF, warp-per-token (fp16 in) -----------------
__global__ void __launch_bounds__(256) k_ln_lif(
        const __half* __restrict__ in, __half* __restrict__ out,
        const float* __restrict__ gam, const float* __restrict__ bet,
        const float* __restrict__ lifw, int lidx){
    int tid = threadIdx.x, wid = tid >> 5, lane = tid & 31;
    int bn = blockIdx.x*8 + wid;
    int cb = lane*16;
    float dec = sigm(lifw[lidx]);
    float gg[16], bb[16];
    #pragma unroll
    for (int i = 0; i < 4; i++){
        float4 t1 = *(const float4*)&gam[cb + i*4];
        float4 t2 = *(const float4*)&bet[cb + i*4];
        gg[i*4]=t1.x; gg[i*4+1]=t1.y; gg[i*4+2]=t1.z; gg[i*4+3]=t1.w;
        bb[i*4]=t2.x; bb[i*4+1]=t2.y; bb[i*4+2]=t2.z; bb[i*4+3]=t2.w;
    }
    float v[16];
    #pragma unroll
    for (int i = 0; i < 16; i++) v[i] = 0.f;
    for (int t = 0; t < T_; t++){
        int row = t*ROWS_PER_T + bn;
        const __half2* xr = (const __half2*)(in + (size_t)row*C_ + cb);
        float xv[16];
        #pragma unroll
        for (int i = 0; i < 8; i++){
            float2 f2 = __half22float2(xr[i]);
            xv[i*2] = f2.x; xv[i*2+1] = f2.y;
        }
        float s = 0.f, ss = 0.f;
        #pragma unroll
        for (int i = 0; i < 16; i++){ s += xv[i]; ss += xv[i]*xv[i]; }
        #pragma unroll
        for (int o = 16; o > 0; o >>= 1){
            s  += __shfl_xor_sync(0xffffffffu, s,  o);
            ss += __shfl_xor_sync(0xffffffffu, ss, o);
        }
        float mean = s*(1.0f/C_);
        float var  = ss*(1.0f/C_) - mean*mean;
        float rstd = rsqrtf(var + 1e-5f);
        union { __half h[16]; uint4 u[2]; } pk;
        #pragma unroll
        for (int k = 0; k < 16; k++){
            float ln = (xv[k]-mean)*rstd*gg[k] + bb[k];
            v[k] += (ln - v[k])*dec;
            float spv = (v[k] >= 1.0f) ? 1.f : 0.f;
            pk.h[k] = __float2half_rn(spv);
            if (spv > 0.f) v[k] = 0.f;
        }
        uint4* dst = (uint4*)(out + (size_t)row*C_ + cb);
        dst[0] = pk.u[0]; dst[1] = pk.u[1];
    }
}

// ---------------- attention phase 1 (HMMA, chunked pipeline) ----------------
// kvT[e,d] = sum_n v[n,e] k[n,d]; 512 blocks = tb*8 + h, 128 threads.
// Tokens streamed in 4 chunks of 64 with double-buffered cp.async.
#define ATT_LD 72

__global__ void __launch_bounds__(128) k_attn_kv_mma(){
    __shared__ __half sk[2][64*ATT_LD];
    __shared__ __half sv[2][64*ATT_LD];
    int blk = blockIdx.x;
    int h  = blk & 7;
    int tb = blk >> 3;
    int tid = threadIdx.x, warp = tid >> 5, lane = tid & 31;

    const __half* base = g_q16 + (size_t)tb*256*(3*C_) + h*D_;

    // prologue: chunk 0 -> buffer 0
    #pragma unroll
    for (int it = 0; it < 4; it++){
        int task = tid + it*128;
        int row = task >> 3, chn = task & 7;
        cp16(s2u(&sk[0][row*ATT_LD + chn*8]), base + (size_t)row*(3*C_) + C_   + chn*8);
        cp16(s2u(&sv[0][row*ATT_LD + chn*8]), base + (size_t)row*(3*C_) + 2*C_ + chn*8);
    }
    asm volatile("cp.async.commit_group;");

    int l8 = lane >> 3;
    int a_r = (lane & 7) + (l8 >> 1)*8;
    int a_c = warp*16 + (l8 & 1)*8;
    int b_r = (lane & 7) + (l8 & 1)*8;
    int b_c = (l8 >> 1)*8;

    float acc[8][4] = {};
    for (int c = 0; c < 4; c++){
        int buf = c & 1;
        if (c + 1 < 4){
            int n0 = (c+1)*64;
            #pragma unroll
            for (int it = 0; it < 4; it++){
                int task = tid + it*128;
                int row = task >> 3, chn = task & 7;
                cp16(s2u(&sk[buf^1][row*ATT_LD + chn*8]),
                     base + (size_t)(n0+row)*(3*C_) + C_   + chn*8);
                cp16(s2u(&sv[buf^1][row*ATT_LD + chn*8]),
                     base + (size_t)(n0+row)*(3*C_) + 2*C_ + chn*8);
            }
            asm volatile("cp.async.commit_group;");
            asm volatile("cp.async.wait_group 1;" ::: "memory");
        } else {
            asm volatile("cp.async.wait_group 0;" ::: "memory");
        }
        __syncthreads();
        #pragma unroll
        for (int s = 0; s < 4; s++){
            uint32_t af[4];
            ldsm4t(af, s2u(&sv[buf][(s*16 + a_r)*ATT_LD + a_c]));
            #pragma unroll
            for (int j = 0; j < 4; j++){
                uint32_t bf[4];
                ldsm4t(bf, s2u(&sk[buf][(s*16 + b_r)*ATT_LD + j*16 + b_c]));
                mma16816(acc[2*j],   af, bf[0], bf[1]);
                mma16816(acc[2*j+1], af, bf[2], bf[3]);
            }
        }
        __syncthreads();
    }

    __half* dst = g_kvT + (size_t)blk*(D_*D_);
    int g = lane >> 2, i2 = (lane & 3)*2;
    int r0 = warp*16 + g, r1 = r0 + 8;
    #pragma unroll
    for (int ni = 0; ni < 8; ni++){
        int col = ni*8 + i2;
        *(__half2*)&dst[r0*D_ + col] = __floats2half2_rn(acc[ni][0], acc[ni][1]);
        *(__half2*)&dst[r1*D_ + col] = __floats2half2_rn(acc[ni][2], acc[ni][3]);
    }
}

// ---------------- attention phase 2 (HMMA): a = q@kvT*scale + LIF -----------
__global__ void __launch_bounds__(128) k_attn_av_mma(const float* __restrict__ lifw){
    __shared__ __half sq [2][64*ATT_LD];
    __shared__ __half skv[2][64*ATT_LD];
    int blk = blockIdx.x;
    int nt = blk & 3;
    int h  = (blk >> 2) & 7;
    int b  = blk >> 5;
    int tid = threadIdx.x, warp = tid >> 5, lane = tid & 31;
    float dec = sigm(lifw[5]);

    int l8 = lane >> 3;
    int arow = (lane & 7) + (l8 & 1)*8, acol = (l8 >> 1)*8;
    int brow = (lane & 7) + (l8 >> 1)*8, bcol = (l8 & 1)*8;
    int g = lane >> 2, i2 = (lane & 3)*2;

    float vst[8][4];
    #pragma unroll
    for (int ni = 0; ni < 8; ni++)
        #pragma unroll
        for (int c = 0; c < 4; c++) vst[ni][c] = 0.f;

    {
        const __half* qb = g_q16 + ((size_t)(0*B_ + b)*256 + nt*64)*(3*C_) + h*D_;
        const __half* kb = g_kvT + (size_t)((0*B_ + b)*NH_ + h)*(D_*D_);
        #pragma unroll
        for (int it = 0; it < 4; it++){
            int task = tid + it*128;
            int row = task >> 3, ch = task & 7;
            cp16(s2u(&sq [0][row*ATT_LD + ch*8]), qb + (size_t)row*(3*C_) + ch*8);
            cp16(s2u(&skv[0][row*ATT_LD + ch*8]), kb + row*D_ + ch*8);
        }
        asm volatile("cp.async.commit_group;");
    }

    for (int t = 0; t < T_; t++){
        int buf = t & 1;
        if (t + 1 < T_){
            int tb1 = (t+1)*B_ + b;
            const __half* qb = g_q16 + ((size_t)tb1*256 + nt*64)*(3*C_) + h*D_;
            const __half* kb = g_kvT + (size_t)(tb1*NH_ + h)*(D_*D_);
            #pragma unroll
            for (int it = 0; it < 4; it++){
                int task = tid + it*128;
                int row = task >> 3, ch = task & 7;
                cp16(s2u(&sq [buf^1][row*ATT_LD + ch*8]), qb + (size_t)row*(3*C_) + ch*8);
                cp16(s2u(&skv[buf^1][row*ATT_LD + ch*8]), kb + row*D_ + ch*8);
            }
            asm volatile("cp.async.commit_group;");
            asm volatile("cp.async.wait_group 1;" ::: "memory");
        } else {
            asm volatile("cp.async.wait_group 0;" ::: "memory");
        }
        __syncthreads();

        int tb = t*B_ + b;
        float acc[8][4] = {};
        #pragma unroll
        for (int s = 0; s < 4; s++){
            uint32_t af[4];
            ldsm4(af, s2u(&sq[buf][(warp*16 + arow)*ATT_LD + s*16 + acol]));
            #pragma unroll
            for (int j = 0; j < 4; j++){
                uint32_t bf[4];
                ldsm4(bf, s2u(&skv[buf][(j*16 + brow)*ATT_LD + s*16 + bcol]));
                mma16816(acc[2*j],   af, bf[0], bf[1]);
                mma16816(acc[2*j+1], af, bf[2], bf[3]);
            }
        }

        int row0 = tb*256 + nt*64 + warp*16 + g;
        #pragma unroll
        for (int ni = 0; ni < 8; ni++){
            int col = h*D_ + ni*8 + i2;
            __half sp[4];
            #pragma unroll
            for (int c = 0; c < 4; c++){
                float a = acc[ni][c]*0.125f;
                float* v = &vst[ni][c];
                *v += (a - *v)*dec;
                float s = (*v >= 1.0f) ? 1.f : 0.f;
                sp[c] = __float2half_rn(s);
                if (s > 0.f) *v = 0.f;
            }
            *(__half2*)&g_a16[(size_t)row0*C_ + col]     = *(__half2*)&sp[0];
            *(__half2*)&g_a16[(size_t)(row0+8)*C_ + col] = *(__half2*)&sp[2];
        }
        __syncthreads();
    }
}

// ---------------- host orchestration ----------------------------------------
extern "C" void kernel_launch(void* const* d_in, const int* in_sizes, int n_in,
                              void* d_out, int out_size){
    const float* x      = (const float*)d_in[0];
    const float* conv_w = (const float*)d_in[1];
    const float* conv_b = (const float*)d_in[2];
    const float* ln1_g  = (const float*)d_in[3];
    const float* ln1_b  = (const float*)d_in[4];
    const float* qkv_w  = (const float*)d_in[5];
    const float* proj_w = (const float*)d_in[6];
    const float* proj_b = (const float*)d_in[7];
    const float* ln2_g  = (const float*)d_in[8];
    const float* ln2_b  = (const float*)d_in[9];
    const float* fc1_w  = (const float*)d_in[10];
    const float* fc1_b  = (const float*)d_in[11];
    const float* fc2_w  = (const float*)d_in[12];
    const float* fc2_b  = (const float*)d_in[13];
    const float* lif_w  = (const float*)d_in[14];
    float* out = (float*)d_out;

    cudaFuncSetAttribute(tc_gemm<0>, cudaFuncAttributeMaxDynamicSharedMemorySize, GEMM_SMEM);
    cudaFuncSetAttribute(tc_gemm<1>, cudaFuncAttributeMaxDynamicSharedMemorySize, GEMM_SMEM);
    cudaFuncSetAttribute(tc_gemm<2>, cudaFuncAttributeMaxDynamicSharedMemorySize, GEMM_SMEM);
    cudaFuncSetAttribute(tc_gemm<3>, cudaFuncAttributeMaxDynamicSharedMemorySize, GEMM_SMEM);

    __half *p_xt, *p_xt2, *p_h16, *p_q16, *p_a16, *p_m16, *p_w;
    cudaGetSymbolAddress((void**)&p_xt,  g_xt);
    cudaGetSymbolAddress((void**)&p_xt2, g_xt2);
    cudaGetSymbolAddress((void**)&p_h16, g_h16);
    cudaGetSymbolAddress((void**)&p_q16, g_q16);
    cudaGetSymbolAddress((void**)&p_a16, g_a16);
    cudaGetSymbolAddress((void**)&p_m16, g_m16);
    cudaGetSymbolAddress((void**)&p_w,   g_wall);

    k_conv_lif<<<512, 256>>>(x, conv_w, conv_b, lif_w, qkv_w, proj_w, fc1_w, fc2_w);
    k_ln_lif<<<512, 256>>>(p_xt, p_h16, ln1_g, ln1_b, lif_w, 1);
    tc_gemm<1><<<dim3(12,128), 256, GEMM_SMEM>>>(p_h16, p_w + WOFF_QKV, nullptr, nullptr,
                                                 nullptr, p_q16, lif_w, 3*C_, C_);
    k_attn_kv_mma<<<512, 128>>>();
    k_attn_av_mma<<<512, 128>>>(lif_w);
    tc_gemm<0><<<dim3(4,128), 256, GEMM_SMEM>>>(p_a16, p_w + WOFF_PROJ, proj_b, p_xt,
                                                nullptr, p_xt2, lif_w, C_, C_);
    k_ln_lif<<<512, 256>>>(p_xt2, p_h16, ln2_g, ln2_b, lif_w, 6);
    tc_gemm<2><<<dim3(16,128), 256, GEMM_SMEM>>>(p_h16, p_w + WOFF_FC1, fc1_b, nullptr,
                                                 nullptr, p_m16, lif_w, HID_, C_);
    tc_gemm<3><<<dim3(4,128), 256, GEMM_SMEM>>>(p_m16, p_w + WOFF_FC2, fc2_b, p_xt2,
                                                out, nullptr, lif_w, C_, HID_);
}